// round 3
// baseline (speedup 1.0000x reference)
#include <cuda_runtime.h>
#include <math.h>

#define BB 2
#define HH 16
#define SS 2048
#define HD 128
#define DD 2048
#define KKEEP 819
#define NEGV -1e9f
#define QT 8
#define FULLW 0xffffffffu

// Scratch (device globals: no allocation allowed)
__device__ float g_q [BB*HH*SS*HD];   // [bh][s][d]
__device__ float g_kT[BB*HH*HD*SS];   // [bh][d][t]  (transposed K)
__device__ float g_v [BB*HH*SS*HD];   // [bh][t][d]
__device__ float g_att[BB*SS*DD];     // [b][s][h*HD+d]

// ---------------------------------------------------------------------------
// Kernel 1: per-head QKV projections. y = x @ W^T + b  (torch Linear layout)
// ---------------------------------------------------------------------------
__global__ __launch_bounds__(256) void qkv_kernel(
    const float* __restrict__ x,
    const float* __restrict__ Wq, const float* __restrict__ Wk, const float* __restrict__ Wv,
    const float* __restrict__ bq, const float* __restrict__ bk, const float* __restrict__ bv)
{
    __shared__ float xs[64][HD];
    __shared__ float Ws[16][HD + 1];

    int bh = blockIdx.y;
    int b  = bh >> 4, h = bh & 15;
    int s0 = blockIdx.x * 64;
    int tid = threadIdx.x;

    const float* xbase = x + ((size_t)b*SS + s0)*DD + h*HD;
    for (int i = tid; i < 64*32; i += 256) {
        int sr = i >> 5, dv = (i & 31) << 2;
        float4 val = *(const float4*)(xbase + (size_t)sr*DD + dv);
        xs[sr][dv+0] = val.x; xs[sr][dv+1] = val.y;
        xs[sr][dv+2] = val.z; xs[sr][dv+3] = val.w;
    }

    int ei = tid & 15, si = tid >> 4;

    for (int w = 0; w < 3; w++) {
        const float* Wh   = ((w==0) ? Wq : (w==1) ? Wk : Wv) + (size_t)h*HD*HD;
        const float* bias = ((w==0) ? bq : (w==1) ? bk : bv) + h*HD;
        for (int et = 0; et < 8; et++) {
            __syncthreads();
            for (int i = tid; i < 512; i += 256) {
                int er = i >> 5, dv = (i & 31) << 2;
                float4 val = *(const float4*)(Wh + (size_t)(et*16 + er)*HD + dv);
                Ws[er][dv+0] = val.x; Ws[er][dv+1] = val.y;
                Ws[er][dv+2] = val.z; Ws[er][dv+3] = val.w;
            }
            __syncthreads();
            float a0 = 0.f, a1 = 0.f, a2 = 0.f, a3 = 0.f;
            #pragma unroll 8
            for (int d = 0; d < HD; d++) {
                float wv = Ws[ei][d];
                a0 += xs[si     ][d] * wv;
                a1 += xs[si + 16][d] * wv;
                a2 += xs[si + 32][d] * wv;
                a3 += xs[si + 48][d] * wv;
            }
            int e = et*16 + ei;
            float bbv = bias[e];
            a0 += bbv; a1 += bbv; a2 += bbv; a3 += bbv;
            if (w == 1) {
                float* kp = g_kT + ((size_t)bh*HD + e)*SS + s0;
                kp[si] = a0; kp[si+16] = a1; kp[si+32] = a2; kp[si+48] = a3;
            } else {
                float* op = (w == 0 ? g_q : g_v) + ((size_t)bh*SS + s0)*HD + e;
                op[(size_t)(si     )*HD] = a0;
                op[(size_t)(si + 16)*HD] = a1;
                op[(size_t)(si + 32)*HD] = a2;
                op[(size_t)(si + 48)*HD] = a3;
            }
        }
    }
}

// ---------------------------------------------------------------------------
// Kernel 2: scores + exact top-k threshold + softmax + attn@V  (8 rows/block)
// ---------------------------------------------------------------------------
__device__ __forceinline__ unsigned f2key(float f) {
    unsigned u = __float_as_uint(f);
    return u ^ ((u & 0x80000000u) ? 0xFFFFFFFFu : 0x80000000u);
}
__device__ __forceinline__ float key2f(unsigned k) {
    unsigned u = (k & 0x80000000u) ? (k ^ 0x80000000u) : ~k;
    return __uint_as_float(u);
}

__global__ __launch_bounds__(256) void attn_kernel()
{
    extern __shared__ float smem[];
    float* sc   = smem;                   // [QT][SS]   scores -> weights
    float* q_s  = sc  + QT*SS;            // [QT][HD]
    float* outp = q_s + QT*HD;            // [QT][HD]   partial V-accum
    int*   hist = (int*)(outp + QT*HD);   // [QT][256]
    __shared__ float rsinv_s[QT];

    int bh   = blockIdx.y;
    int s0   = (gridDim.x - 1 - blockIdx.x) * QT;   // longest blocks first
    int tid  = threadIdx.x;
    int lane = tid & 31, wid = tid >> 5;
    int smax = s0 + QT - 1;

    const float* qg = g_q + ((size_t)bh*SS + s0)*HD;
    for (int i = tid; i < QT*HD; i += 256) q_s[i] = qg[i];
    __syncthreads();

    // ---- Phase A: scores (causal-bounded), 4 columns per thread ----
    const float* kTg = g_kT + (size_t)bh*HD*SS;
    const float scale = 0.08838834764831845f;  // 1/sqrt(128)
    #pragma unroll
    for (int j = 0; j < 2; j++) {
        int t0 = (tid + j*256) << 2;
        if (t0 <= smax) {
            float4 acc[QT];
            #pragma unroll
            for (int r = 0; r < QT; r++) { acc[r].x=0.f; acc[r].y=0.f; acc[r].z=0.f; acc[r].w=0.f; }
            #pragma unroll 2
            for (int d = 0; d < HD; d++) {
                float4 kv = *(const float4*)(kTg + (size_t)d*SS + t0);
                #pragma unroll
                for (int r = 0; r < QT; r++) {
                    float qv = q_s[r*HD + d];
                    acc[r].x += qv*kv.x; acc[r].y += qv*kv.y;
                    acc[r].z += qv*kv.z; acc[r].w += qv*kv.w;
                }
            }
            #pragma unroll
            for (int r = 0; r < QT; r++) {
                int lim = s0 + r;
                sc[r*SS + t0 + 0] = (t0 + 0 <= lim) ? acc[r].x*scale : NEGV;
                sc[r*SS + t0 + 1] = (t0 + 1 <= lim) ? acc[r].y*scale : NEGV;
                sc[r*SS + t0 + 2] = (t0 + 2 <= lim) ? acc[r].z*scale : NEGV;
                sc[r*SS + t0 + 3] = (t0 + 3 <= lim) ? acc[r].w*scale : NEGV;
            }
        } else {
            #pragma unroll
            for (int r = 0; r < QT; r++) {
                sc[r*SS + t0 + 0] = NEGV; sc[r*SS + t0 + 1] = NEGV;
                sc[r*SS + t0 + 2] = NEGV; sc[r*SS + t0 + 3] = NEGV;
            }
        }
    }
    __syncthreads();

    // ---- Phase B: warp-per-row exact radix-select (kth of 2048) + softmax ----
    {
        int r = wid;                     // 8 warps == QT rows
        float* row = sc + r*SS;
        int*   h   = hist + r*256;
        unsigned prefix = 0; int K = KKEEP;
        float lm = -3.4e38f;

        #pragma unroll
        for (int pass = 0; pass < 4; pass++) {
            int shift = 24 - pass*8;
            #pragma unroll
            for (int i = lane; i < 256; i += 32) h[i] = 0;
            __syncwarp();
            for (int t = lane; t < SS; t += 32) {
                float v = row[t];
                if (pass == 0) lm = fmaxf(lm, v);
                unsigned key = f2key(v);
                bool cand = (pass == 0) || (((key ^ prefix) >> (shift + 8)) == 0u);
                int bin = cand ? (int)((key >> shift) & 255u) : -1;
                unsigned peers = __match_any_sync(FULLW, bin);
                if (cand && lane == (__ffs(peers) - 1))
                    atomicAdd(&h[bin], __popc(peers));
            }
            __syncwarp();
            // suffix scan over 256 bins (8 per lane)
            int hv[8]; int ssum = 0;
            #pragma unroll
            for (int i = 0; i < 8; i++) { hv[i] = h[lane*8 + i]; ssum += hv[i]; }
            int suf = ssum;
            #pragma unroll
            for (int off = 1; off < 32; off <<= 1) {
                int v = __shfl_down_sync(FULLW, suf, off);
                if (lane + off < 32) suf += v;
            }
            int above = suf - ssum;      // count in bins strictly above my chunk
            int selbin = -1, newK = 0;
            if (suf >= K && above < K) {
                int run = above;
                #pragma unroll
                for (int b = 7; b >= 0; b--) {
                    run += hv[b];
                    if (run >= K) { selbin = lane*8 + b; newK = K - (run - hv[b]); break; }
                }
            }
            unsigned msk = __ballot_sync(FULLW, selbin >= 0);
            int src = __ffs(msk) - 1;
            selbin = __shfl_sync(FULLW, selbin, src);
            newK   = __shfl_sync(FULLW, newK,  src);
            prefix |= ((unsigned)selbin) << shift;
            K = newK;
        }
        float thr = key2f(prefix);

        #pragma unroll
        for (int off = 16; off > 0; off >>= 1)
            lm = fmaxf(lm, __shfl_xor_sync(FULLW, lm, off));

        // weights + sum (only t <= smax is ever read downstream)
        float ls = 0.f;
        for (int t = lane; t <= smax; t += 32) {
            float v = row[t];
            float wv = (v >= thr) ? __expf(v - lm) : 0.f;
            row[t] = wv; ls += wv;
        }
        #pragma unroll
        for (int off = 16; off > 0; off >>= 1)
            ls += __shfl_xor_sync(FULLW, ls, off);
        if (lane == 0) rsinv_s[r] = 1.f / ls;
    }
    __syncthreads();

    // ---- Phase D: out = attn @ V  (two t-pairs interleaved across halves) ----
    int d = tid & 127, half = tid >> 7;
    int tend = smax + 1;                 // multiple of 8
    const float* vg = g_v + (size_t)bh*SS*HD + d;
    float acc[QT];
    #pragma unroll
    for (int r = 0; r < QT; r++) acc[r] = 0.f;
    for (int p = half; p < tend/2; p += 2) {
        int t = p*2;
        float v0 = vg[(size_t)t*HD];
        float v1 = vg[(size_t)(t+1)*HD];
        #pragma unroll
        for (int r = 0; r < QT; r++) {
            float2 w = *(const float2*)(sc + r*SS + t);
            acc[r] += w.x*v0 + w.y*v1;
        }
    }
    if (half) {
        #pragma unroll
        for (int r = 0; r < QT; r++) outp[r*HD + d] = acc[r];
    }
    __syncthreads();
    if (!half) {
        int b = bh >> 4, h = bh & 15;
        #pragma unroll
        for (int r = 0; r < QT; r++) {
            float o = (acc[r] + outp[r*HD + d]) * rsinv_s[r];
            g_att[((size_t)b*SS + s0 + r)*DD + h*HD + d] = o;
        }
    }
}

// ---------------------------------------------------------------------------
// Kernel 3: out[b,i,t] = sum_s g_att[b,s,i] * Wo[t,s] + bo[t]
// ---------------------------------------------------------------------------
__global__ __launch_bounds__(256) void proj_kernel(
    const float* __restrict__ Wo, const float* __restrict__ bo,
    float* __restrict__ out)
{
    __shared__ float As[16][128];
    __shared__ float Bs[16][128];

    int b  = blockIdx.z;
    int i0 = blockIdx.y * 128;
    int t0 = blockIdx.x * 128;
    int tid = threadIdx.x;
    int tx = tid & 15, ty = tid >> 4;

    float acc[8][8];
    #pragma unroll
    for (int i = 0; i < 8; i++)
        #pragma unroll
        for (int j = 0; j < 8; j++) acc[i][j] = 0.f;

    const float* Ab = g_att + (size_t)b*SS*DD;

    for (int k0 = 0; k0 < SS; k0 += 16) {
        __syncthreads();
        #pragma unroll
        for (int l = 0; l < 2; l++) {
            int idx = tid + l*256;
            int kk = idx >> 5, c4 = (idx & 31) << 2;
            float4 av = *(const float4*)(Ab + (size_t)(k0 + kk)*DD + i0 + c4);
            As[kk][c4+0] = av.x; As[kk][c4+1] = av.y;
            As[kk][c4+2] = av.z; As[kk][c4+3] = av.w;
            int tt = idx >> 2, cc = (idx & 3) << 2;
            float4 bv = *(const float4*)(Wo + (size_t)(t0 + tt)*SS + k0 + cc);
            Bs[cc+0][tt] = bv.x; Bs[cc+1][tt] = bv.y;
            Bs[cc+2][tt] = bv.z; Bs[cc+3][tt] = bv.w;
        }
        __syncthreads();
        #pragma unroll
        for (int kk = 0; kk < 16; kk++) {
            float a[8], bbv[8];
            #pragma unroll
            for (int i = 0; i < 8; i++) a[i]   = As[kk][ty*8 + i];
            #pragma unroll
            for (int j = 0; j < 8; j++) bbv[j] = Bs[kk][tx*8 + j];
            #pragma unroll
            for (int i = 0; i < 8; i++)
                #pragma unroll
                for (int j = 0; j < 8; j++) acc[i][j] += a[i] * bbv[j];
        }
    }

    float bias[8];
    #pragma unroll
    for (int j = 0; j < 8; j++) bias[j] = bo[t0 + tx*8 + j];
    #pragma unroll
    for (int i = 0; i < 8; i++) {
        float* op = out + ((size_t)b*DD + i0 + ty*8 + i)*DD + t0 + tx*8;
        #pragma unroll
        for (int j = 0; j < 8; j++) op[j] = acc[i][j] + bias[j];
    }
}

// ---------------------------------------------------------------------------
extern "C" void kernel_launch(void* const* d_in, const int* in_sizes, int n_in,
                              void* d_out, int out_size)
{
    const float* x  = (const float*)d_in[0];
    // d_in[1] = causal_mask (unused; mask computed analytically)
    const float* Wq = (const float*)d_in[2];
    const float* Wk = (const float*)d_in[3];
    const float* Wv = (const float*)d_in[4];
    const float* bq = (const float*)d_in[5];
    const float* bk = (const float*)d_in[6];
    const float* bv = (const float*)d_in[7];
    const float* Wo = (const float*)d_in[8];
    const float* bo = (const float*)d_in[9];
    float* out = (float*)d_out;

    const int SMEM2 = (QT*SS + 2*QT*HD)*4 + QT*256*4;  // 81920 bytes

    qkv_kernel<<<dim3(SS/64, BB*HH), 256>>>(x, Wq, Wk, Wv, bq, bk, bv);

    cudaFuncSetAttribute(attn_kernel, cudaFuncAttributeMaxDynamicSharedMemorySize, SMEM2);
    attn_kernel<<<dim3(SS/QT, BB*HH), 256, SMEM2>>>();

    proj_kernel<<<dim3(DD/128, DD/128, BB), 256>>>(Wo, bo, out);
}

// round 4
// speedup vs baseline: 1.6538x; 1.6538x over previous
#include <cuda_runtime.h>
#include <math.h>

#define BB 2
#define HH 16
#define SS 2048
#define HD 128
#define DD 2048
#define KKEEP 819
#define NEGV -1e9f
#define QT 16
#define FULLW 0xffffffffu

// Scratch (device globals: no allocation allowed)
__device__ float g_q [BB*HH*SS*HD];   // [bh][s][d]
__device__ float g_kT[BB*HH*HD*SS];   // [bh][d][t]  (transposed K)
__device__ float g_v [BB*HH*SS*HD];   // [bh][t][d]
__device__ float g_att[BB*SS*DD];     // [b][s][h*HD+d]

// ---------------------------------------------------------------------------
// Kernel 1: per-head QKV projections. y = x @ W^T + b  (torch Linear layout)
// ---------------------------------------------------------------------------
__global__ __launch_bounds__(256) void qkv_kernel(
    const float* __restrict__ x,
    const float* __restrict__ Wq, const float* __restrict__ Wk, const float* __restrict__ Wv,
    const float* __restrict__ bq, const float* __restrict__ bk, const float* __restrict__ bv)
{
    __shared__ float xs[64][HD];
    __shared__ float Ws[16][HD + 1];

    int bh = blockIdx.y;
    int b  = bh >> 4, h = bh & 15;
    int s0 = blockIdx.x * 64;
    int tid = threadIdx.x;

    const float* xbase = x + ((size_t)b*SS + s0)*DD + h*HD;
    for (int i = tid; i < 64*32; i += 256) {
        int sr = i >> 5, dv = (i & 31) << 2;
        float4 val = *(const float4*)(xbase + (size_t)sr*DD + dv);
        xs[sr][dv+0] = val.x; xs[sr][dv+1] = val.y;
        xs[sr][dv+2] = val.z; xs[sr][dv+3] = val.w;
    }

    int ei = tid & 15, si = tid >> 4;

    for (int w = 0; w < 3; w++) {
        const float* Wh   = ((w==0) ? Wq : (w==1) ? Wk : Wv) + (size_t)h*HD*HD;
        const float* bias = ((w==0) ? bq : (w==1) ? bk : bv) + h*HD;
        for (int et = 0; et < 8; et++) {
            __syncthreads();
            for (int i = tid; i < 512; i += 256) {
                int er = i >> 5, dv = (i & 31) << 2;
                float4 val = *(const float4*)(Wh + (size_t)(et*16 + er)*HD + dv);
                Ws[er][dv+0] = val.x; Ws[er][dv+1] = val.y;
                Ws[er][dv+2] = val.z; Ws[er][dv+3] = val.w;
            }
            __syncthreads();
            float a0 = 0.f, a1 = 0.f, a2 = 0.f, a3 = 0.f;
            #pragma unroll 8
            for (int d = 0; d < HD; d++) {
                float wv = Ws[ei][d];
                a0 += xs[si     ][d] * wv;
                a1 += xs[si + 16][d] * wv;
                a2 += xs[si + 32][d] * wv;
                a3 += xs[si + 48][d] * wv;
            }
            int e = et*16 + ei;
            float bbv = bias[e];
            a0 += bbv; a1 += bbv; a2 += bbv; a3 += bbv;
            if (w == 1) {
                float* kp = g_kT + ((size_t)bh*HD + e)*SS + s0;
                kp[si] = a0; kp[si+16] = a1; kp[si+32] = a2; kp[si+48] = a3;
            } else {
                float* op = (w == 0 ? g_q : g_v) + ((size_t)bh*SS + s0)*HD + e;
                op[(size_t)(si     )*HD] = a0;
                op[(size_t)(si + 16)*HD] = a1;
                op[(size_t)(si + 32)*HD] = a2;
                op[(size_t)(si + 48)*HD] = a3;
            }
        }
    }
}

// ---------------------------------------------------------------------------
// Kernel 2: scores + exact top-k threshold + softmax + attn@V (16 rows/block)
// ---------------------------------------------------------------------------
__device__ __forceinline__ unsigned f2key(float f) {
    unsigned u = __float_as_uint(f);
    return u ^ ((u & 0x80000000u) ? 0xFFFFFFFFu : 0x80000000u);
}
__device__ __forceinline__ float key2f(unsigned k) {
    unsigned u = (k & 0x80000000u) ? (k ^ 0x80000000u) : ~k;
    return __uint_as_float(u);
}

__global__ __launch_bounds__(512) void attn_kernel()
{
    extern __shared__ float smem[];
    float* sc   = smem;                    // [QT][SS]     scores -> weights (128KB)
    float* q_s  = sc  + QT*SS;             // [QT][HD]     (8KB)
    float* outp = q_s + QT*HD;             // [3][QT][HD]  partial V-accum (24KB)
    int*   hist = (int*)(outp + 3*QT*HD);  // [QT][256]    (16KB)
    __shared__ float rsinv_s[QT];

    int bh   = blockIdx.y;
    int s0   = (gridDim.x - 1 - blockIdx.x) * QT;   // longest blocks first
    int tid  = threadIdx.x;
    int lane = tid & 31, wid = tid >> 5;
    int smax = s0 + QT - 1;

    const float* qg = g_q + ((size_t)bh*SS + s0)*HD;
    for (int i = tid; i < QT*HD; i += 512) q_s[i] = qg[i];
    __syncthreads();

    // ---- Phase A: scores (causal-bounded), 4 columns per thread ----
    const float* kTg = g_kT + (size_t)bh*HD*SS;
    const float scale = 0.08838834764831845f;  // 1/sqrt(128)
    {
        int t0 = tid << 2;                 // 512 threads * 4 = 2048 cols
        if (t0 <= smax) {
            float4 acc[QT];
            #pragma unroll
            for (int r = 0; r < QT; r++) { acc[r].x=0.f; acc[r].y=0.f; acc[r].z=0.f; acc[r].w=0.f; }
            #pragma unroll 1
            for (int d = 0; d < HD; d += 4) {
                float4 kv0 = *(const float4*)(kTg + (size_t)(d+0)*SS + t0);
                float4 kv1 = *(const float4*)(kTg + (size_t)(d+1)*SS + t0);
                float4 kv2 = *(const float4*)(kTg + (size_t)(d+2)*SS + t0);
                float4 kv3 = *(const float4*)(kTg + (size_t)(d+3)*SS + t0);
                #pragma unroll
                for (int r = 0; r < QT; r++) {
                    float4 qv = *(const float4*)(q_s + r*HD + d);
                    acc[r].x += qv.x*kv0.x + qv.y*kv1.x + qv.z*kv2.x + qv.w*kv3.x;
                    acc[r].y += qv.x*kv0.y + qv.y*kv1.y + qv.z*kv2.y + qv.w*kv3.y;
                    acc[r].z += qv.x*kv0.z + qv.y*kv1.z + qv.z*kv2.z + qv.w*kv3.z;
                    acc[r].w += qv.x*kv0.w + qv.y*kv1.w + qv.z*kv2.w + qv.w*kv3.w;
                }
            }
            #pragma unroll
            for (int r = 0; r < QT; r++) {
                int lim = s0 + r;
                float4 o;
                o.x = (t0 + 0 <= lim) ? acc[r].x*scale : NEGV;
                o.y = (t0 + 1 <= lim) ? acc[r].y*scale : NEGV;
                o.z = (t0 + 2 <= lim) ? acc[r].z*scale : NEGV;
                o.w = (t0 + 3 <= lim) ? acc[r].w*scale : NEGV;
                *(float4*)(sc + r*SS + t0) = o;
            }
        } else {
            float4 n4 = make_float4(NEGV, NEGV, NEGV, NEGV);
            #pragma unroll
            for (int r = 0; r < QT; r++) *(float4*)(sc + r*SS + t0) = n4;
        }
    }
    __syncthreads();

    // ---- Phase B: warp-per-row exact radix-select (kth of 2048) + softmax ----
    {
        int r = wid;                      // 16 warps == QT rows
        float* row = sc + r*SS;
        int*   h   = hist + r*256;
        unsigned prefix = 0; int K = KKEEP;
        float lm = -3.4e38f;

        #pragma unroll
        for (int pass = 0; pass < 4; pass++) {
            int shift = 24 - pass*8;
            #pragma unroll
            for (int i = lane; i < 256; i += 32) h[i] = 0;
            __syncwarp();
            for (int t = lane; t < SS; t += 32) {
                float v = row[t];
                if (pass == 0) lm = fmaxf(lm, v);
                unsigned key = f2key(v);
                bool cand = (pass == 0) || (((key ^ prefix) >> (shift + 8)) == 0u);
                int bin = cand ? (int)((key >> shift) & 255u) : -1;
                unsigned peers = __match_any_sync(FULLW, bin);
                if (cand && lane == (__ffs(peers) - 1))
                    atomicAdd(&h[bin], __popc(peers));
            }
            __syncwarp();
            // suffix scan over 256 bins (8 per lane)
            int hv[8]; int ssum = 0;
            #pragma unroll
            for (int i = 0; i < 8; i++) { hv[i] = h[lane*8 + i]; ssum += hv[i]; }
            int suf = ssum;
            #pragma unroll
            for (int off = 1; off < 32; off <<= 1) {
                int v = __shfl_down_sync(FULLW, suf, off);
                if (lane + off < 32) suf += v;
            }
            int above = suf - ssum;       // count in bins strictly above my chunk
            int selbin = -1, newK = 0;
            if (suf >= K && above < K) {
                int run = above;
                #pragma unroll
                for (int b = 7; b >= 0; b--) {
                    run += hv[b];
                    if (run >= K) { selbin = lane*8 + b; newK = K - (run - hv[b]); break; }
                }
            }
            unsigned msk = __ballot_sync(FULLW, selbin >= 0);
            int src = __ffs(msk) - 1;
            selbin = __shfl_sync(FULLW, selbin, src);
            newK   = __shfl_sync(FULLW, newK,  src);
            prefix |= ((unsigned)selbin) << shift;
            K = newK;
        }
        float thr = key2f(prefix);

        #pragma unroll
        for (int off = 16; off > 0; off >>= 1)
            lm = fmaxf(lm, __shfl_xor_sync(FULLW, lm, off));

        // weights + sum (only t <= smax is ever read downstream)
        float ls = 0.f;
        for (int t = lane; t <= smax; t += 32) {
            float v = row[t];
            float wv = (v >= thr) ? __expf(v - lm) : 0.f;
            row[t] = wv; ls += wv;
        }
        #pragma unroll
        for (int off = 16; off > 0; off >>= 1)
            ls += __shfl_xor_sync(FULLW, ls, off);
        if (lane == 0) rsinv_s[r] = 1.f / ls;
    }
    __syncthreads();

    // ---- Phase D: out = attn @ V  (t-chunks of 4, split over 4 quarters) ----
    {
        int d = tid & 127, qtr = tid >> 7;
        int tend = smax + 1;               // multiple of 16
        const float* vg = g_v + (size_t)bh*SS*HD + d;
        float acc[QT];
        #pragma unroll
        for (int r = 0; r < QT; r++) acc[r] = 0.f;
        for (int t0 = qtr*4; t0 < tend; t0 += 16) {
            float v0 = vg[(size_t)(t0+0)*HD];
            float v1 = vg[(size_t)(t0+1)*HD];
            float v2 = vg[(size_t)(t0+2)*HD];
            float v3 = vg[(size_t)(t0+3)*HD];
            #pragma unroll
            for (int r = 0; r < QT; r++) {
                float4 w = *(const float4*)(sc + r*SS + t0);
                acc[r] += w.x*v0 + w.y*v1 + w.z*v2 + w.w*v3;
            }
        }
        if (qtr) {
            float* op = outp + (qtr-1)*QT*HD + d;
            #pragma unroll
            for (int r = 0; r < QT; r++) op[r*HD] = acc[r];
        }
        __syncthreads();
        if (!qtr) {
            int b = bh >> 4, h = bh & 15;
            #pragma unroll
            for (int r = 0; r < QT; r++) {
                float o = acc[r] + outp[0*QT*HD + r*HD + d]
                                 + outp[1*QT*HD + r*HD + d]
                                 + outp[2*QT*HD + r*HD + d];
                g_att[((size_t)b*SS + s0 + r)*DD + h*HD + d] = o * rsinv_s[r];
            }
        }
    }
}

// ---------------------------------------------------------------------------
// Kernel 3: out[b,i,t] = sum_s g_att[b,s,i] * Wo[t,s] + bo[t]
// ---------------------------------------------------------------------------
__global__ __launch_bounds__(256) void proj_kernel(
    const float* __restrict__ Wo, const float* __restrict__ bo,
    float* __restrict__ out)
{
    __shared__ float As[16][128];
    __shared__ float Bs[16][128];

    int b  = blockIdx.z;
    int i0 = blockIdx.y * 128;
    int t0 = blockIdx.x * 128;
    int tid = threadIdx.x;
    int tx = tid & 15, ty = tid >> 4;

    float acc[8][8];
    #pragma unroll
    for (int i = 0; i < 8; i++)
        #pragma unroll
        for (int j = 0; j < 8; j++) acc[i][j] = 0.f;

    const float* Ab = g_att + (size_t)b*SS*DD;

    for (int k0 = 0; k0 < SS; k0 += 16) {
        __syncthreads();
        #pragma unroll
        for (int l = 0; l < 2; l++) {
            int idx = tid + l*256;
            int kk = idx >> 5, c4 = (idx & 31) << 2;
            float4 av = *(const float4*)(Ab + (size_t)(k0 + kk)*DD + i0 + c4);
            As[kk][c4+0] = av.x; As[kk][c4+1] = av.y;
            As[kk][c4+2] = av.z; As[kk][c4+3] = av.w;
            int tt = idx >> 2, cc = (idx & 3) << 2;
            float4 bv = *(const float4*)(Wo + (size_t)(t0 + tt)*SS + k0 + cc);
            Bs[cc+0][tt] = bv.x; Bs[cc+1][tt] = bv.y;
            Bs[cc+2][tt] = bv.z; Bs[cc+3][tt] = bv.w;
        }
        __syncthreads();
        #pragma unroll
        for (int kk = 0; kk < 16; kk++) {
            float a[8], bbv[8];
            #pragma unroll
            for (int i = 0; i < 8; i++) a[i]   = As[kk][ty*8 + i];
            #pragma unroll
            for (int j = 0; j < 8; j++) bbv[j] = Bs[kk][tx*8 + j];
            #pragma unroll
            for (int i = 0; i < 8; i++)
                #pragma unroll
                for (int j = 0; j < 8; j++) acc[i][j] += a[i] * bbv[j];
        }
    }

    float bias[8];
    #pragma unroll
    for (int j = 0; j < 8; j++) bias[j] = bo[t0 + tx*8 + j];
    #pragma unroll
    for (int i = 0; i < 8; i++) {
        float* op = out + ((size_t)b*DD + i0 + ty*8 + i)*DD + t0 + tx*8;
        #pragma unroll
        for (int j = 0; j < 8; j++) op[j] = acc[i][j] + bias[j];
    }
}

// ---------------------------------------------------------------------------
extern "C" void kernel_launch(void* const* d_in, const int* in_sizes, int n_in,
                              void* d_out, int out_size)
{
    const float* x  = (const float*)d_in[0];
    // d_in[1] = causal_mask (unused; mask computed analytically)
    const float* Wq = (const float*)d_in[2];
    const float* Wk = (const float*)d_in[3];
    const float* Wv = (const float*)d_in[4];
    const float* bq = (const float*)d_in[5];
    const float* bk = (const float*)d_in[6];
    const float* bv = (const float*)d_in[7];
    const float* Wo = (const float*)d_in[8];
    const float* bo = (const float*)d_in[9];
    float* out = (float*)d_out;

    const int SMEM2 = (QT*SS + QT*HD + 3*QT*HD)*4 + QT*256*4;  // 180224 bytes

    qkv_kernel<<<dim3(SS/64, BB*HH), 256>>>(x, Wq, Wk, Wv, bq, bk, bv);

    cudaFuncSetAttribute(attn_kernel, cudaFuncAttributeMaxDynamicSharedMemorySize, SMEM2);
    attn_kernel<<<dim3(SS/QT, BB*HH), 512, SMEM2>>>();

    proj_kernel<<<dim3(DD/128, DD/128, BB), 256>>>(Wo, bo, out);
}

// round 6
// speedup vs baseline: 1.9817x; 1.1983x over previous
#include <cuda_runtime.h>
#include <cuda_bf16.h>
#include <cstdint>
#include <math.h>

#define BB 2
#define HH 16
#define SS 2048
#define HD 128
#define DD 2048
#define KKEEP 819
#define NEGV -1e9f
#define QT 16
#define FULLW 0xffffffffu

// ---------------- scratch (device globals; no allocation allowed) ----------
__device__ float g_q  [BB*HH*SS*HD];   // [bh][s][d]
__device__ float g_kT [BB*HH*HD*SS];   // [bh][d][t]
__device__ float g_v  [BB*HH*SS*HD];   // [bh][t][d]
__device__ float g_attT[BB*DD*SS];     // [b][i][s]  (i = h*HD+d)

// bf16 hi/lo split operands, plain K-major [row][2048]
__device__ __nv_bfloat16 g_Ahi[(size_t)BB*DD*SS];
__device__ __nv_bfloat16 g_Alo[(size_t)BB*DD*SS];
__device__ __nv_bfloat16 g_Whi[(size_t)DD*SS];
__device__ __nv_bfloat16 g_Wlo[(size_t)DD*SS];

// ---------------------------------------------------------------------------
// Kernel 1: per-head QKV projections. y = x @ W^T + b
// ---------------------------------------------------------------------------
__global__ __launch_bounds__(256) void qkv_kernel(
    const float* __restrict__ x,
    const float* __restrict__ Wq, const float* __restrict__ Wk, const float* __restrict__ Wv,
    const float* __restrict__ bq, const float* __restrict__ bk, const float* __restrict__ bv)
{
    __shared__ float xs[64][HD];
    __shared__ float Ws[16][HD + 1];

    int bh = blockIdx.y;
    int b  = bh >> 4, h = bh & 15;
    int s0 = blockIdx.x * 64;
    int tid = threadIdx.x;

    const float* xbase = x + ((size_t)b*SS + s0)*DD + h*HD;
    for (int i = tid; i < 64*32; i += 256) {
        int sr = i >> 5, dv = (i & 31) << 2;
        float4 val = *(const float4*)(xbase + (size_t)sr*DD + dv);
        xs[sr][dv+0] = val.x; xs[sr][dv+1] = val.y;
        xs[sr][dv+2] = val.z; xs[sr][dv+3] = val.w;
    }

    int ei = tid & 15, si = tid >> 4;

    for (int w = 0; w < 3; w++) {
        const float* Wh   = ((w==0) ? Wq : (w==1) ? Wk : Wv) + (size_t)h*HD*HD;
        const float* bias = ((w==0) ? bq : (w==1) ? bk : bv) + h*HD;
        for (int et = 0; et < 8; et++) {
            __syncthreads();
            for (int i = tid; i < 512; i += 256) {
                int er = i >> 5, dv = (i & 31) << 2;
                float4 val = *(const float4*)(Wh + (size_t)(et*16 + er)*HD + dv);
                Ws[er][dv+0] = val.x; Ws[er][dv+1] = val.y;
                Ws[er][dv+2] = val.z; Ws[er][dv+3] = val.w;
            }
            __syncthreads();
            float a0 = 0.f, a1 = 0.f, a2 = 0.f, a3 = 0.f;
            #pragma unroll 8
            for (int d = 0; d < HD; d++) {
                float wv = Ws[ei][d];
                a0 += xs[si     ][d] * wv;
                a1 += xs[si + 16][d] * wv;
                a2 += xs[si + 32][d] * wv;
                a3 += xs[si + 48][d] * wv;
            }
            int e = et*16 + ei;
            float bbv = bias[e];
            a0 += bbv; a1 += bbv; a2 += bbv; a3 += bbv;
            if (w == 1) {
                float* kp = g_kT + ((size_t)bh*HD + e)*SS + s0;
                kp[si] = a0; kp[si+16] = a1; kp[si+32] = a2; kp[si+48] = a3;
            } else {
                float* op = (w == 0 ? g_q : g_v) + ((size_t)bh*SS + s0)*HD + e;
                op[(size_t)(si     )*HD] = a0;
                op[(size_t)(si + 16)*HD] = a1;
                op[(size_t)(si + 32)*HD] = a2;
                op[(size_t)(si + 48)*HD] = a3;
            }
        }
    }
}

// ---------------------------------------------------------------------------
// Kernel 2: scores + exact top-k threshold + softmax + attn@V (16 rows/block)
// ---------------------------------------------------------------------------
__device__ __forceinline__ unsigned f2key(float f) {
    unsigned u = __float_as_uint(f);
    return u ^ ((u & 0x80000000u) ? 0xFFFFFFFFu : 0x80000000u);
}
__device__ __forceinline__ float key2f(unsigned k) {
    unsigned u = (k & 0x80000000u) ? (k ^ 0x80000000u) : ~k;
    return __uint_as_float(u);
}

__global__ __launch_bounds__(512) void attn_kernel()
{
    extern __shared__ float smem[];
    float* sc   = smem;                    // [QT][SS]
    float* q_s  = sc  + QT*SS;             // [QT][HD]
    float* outp = q_s + QT*HD;             // [3][QT][HD]
    int*   hist = (int*)(outp + 3*QT*HD);  // [QT][256]
    __shared__ float rsinv_s[QT];

    int bh   = blockIdx.y;
    int s0   = (gridDim.x - 1 - blockIdx.x) * QT;
    int tid  = threadIdx.x;
    int lane = tid & 31, wid = tid >> 5;
    int smax = s0 + QT - 1;

    const float* qg = g_q + ((size_t)bh*SS + s0)*HD;
    for (int i = tid; i < QT*HD; i += 512) q_s[i] = qg[i];
    __syncthreads();

    const float* kTg = g_kT + (size_t)bh*HD*SS;
    const float scale = 0.08838834764831845f;
    {
        int t0 = tid << 2;
        if (t0 <= smax) {
            float4 acc[QT];
            #pragma unroll
            for (int r = 0; r < QT; r++) { acc[r].x=0.f; acc[r].y=0.f; acc[r].z=0.f; acc[r].w=0.f; }
            #pragma unroll 1
            for (int d = 0; d < HD; d += 4) {
                float4 kv0 = *(const float4*)(kTg + (size_t)(d+0)*SS + t0);
                float4 kv1 = *(const float4*)(kTg + (size_t)(d+1)*SS + t0);
                float4 kv2 = *(const float4*)(kTg + (size_t)(d+2)*SS + t0);
                float4 kv3 = *(const float4*)(kTg + (size_t)(d+3)*SS + t0);
                #pragma unroll
                for (int r = 0; r < QT; r++) {
                    float4 qv = *(const float4*)(q_s + r*HD + d);
                    acc[r].x += qv.x*kv0.x + qv.y*kv1.x + qv.z*kv2.x + qv.w*kv3.x;
                    acc[r].y += qv.x*kv0.y + qv.y*kv1.y + qv.z*kv2.y + qv.w*kv3.y;
                    acc[r].z += qv.x*kv0.z + qv.y*kv1.z + qv.z*kv2.z + qv.w*kv3.z;
                    acc[r].w += qv.x*kv0.w + qv.y*kv1.w + qv.z*kv2.w + qv.w*kv3.w;
                }
            }
            #pragma unroll
            for (int r = 0; r < QT; r++) {
                int lim = s0 + r;
                float4 o;
                o.x = (t0 + 0 <= lim) ? acc[r].x*scale : NEGV;
                o.y = (t0 + 1 <= lim) ? acc[r].y*scale : NEGV;
                o.z = (t0 + 2 <= lim) ? acc[r].z*scale : NEGV;
                o.w = (t0 + 3 <= lim) ? acc[r].w*scale : NEGV;
                *(float4*)(sc + r*SS + t0) = o;
            }
        } else {
            float4 n4 = make_float4(NEGV, NEGV, NEGV, NEGV);
            #pragma unroll
            for (int r = 0; r < QT; r++) *(float4*)(sc + r*SS + t0) = n4;
        }
    }
    __syncthreads();

    {
        int r = wid;
        float* row = sc + r*SS;
        int*   h   = hist + r*256;
        unsigned prefix = 0; int K = KKEEP;
        float lm = -3.4e38f;

        #pragma unroll
        for (int pass = 0; pass < 4; pass++) {
            int shift = 24 - pass*8;
            #pragma unroll
            for (int i = lane; i < 256; i += 32) h[i] = 0;
            __syncwarp();
            for (int t = lane; t < SS; t += 32) {
                float v = row[t];
                if (pass == 0) lm = fmaxf(lm, v);
                unsigned key = f2key(v);
                bool cand = (pass == 0) || (((key ^ prefix) >> (shift + 8)) == 0u);
                int bin = cand ? (int)((key >> shift) & 255u) : -1;
                unsigned peers = __match_any_sync(FULLW, bin);
                if (cand && lane == (__ffs(peers) - 1))
                    atomicAdd(&h[bin], __popc(peers));
            }
            __syncwarp();
            int hv[8]; int ssum = 0;
            #pragma unroll
            for (int i = 0; i < 8; i++) { hv[i] = h[lane*8 + i]; ssum += hv[i]; }
            int suf = ssum;
            #pragma unroll
            for (int off = 1; off < 32; off <<= 1) {
                int v = __shfl_down_sync(FULLW, suf, off);
                if (lane + off < 32) suf += v;
            }
            int above = suf - ssum;
            int selbin = -1, newK = 0;
            if (suf >= K && above < K) {
                int run = above;
                #pragma unroll
                for (int b = 7; b >= 0; b--) {
                    run += hv[b];
                    if (run >= K) { selbin = lane*8 + b; newK = K - (run - hv[b]); break; }
                }
            }
            unsigned msk = __ballot_sync(FULLW, selbin >= 0);
            int src = __ffs(msk) - 1;
            selbin = __shfl_sync(FULLW, selbin, src);
            newK   = __shfl_sync(FULLW, newK,  src);
            prefix |= ((unsigned)selbin) << shift;
            K = newK;
        }
        float thr = key2f(prefix);

        #pragma unroll
        for (int off = 16; off > 0; off >>= 1)
            lm = fmaxf(lm, __shfl_xor_sync(FULLW, lm, off));

        float ls = 0.f;
        for (int t = lane; t <= smax; t += 32) {
            float v = row[t];
            float wv = (v >= thr) ? __expf(v - lm) : 0.f;
            row[t] = wv; ls += wv;
        }
        #pragma unroll
        for (int off = 16; off > 0; off >>= 1)
            ls += __shfl_xor_sync(FULLW, ls, off);
        if (lane == 0) rsinv_s[r] = 1.f / ls;
    }
    __syncthreads();

    {
        int d = tid & 127, qtr = tid >> 7;
        int tend = smax + 1;
        const float* vg = g_v + (size_t)bh*SS*HD + d;
        float acc[QT];
        #pragma unroll
        for (int r = 0; r < QT; r++) acc[r] = 0.f;
        for (int t0 = qtr*4; t0 < tend; t0 += 16) {
            float v0 = vg[(size_t)(t0+0)*HD];
            float v1 = vg[(size_t)(t0+1)*HD];
            float v2 = vg[(size_t)(t0+2)*HD];
            float v3 = vg[(size_t)(t0+3)*HD];
            #pragma unroll
            for (int r = 0; r < QT; r++) {
                float4 w = *(const float4*)(sc + r*SS + t0);
                acc[r] += w.x*v0 + w.y*v1 + w.z*v2 + w.w*v3;
            }
        }
        if (qtr) {
            float* op = outp + (qtr-1)*QT*HD + d;
            #pragma unroll
            for (int r = 0; r < QT; r++) op[r*HD] = acc[r];
        }
        __syncthreads();
        if (!qtr) {
            int b = bh >> 4, h = bh & 15;
            float ov[QT];
            #pragma unroll
            for (int r = 0; r < QT; r++) {
                float o = acc[r] + outp[0*QT*HD + r*HD + d]
                                 + outp[1*QT*HD + r*HD + d]
                                 + outp[2*QT*HD + r*HD + d];
                ov[r] = o * rsinv_s[r];
            }
            float* dst = g_attT + ((size_t)b*DD + h*HD + d)*SS + s0;
            #pragma unroll
            for (int r4 = 0; r4 < QT; r4 += 4)
                *(float4*)(dst + r4) = make_float4(ov[r4], ov[r4+1], ov[r4+2], ov[r4+3]);
        }
    }
}

// ---------------------------------------------------------------------------
// Kernel 3: fp32 -> bf16 hi/lo split, plain K-major layout
// y=0: Wo -> Whi/Wlo ; y=1,2: g_attT[b=y-1] -> Ahi/Alo
// ---------------------------------------------------------------------------
__global__ __launch_bounds__(256) void split_kernel(const float* __restrict__ Wo)
{
    int row = blockIdx.x, z = blockIdx.y;
    int tid = threadIdx.x;
    const float* src;
    __nv_bfloat16 *dhi, *dlo;
    if (z == 0) {
        src = Wo + (size_t)row*SS;
        dhi = g_Whi + (size_t)row*SS; dlo = g_Wlo + (size_t)row*SS;
    } else {
        int b = z - 1;
        src = g_attT + ((size_t)b*DD + row)*SS;
        dhi = g_Ahi + ((size_t)b*DD + row)*SS;
        dlo = g_Alo + ((size_t)b*DD + row)*SS;
    }
    int base = tid * 8;
    float4 f0 = *(const float4*)(src + base);
    float4 f1 = *(const float4*)(src + base + 4);
    float v[8] = {f0.x, f0.y, f0.z, f0.w, f1.x, f1.y, f1.z, f1.w};
    unsigned hw[4], lw[4];
    #pragma unroll
    for (int p = 0; p < 4; p++) {
        float a = v[2*p], b2 = v[2*p+1];
        __nv_bfloat16 ha = __float2bfloat16(a), hb = __float2bfloat16(b2);
        float la = a - __bfloat162float(ha);
        float lb = b2 - __bfloat162float(hb);
        __nv_bfloat162 hp = __halves2bfloat162(ha, hb);
        __nv_bfloat162 lp = __halves2bfloat162(__float2bfloat16(la), __float2bfloat16(lb));
        hw[p] = *(unsigned*)&hp;
        lw[p] = *(unsigned*)&lp;
    }
    *(uint4*)(dhi + base) = make_uint4(hw[0], hw[1], hw[2], hw[3]);
    *(uint4*)(dlo + base) = make_uint4(lw[0], lw[1], lw[2], lw[3]);
}

// ---------------------------------------------------------------------------
// Kernel 4: HMMA GEMM  out[b, mt*128+m, nt*128+n] = sum_k A[m,k]*W[n,k] + bo[n]
// K = 3 segments x 2048. BM=BN=128, BK=64, 8 warps (4m x 2n), 2-stage cp.async.
// ---------------------------------------------------------------------------
__device__ __forceinline__ uint32_t smem_u32(const void* p) {
    uint32_t a;
    asm("{ .reg .u64 t; cvta.to.shared.u64 t, %1; cvt.u32.u64 %0, t; }" : "=r"(a) : "l"(p));
    return a;
}
__device__ __forceinline__ void cpa16(uint32_t s, const void* g) {
    asm volatile("cp.async.cg.shared.global [%0], [%1], 16;" :: "r"(s), "l"(g));
}
__device__ __forceinline__ void ldsm4(uint32_t* r, uint32_t a) {
    asm volatile("ldmatrix.sync.aligned.m8n8.x4.shared.b16 {%0,%1,%2,%3}, [%4];"
                 : "=r"(r[0]), "=r"(r[1]), "=r"(r[2]), "=r"(r[3]) : "r"(a));
}
__device__ __forceinline__ void mma16816(float* c, const uint32_t* a, uint32_t b0, uint32_t b1) {
    asm volatile("mma.sync.aligned.m16n8k16.row.col.f32.bf16.bf16.f32 "
                 "{%0,%1,%2,%3}, {%4,%5,%6,%7}, {%8,%9}, {%0,%1,%2,%3};"
                 : "+f"(c[0]), "+f"(c[1]), "+f"(c[2]), "+f"(c[3])
                 : "r"(a[0]), "r"(a[1]), "r"(a[2]), "r"(a[3]), "r"(b0), "r"(b1));
}

#define PJ_STAGE 32768   // 16KB A + 16KB B per stage
#define PJ_SMEM  (2*PJ_STAGE)

__global__ __launch_bounds__(256) void proj_mma_kernel(
    const float* __restrict__ bo, float* __restrict__ out)
{
    extern __shared__ char psm[];
    uint32_t sb = smem_u32(psm);

    int tid = threadIdx.x, lane = tid & 31, wid = tid >> 5;
    int wm = wid & 3, wn = wid >> 2;
    int nt = blockIdx.x, mt = blockIdx.y, b = blockIdx.z;

    const __nv_bfloat16* Abase = g_Ahi + ((size_t)b*DD + mt*128)*SS;
    const __nv_bfloat16* AbaseLo = g_Alo + ((size_t)b*DD + mt*128)*SS;
    const __nv_bfloat16* Wbase = g_Whi + (size_t)(nt*128)*SS;
    const __nv_bfloat16* WbaseLo = g_Wlo + (size_t)(nt*128)*SS;

    // loader indices: 1024 16B chunks per operand tile, 256 threads -> 4 each
    int lrow = tid >> 3, lc16 = tid & 7;     // +32 rows per rep

    float acc[2][8][4];
    #pragma unroll
    for (int i = 0; i < 2; i++)
        #pragma unroll
        for (int j = 0; j < 8; j++)
            #pragma unroll
            for (int q = 0; q < 4; q++) acc[i][j][q] = 0.f;

    // ldmatrix lane addressing (pre-swizzle components)
    int rowa_l = wm*32 + (lane & 15);            // + i*16
    int ca_l   = (lane >> 4);                    // + kstep*2
    int rowb_l = wn*64 + (lane & 7) + ((lane >> 4) << 3);  // + j4*16
    int cb_l   = (lane >> 3) & 1;                // + kstep*2

    const int NC = 96;  // 3 segments * 32 BK-chunks

    // prologue: load chunk 0 into stage 0
    {
        const __nv_bfloat16* As = Abase;
        const __nv_bfloat16* Bs = Wbase;
        uint32_t sa = sb, sbB = sb + 16384;
        #pragma unroll
        for (int rep = 0; rep < 4; rep++) {
            int row = lrow + rep*32;
            uint32_t off = (uint32_t)row*128 + 16u*(uint32_t)(lc16 ^ (row & 7));
            cpa16(sa  + off, As + (size_t)row*SS + lc16*8);
            cpa16(sbB + off, Bs + (size_t)row*SS + lc16*8);
        }
        asm volatile("cp.async.commit_group;");
    }

    for (int c = 0; c < NC; c++) {
        int st = c & 1;
        if (c + 1 < NC) {
            int nc2 = c + 1;
            int seg = nc2 >> 5, kk = (nc2 & 31) * 64;
            const __nv_bfloat16* As = (seg == 1 ? AbaseLo : Abase);
            const __nv_bfloat16* Bs = (seg == 2 ? WbaseLo : Wbase);
            uint32_t sa = sb + (st^1)*PJ_STAGE, sbB = sa + 16384;
            #pragma unroll
            for (int rep = 0; rep < 4; rep++) {
                int row = lrow + rep*32;
                uint32_t off = (uint32_t)row*128 + 16u*(uint32_t)(lc16 ^ (row & 7));
                cpa16(sa  + off, As + (size_t)row*SS + kk + lc16*8);
                cpa16(sbB + off, Bs + (size_t)row*SS + kk + lc16*8);
            }
            asm volatile("cp.async.commit_group;");
            asm volatile("cp.async.wait_group 1;");
        } else {
            asm volatile("cp.async.wait_group 0;");
        }
        __syncthreads();

        uint32_t sa = sb + st*PJ_STAGE, sbB = sa + 16384;
        #pragma unroll
        for (int kstep = 0; kstep < 4; kstep++) {
            uint32_t afr[2][4];
            #pragma unroll
            for (int i = 0; i < 2; i++) {
                int row = rowa_l + i*16;
                int c16 = kstep*2 + ca_l;
                ldsm4(afr[i], sa + (uint32_t)row*128 + 16u*(uint32_t)(c16 ^ (row & 7)));
            }
            uint32_t bfr[4][4];
            #pragma unroll
            for (int j4 = 0; j4 < 4; j4++) {
                int row = rowb_l + j4*16;
                int c16 = kstep*2 + cb_l;
                ldsm4(bfr[j4], sbB + (uint32_t)row*128 + 16u*(uint32_t)(c16 ^ (row & 7)));
            }
            #pragma unroll
            for (int i = 0; i < 2; i++)
                #pragma unroll
                for (int j4 = 0; j4 < 4; j4++) {
                    mma16816(acc[i][2*j4+0], afr[i], bfr[j4][0], bfr[j4][1]);
                    mma16816(acc[i][2*j4+1], afr[i], bfr[j4][2], bfr[j4][3]);
                }
        }
        __syncthreads();
    }

    // epilogue
    int r0w = lane >> 2, cc = (lane & 3) * 2;
    const float* bop = bo + nt*128 + wn*64;
    #pragma unroll
    for (int i = 0; i < 2; i++) {
        int m = mt*128 + wm*32 + i*16 + r0w;
        float* row0 = out + ((size_t)b*DD + m)*DD + nt*128 + wn*64;
        float* row1 = row0 + (size_t)8*DD;
        #pragma unroll
        for (int j = 0; j < 8; j++) {
            float2 bb = *(const float2*)(bop + j*8 + cc);
            float2 v0 = make_float2(acc[i][j][0] + bb.x, acc[i][j][1] + bb.y);
            float2 v1 = make_float2(acc[i][j][2] + bb.x, acc[i][j][3] + bb.y);
            *(float2*)(row0 + j*8 + cc) = v0;
            *(float2*)(row1 + j*8 + cc) = v1;
        }
    }
}

// ---------------------------------------------------------------------------
extern "C" void kernel_launch(void* const* d_in, const int* in_sizes, int n_in,
                              void* d_out, int out_size)
{
    const float* x  = (const float*)d_in[0];
    const float* Wq = (const float*)d_in[2];
    const float* Wk = (const float*)d_in[3];
    const float* Wv = (const float*)d_in[4];
    const float* bq = (const float*)d_in[5];
    const float* bk = (const float*)d_in[6];
    const float* bv = (const float*)d_in[7];
    const float* Wo = (const float*)d_in[8];
    const float* bo = (const float*)d_in[9];
    float* out = (float*)d_out;

    const int SMEM2 = (QT*SS + QT*HD + 3*QT*HD)*4 + QT*256*4;  // 180224 bytes

    qkv_kernel<<<dim3(SS/64, BB*HH), 256>>>(x, Wq, Wk, Wv, bq, bk, bv);

    cudaFuncSetAttribute(attn_kernel, cudaFuncAttributeMaxDynamicSharedMemorySize, SMEM2);
    attn_kernel<<<dim3(SS/QT, BB*HH), 512, SMEM2>>>();

    split_kernel<<<dim3(DD, 3), 256>>>(Wo);

    cudaFuncSetAttribute(proj_mma_kernel, cudaFuncAttributeMaxDynamicSharedMemorySize, PJ_SMEM);
    proj_mma_kernel<<<dim3(16, 16, BB), 256, PJ_SMEM>>>(bo, out);
}

// round 8
// speedup vs baseline: 2.4353x; 1.2289x over previous
#include <cuda_runtime.h>
#include <cuda_bf16.h>
#include <cstdint>
#include <math.h>

#define BB 2
#define HH 16
#define SS 2048
#define HD 128
#define DD 2048
#define KKEEP 819
#define NEGV -1e9f
#define QT 16
#define FULLW 0xffffffffu

// ---------------- scratch (device globals; no allocation allowed) ----------
__device__ __nv_bfloat16 g_qhi [BB*HH*SS*HD];  // [bh][s][d]
__device__ __nv_bfloat16 g_qlo [BB*HH*SS*HD];
__device__ __nv_bfloat16 g_khi [BB*HH*SS*HD];  // [bh][t][d]
__device__ __nv_bfloat16 g_klo [BB*HH*SS*HD];
__device__ __nv_bfloat16 g_vthi[BB*HH*HD*SS];  // [bh][d][t]
__device__ __nv_bfloat16 g_vtlo[BB*HH*HD*SS];

// proj operands (A written directly by attn epilogue)
__device__ __nv_bfloat16 g_Ahi[(size_t)BB*DD*SS];  // [b][i][s]
__device__ __nv_bfloat16 g_Alo[(size_t)BB*DD*SS];
__device__ __nv_bfloat16 g_Whi[(size_t)DD*SS];
__device__ __nv_bfloat16 g_Wlo[(size_t)DD*SS];

// ---------------- common helpers -------------------------------------------
__device__ __forceinline__ uint32_t smem_u32(const void* p) {
    uint32_t a;
    asm("{ .reg .u64 t; cvta.to.shared.u64 t, %1; cvt.u32.u64 %0, t; }" : "=r"(a) : "l"(p));
    return a;
}
__device__ __forceinline__ void cpa16(uint32_t s, const void* g) {
    asm volatile("cp.async.cg.shared.global [%0], [%1], 16;" :: "r"(s), "l"(g));
}
__device__ __forceinline__ void ldsm4(uint32_t* r, uint32_t a) {
    asm volatile("ldmatrix.sync.aligned.m8n8.x4.shared.b16 {%0,%1,%2,%3}, [%4];"
                 : "=r"(r[0]), "=r"(r[1]), "=r"(r[2]), "=r"(r[3]) : "r"(a));
}
__device__ __forceinline__ void ldsm2(uint32_t* r, uint32_t a) {
    asm volatile("ldmatrix.sync.aligned.m8n8.x2.shared.b16 {%0,%1}, [%2];"
                 : "=r"(r[0]), "=r"(r[1]) : "r"(a));
}
__device__ __forceinline__ void mma16816(float* c, const uint32_t* a, uint32_t b0, uint32_t b1) {
    asm volatile("mma.sync.aligned.m16n8k16.row.col.f32.bf16.bf16.f32 "
                 "{%0,%1,%2,%3}, {%4,%5,%6,%7}, {%8,%9}, {%0,%1,%2,%3};"
                 : "+f"(c[0]), "+f"(c[1]), "+f"(c[2]), "+f"(c[3])
                 : "r"(a[0]), "r"(a[1]), "r"(a[2]), "r"(a[3]), "r"(b0), "r"(b1));
}
__device__ __forceinline__ void splitbf(float a, __nv_bfloat16& h, __nv_bfloat16& l) {
    h = __float2bfloat16(a);
    l = __float2bfloat16(a - __bfloat162float(h));
}

// ---------------------------------------------------------------------------
// Kernel 1: per-head QKV projections -> bf16 hi/lo operands
// ---------------------------------------------------------------------------
__global__ __launch_bounds__(256) void qkv_kernel(
    const float* __restrict__ x,
    const float* __restrict__ Wq, const float* __restrict__ Wk, const float* __restrict__ Wv,
    const float* __restrict__ bq, const float* __restrict__ bk, const float* __restrict__ bv)
{
    __shared__ float xs[64][HD];
    __shared__ float Ws[16][HD + 1];

    int bh = blockIdx.y;
    int b  = bh >> 4, h = bh & 15;
    int s0 = blockIdx.x * 64;
    int tid = threadIdx.x;

    const float* xbase = x + ((size_t)b*SS + s0)*DD + h*HD;
    for (int i = tid; i < 64*32; i += 256) {
        int sr = i >> 5, dv = (i & 31) << 2;
        float4 val = *(const float4*)(xbase + (size_t)sr*DD + dv);
        xs[sr][dv+0] = val.x; xs[sr][dv+1] = val.y;
        xs[sr][dv+2] = val.z; xs[sr][dv+3] = val.w;
    }

    int ei = tid & 15, si = tid >> 4;

    for (int w = 0; w < 3; w++) {
        const float* Wh   = ((w==0) ? Wq : (w==1) ? Wk : Wv) + (size_t)h*HD*HD;
        const float* bias = ((w==0) ? bq : (w==1) ? bk : bv) + h*HD;
        for (int et = 0; et < 8; et++) {
            __syncthreads();
            for (int i = tid; i < 512; i += 256) {
                int er = i >> 5, dv = (i & 31) << 2;
                float4 val = *(const float4*)(Wh + (size_t)(et*16 + er)*HD + dv);
                Ws[er][dv+0] = val.x; Ws[er][dv+1] = val.y;
                Ws[er][dv+2] = val.z; Ws[er][dv+3] = val.w;
            }
            __syncthreads();
            float a0 = 0.f, a1 = 0.f, a2 = 0.f, a3 = 0.f;
            #pragma unroll 8
            for (int d = 0; d < HD; d++) {
                float wv = Ws[ei][d];
                a0 += xs[si     ][d] * wv;
                a1 += xs[si + 16][d] * wv;
                a2 += xs[si + 32][d] * wv;
                a3 += xs[si + 48][d] * wv;
            }
            int e = et*16 + ei;
            float bbv = bias[e];
            a0 += bbv; a1 += bbv; a2 += bbv; a3 += bbv;

            float vals[4] = {a0, a1, a2, a3};
            if (w == 2) {
                size_t vb = ((size_t)bh*HD + e)*SS + s0;
                #pragma unroll
                for (int k = 0; k < 4; k++) {
                    __nv_bfloat16 hh, ll;
                    splitbf(vals[k], hh, ll);
                    g_vthi[vb + si + 16*k] = hh;
                    g_vtlo[vb + si + 16*k] = ll;
                }
            } else {
                size_t ob = ((size_t)bh*SS + s0)*HD + e;
                __nv_bfloat16* ph = (w == 0 ? g_qhi : g_khi) + ob;
                __nv_bfloat16* pl = (w == 0 ? g_qlo : g_klo) + ob;
                #pragma unroll
                for (int k = 0; k < 4; k++) {
                    __nv_bfloat16 hh, ll;
                    splitbf(vals[k], hh, ll);
                    ph[(size_t)(si + 16*k)*HD] = hh;
                    pl[(size_t)(si + 16*k)*HD] = ll;
                }
            }
        }
    }
}

// ---------------------------------------------------------------------------
// Kernel 2: HMMA scores + exact top-k + softmax + HMMA attn@V (16 rows/block)
// ---------------------------------------------------------------------------
__device__ __forceinline__ unsigned f2key(float f) {
    unsigned u = __float_as_uint(f);
    return u ^ ((u & 0x80000000u) ? 0xFFFFFFFFu : 0x80000000u);
}
__device__ __forceinline__ float key2f(unsigned k) {
    unsigned u = (k & 0x80000000u) ? (k ^ 0x80000000u) : ~k;
    return __uint_as_float(u);
}

// smem layout (bytes). Scores: fp32 [16][SCW], stride-padded; softmax weights
// are packed IN PLACE into the score slots as (hi_bf16 | lo_bf16 << 16).
#define SCW      2056                 // floats per score row (8224 B, != 0 mod 128)
#define AT_SC    0                    // 16*2056*4 = 131584
#define AT_QHI   131584               // bf16 [16][128] swizzled, 4096
#define AT_QLO   135680               // 4096
#define AT_KBH   139776               // chunk buf hi 128x128 bf16, 32768
#define AT_KBL   172544               // chunk buf lo, 32768
#define AT_SMEM  205312

__global__ __launch_bounds__(512) void attn_kernel()
{
    extern __shared__ char sm[];
    float* sc  = (float*)sm;
    int*  hist = (int*)(sm + AT_KBH);   // aliases chunk buffer (phase-exclusive)
    __shared__ float rsinv_s[QT];

    uint32_t sb = smem_u32(sm);
    int bh   = blockIdx.y;
    int b    = bh >> 4, h = bh & 15;
    int s0   = (gridDim.x - 1 - blockIdx.x) * QT;   // longest blocks first
    int tid  = threadIdx.x;
    int lane = tid & 31, wid = tid >> 5;
    int smax = s0 + QT - 1;
    int nchunks = (smax >> 7) + 1;
    const float scale = 0.08838834764831845f;       // 1/sqrt(128)

    // ---- load Q tile (swizzled) + NEGV tail init ----
    {
        size_t qoff = ((size_t)bh*SS + s0)*HD;
        int t2 = tid & 255;
        int row = t2 >> 4, u = t2 & 15;
        const __nv_bfloat16* src = (tid < 256 ? g_qhi : g_qlo) + qoff + (size_t)row*HD + u*8;
        uint32_t doff = (tid < 256 ? AT_QHI : AT_QLO) + row*256 + 16*(u ^ (row & 7));
        *(uint4*)(sm + doff) = *(const uint4*)src;

        float4 n4 = make_float4(NEGV, NEGV, NEGV, NEGV);
        int tail0 = nchunks*128;
        int t = tail0 + tid*4;
        if (t < SS)
            #pragma unroll
            for (int r = 0; r < QT; r++) *(float4*)(sc + r*SCW + t) = n4;
    }
    __syncthreads();

    // ---- preload Q fragments (m16k16 x 8 ksteps, hi+lo) ----
    uint32_t qfh[8][4], qfl[8][4];
    {
        int qr = lane & 15;
        #pragma unroll
        for (int ks = 0; ks < 8; ks++) {
            int u = ks*2 + (lane >> 4);
            uint32_t off = (uint32_t)qr*256 + 16u*(uint32_t)(u ^ (qr & 7));
            ldsm4(qfh[ks], sb + AT_QHI + off);
            ldsm4(qfl[ks], sb + AT_QLO + off);
        }
    }

    // ---- Phase A: scores via HMMA, 128-t chunks ----
    {
        const __nv_bfloat16* khb = g_khi + (size_t)bh*SS*HD;
        const __nv_bfloat16* klb = g_klo + (size_t)bh*SS*HD;
        int lrow = tid >> 4, lu = tid & 15;

        for (int c = 0; c < nchunks; c++) {
            const __nv_bfloat16* kh = khb + (size_t)c*128*HD;
            const __nv_bfloat16* kl = klb + (size_t)c*128*HD;
            #pragma unroll
            for (int rep = 0; rep < 4; rep++) {
                int row = lrow + rep*32;
                uint32_t off = (uint32_t)row*256 + 16u*(uint32_t)(lu ^ (row & 7));
                cpa16(sb + AT_KBH + off, kh + (size_t)row*HD + lu*8);
                cpa16(sb + AT_KBL + off, kl + (size_t)row*HD + lu*8);
            }
            asm volatile("cp.async.commit_group;");
            asm volatile("cp.async.wait_group 0;");
            __syncthreads();

            float ac[4] = {0.f, 0.f, 0.f, 0.f};
            int brow = wid*8 + (lane & 7);
            #pragma unroll
            for (int ks = 0; ks < 8; ks++) {
                int bu = ks*2 + ((lane >> 3) & 1);
                uint32_t boff = (uint32_t)brow*256 + 16u*(uint32_t)(bu ^ (brow & 7));
                uint32_t bh2[2], bl2[2];
                ldsm2(bh2, sb + AT_KBH + boff);
                ldsm2(bl2, sb + AT_KBL + boff);
                mma16816(ac, qfh[ks], bh2[0], bh2[1]);
                mma16816(ac, qfl[ks], bh2[0], bh2[1]);
                mma16816(ac, qfh[ks], bl2[0], bl2[1]);
            }
            // write scores with causal mask + scale
            int r0 = lane >> 2;
            int tc = c*128 + wid*8 + (lane & 3)*2;
            sc[r0*SCW + tc]       = (tc     <= s0 + r0)     ? ac[0]*scale : NEGV;
            sc[r0*SCW + tc + 1]   = (tc + 1 <= s0 + r0)     ? ac[1]*scale : NEGV;
            sc[(r0+8)*SCW + tc]   = (tc     <= s0 + r0 + 8) ? ac[2]*scale : NEGV;
            sc[(r0+8)*SCW + tc+1] = (tc + 1 <= s0 + r0 + 8) ? ac[3]*scale : NEGV;
            __syncthreads();
        }
    }

    // ---- Phase B: warp-per-row exact radix-select + softmax -> packed hi/lo ----
    {
        int r = wid;
        float* row = sc + r*SCW;
        int*   hh  = hist + r*256;
        unsigned prefix = 0; int K = KKEEP;
        float lm = -3.4e38f;

        #pragma unroll
        for (int pass = 0; pass < 4; pass++) {
            int shift = 24 - pass*8;
            #pragma unroll
            for (int i = lane; i < 256; i += 32) hh[i] = 0;
            __syncwarp();
            for (int t = lane; t < SS; t += 32) {
                float v = row[t];
                if (pass == 0) lm = fmaxf(lm, v);
                unsigned key = f2key(v);
                bool cand = (pass == 0) || (((key ^ prefix) >> (shift + 8)) == 0u);
                int bin = cand ? (int)((key >> shift) & 255u) : -1;
                unsigned peers = __match_any_sync(FULLW, bin);
                if (cand && lane == (__ffs(peers) - 1))
                    atomicAdd(&hh[bin], __popc(peers));
            }
            __syncwarp();
            int hv[8]; int ssum = 0;
            #pragma unroll
            for (int i = 0; i < 8; i++) { hv[i] = hh[lane*8 + i]; ssum += hv[i]; }
            int suf = ssum;
            #pragma unroll
            for (int off = 1; off < 32; off <<= 1) {
                int v = __shfl_down_sync(FULLW, suf, off);
                if (lane + off < 32) suf += v;
            }
            int above = suf - ssum;
            int selbin = -1, newK = 0;
            if (suf >= K && above < K) {
                int run = above;
                #pragma unroll
                for (int bb2 = 7; bb2 >= 0; bb2--) {
                    run += hv[bb2];
                    if (run >= K) { selbin = lane*8 + bb2; newK = K - (run - hv[bb2]); break; }
                }
            }
            unsigned msk = __ballot_sync(FULLW, selbin >= 0);
            int src = __ffs(msk) - 1;
            selbin = __shfl_sync(FULLW, selbin, src);
            newK   = __shfl_sync(FULLW, newK,  src);
            prefix |= ((unsigned)selbin) << shift;
            K = newK;
        }
        float thr = key2f(prefix);

        #pragma unroll
        for (int off = 16; off > 0; off >>= 1)
            lm = fmaxf(lm, __shfl_xor_sync(FULLW, lm, off));

        int tlimit = nchunks*128;
        float ls = 0.f;
        for (int t = lane; t < tlimit; t += 32) {
            float v = row[t];
            float wv = (v >= thr) ? __expf(v - lm) : 0.f;
            ls += wv;
            __nv_bfloat16 hw, lw;
            splitbf(wv, hw, lw);
            unsigned pk = (unsigned)*(unsigned short*)&hw
                        | ((unsigned)*(unsigned short*)&lw << 16);
            *(unsigned*)(row + t) = pk;     // in-place packed weight
        }
        #pragma unroll
        for (int off = 16; off > 0; off >>= 1)
            ls += __shfl_xor_sync(FULLW, ls, off);
        if (lane == 0) rsinv_s[r] = 1.f / ls;
    }
    __syncthreads();

    // ---- Phase D: out = attn @ V via HMMA (V^T chunks; warp owns n8 = d8) ----
    {
        const __nv_bfloat16* vhb = g_vthi + (size_t)bh*HD*SS;
        const __nv_bfloat16* vlb = g_vtlo + (size_t)bh*HD*SS;
        int lrow = tid >> 4, lu = tid & 15;
        const unsigned* scp = (const unsigned*)sc;
        int r_  = lane >> 2;
        int cc2 = (lane & 3)*2;

        float acc[4] = {0.f, 0.f, 0.f, 0.f};
        for (int c = 0; c < nchunks; c++) {
            #pragma unroll
            for (int rep = 0; rep < 4; rep++) {
                int row = lrow + rep*32;   // d index
                uint32_t off = (uint32_t)row*256 + 16u*(uint32_t)(lu ^ (row & 7));
                cpa16(sb + AT_KBH + off, vhb + (size_t)row*SS + c*128 + lu*8);
                cpa16(sb + AT_KBL + off, vlb + (size_t)row*SS + c*128 + lu*8);
            }
            asm volatile("cp.async.commit_group;");
            asm volatile("cp.async.wait_group 0;");
            __syncthreads();

            int brow = wid*8 + (lane & 7);
            #pragma unroll
            for (int ks = 0; ks < 8; ks++) {
                int kb = c*128 + ks*16 + cc2;
                // manual A-fragment from packed weights (canonical a0..a3)
                uint2 w00 = *(const uint2*)(scp + r_*SCW + kb);
                uint2 w10 = *(const uint2*)(scp + (r_+8)*SCW + kb);
                uint2 w01 = *(const uint2*)(scp + r_*SCW + kb + 8);
                uint2 w11 = *(const uint2*)(scp + (r_+8)*SCW + kb + 8);
                uint32_t ah[4], al[4];
                ah[0] = __byte_perm(w00.x, w00.y, 0x5410); al[0] = __byte_perm(w00.x, w00.y, 0x7632);
                ah[1] = __byte_perm(w10.x, w10.y, 0x5410); al[1] = __byte_perm(w10.x, w10.y, 0x7632);
                ah[2] = __byte_perm(w01.x, w01.y, 0x5410); al[2] = __byte_perm(w01.x, w01.y, 0x7632);
                ah[3] = __byte_perm(w11.x, w11.y, 0x5410); al[3] = __byte_perm(w11.x, w11.y, 0x7632);

                int bu = ks*2 + ((lane >> 3) & 1);
                uint32_t boff = (uint32_t)brow*256 + 16u*(uint32_t)(bu ^ (brow & 7));
                uint32_t vh2[2], vl2[2];
                ldsm2(vh2, sb + AT_KBH + boff);
                ldsm2(vl2, sb + AT_KBL + boff);
                mma16816(acc, ah, vh2[0], vh2[1]);
                mma16816(acc, al, vh2[0], vh2[1]);
                mma16816(acc, ah, vl2[0], vl2[1]);
            }
            __syncthreads();
        }

        // epilogue: normalize, split, write g_Ahi/g_Alo at [b][h*128+d][s0+r]
        int d0 = wid*8 + (lane & 3)*2;
        float rs0 = rsinv_s[r_], rs1 = rsinv_s[r_ + 8];
        size_t i0 = ((size_t)b*DD + h*HD + d0)*SS + s0;
        float o0 = acc[0]*rs0, o1 = acc[1]*rs0, o2 = acc[2]*rs1, o3 = acc[3]*rs1;
        __nv_bfloat16 hh, ll;
        splitbf(o0, hh, ll); g_Ahi[i0 + r_] = hh;          g_Alo[i0 + r_] = ll;
        splitbf(o1, hh, ll); g_Ahi[i0 + SS + r_] = hh;     g_Alo[i0 + SS + r_] = ll;
        splitbf(o2, hh, ll); g_Ahi[i0 + r_ + 8] = hh;      g_Alo[i0 + r_ + 8] = ll;
        splitbf(o3, hh, ll); g_Ahi[i0 + SS + r_ + 8] = hh; g_Alo[i0 + SS + r_ + 8] = ll;
    }
}

// ---------------------------------------------------------------------------
// Kernel 3: fp32 -> bf16 hi/lo split for Wo only
// ---------------------------------------------------------------------------
__global__ __launch_bounds__(256) void split_kernel(const float* __restrict__ Wo)
{
    int row = blockIdx.x;
    int tid = threadIdx.x;
    const float* src = Wo + (size_t)row*SS;
    __nv_bfloat16* dhi = g_Whi + (size_t)row*SS;
    __nv_bfloat16* dlo = g_Wlo + (size_t)row*SS;

    int base = tid * 8;
    float4 f0 = *(const float4*)(src + base);
    float4 f1 = *(const float4*)(src + base + 4);
    float v[8] = {f0.x, f0.y, f0.z, f0.w, f1.x, f1.y, f1.z, f1.w};
    unsigned hw[4], lw[4];
    #pragma unroll
    for (int p = 0; p < 4; p++) {
        __nv_bfloat16 ha, hb, la, lb;
        splitbf(v[2*p], ha, la);
        splitbf(v[2*p+1], hb, lb);
        __nv_bfloat162 hp = __halves2bfloat162(ha, hb);
        __nv_bfloat162 lp = __halves2bfloat162(la, lb);
        hw[p] = *(unsigned*)&hp;
        lw[p] = *(unsigned*)&lp;
    }
    *(uint4*)(dhi + base) = make_uint4(hw[0], hw[1], hw[2], hw[3]);
    *(uint4*)(dlo + base) = make_uint4(lw[0], lw[1], lw[2], lw[3]);
}

// ---------------------------------------------------------------------------
// Kernel 4: HMMA GEMM  out[b, mt*128+m, nt*128+n] = sum_k A[m,k]*W[n,k] + bo[n]
// ---------------------------------------------------------------------------
#define PJ_STAGE 32768
#define PJ_SMEM  (2*PJ_STAGE)

__global__ __launch_bounds__(256) void proj_mma_kernel(
    const float* __restrict__ bo, float* __restrict__ out)
{
    extern __shared__ char psm[];
    uint32_t sb = smem_u32(psm);

    int tid = threadIdx.x, lane = tid & 31, wid = tid >> 5;
    int wm = wid & 3, wn = wid >> 2;
    int nt = blockIdx.x, mt = blockIdx.y, b = blockIdx.z;

    const __nv_bfloat16* Abase   = g_Ahi + ((size_t)b*DD + mt*128)*SS;
    const __nv_bfloat16* AbaseLo = g_Alo + ((size_t)b*DD + mt*128)*SS;
    const __nv_bfloat16* Wbase   = g_Whi + (size_t)(nt*128)*SS;
    const __nv_bfloat16* WbaseLo = g_Wlo + (size_t)(nt*128)*SS;

    int lrow = tid >> 3, lc16 = tid & 7;

    float acc[2][8][4];
    #pragma unroll
    for (int i = 0; i < 2; i++)
        #pragma unroll
        for (int j = 0; j < 8; j++)
            #pragma unroll
            for (int q = 0; q < 4; q++) acc[i][j][q] = 0.f;

    int rowa_l = wm*32 + (lane & 15);
    int ca_l   = (lane >> 4);
    int rowb_l = wn*64 + (lane & 7) + ((lane >> 4) << 3);
    int cb_l   = (lane >> 3) & 1;

    const int NC = 96;

    {
        uint32_t sa = sb, sbB = sb + 16384;
        #pragma unroll
        for (int rep = 0; rep < 4; rep++) {
            int row = lrow + rep*32;
            uint32_t off = (uint32_t)row*128 + 16u*(uint32_t)(lc16 ^ (row & 7));
            cpa16(sa  + off, Abase + (size_t)row*SS + lc16*8);
            cpa16(sbB + off, Wbase + (size_t)row*SS + lc16*8);
        }
        asm volatile("cp.async.commit_group;");
    }

    for (int c = 0; c < NC; c++) {
        int st = c & 1;
        if (c + 1 < NC) {
            int nc2 = c + 1;
            int seg = nc2 >> 5, kk = (nc2 & 31) * 64;
            const __nv_bfloat16* As = (seg == 1 ? AbaseLo : Abase);
            const __nv_bfloat16* Bs = (seg == 2 ? WbaseLo : Wbase);
            uint32_t sa = sb + (st^1)*PJ_STAGE, sbB = sa + 16384;
            #pragma unroll
            for (int rep = 0; rep < 4; rep++) {
                int row = lrow + rep*32;
                uint32_t off = (uint32_t)row*128 + 16u*(uint32_t)(lc16 ^ (row & 7));
                cpa16(sa  + off, As + (size_t)row*SS + kk + lc16*8);
                cpa16(sbB + off, Bs + (size_t)row*SS + kk + lc16*8);
            }
            asm volatile("cp.async.commit_group;");
            asm volatile("cp.async.wait_group 1;");
        } else {
            asm volatile("cp.async.wait_group 0;");
        }
        __syncthreads();

        uint32_t sa = sb + st*PJ_STAGE, sbB = sa + 16384;
        #pragma unroll
        for (int kstep = 0; kstep < 4; kstep++) {
            uint32_t afr[2][4];
            #pragma unroll
            for (int i = 0; i < 2; i++) {
                int row = rowa_l + i*16;
                int c16 = kstep*2 + ca_l;
                ldsm4(afr[i], sa + (uint32_t)row*128 + 16u*(uint32_t)(c16 ^ (row & 7)));
            }
            uint32_t bfr[4][4];
            #pragma unroll
            for (int j4 = 0; j4 < 4; j4++) {
                int row = rowb_l + j4*16;
                int c16 = kstep*2 + cb_l;
                ldsm4(bfr[j4], sbB + (uint32_t)row*128 + 16u*(uint32_t)(c16 ^ (row & 7)));
            }
            #pragma unroll
            for (int i = 0; i < 2; i++)
                #pragma unroll
                for (int j4 = 0; j4 < 4; j4++) {
                    mma16816(acc[i][2*j4+0], afr[i], bfr[j4][0], bfr[j4][1]);
                    mma16816(acc[i][2*j4+1], afr[i], bfr[j4][2], bfr[j4][3]);
                }
        }
        __syncthreads();
    }

    int r0w = lane >> 2, cc = (lane & 3) * 2;
    const float* bop = bo + nt*128 + wn*64;
    #pragma unroll
    for (int i = 0; i < 2; i++) {
        int m = mt*128 + wm*32 + i*16 + r0w;
        float* row0 = out + ((size_t)b*DD + m)*DD + nt*128 + wn*64;
        float* row1 = row0 + (size_t)8*DD;
        #pragma unroll
        for (int j = 0; j < 8; j++) {
            float2 bb = *(const float2*)(bop + j*8 + cc);
            float2 v0 = make_float2(acc[i][j][0] + bb.x, acc[i][j][1] + bb.y);
            float2 v1 = make_float2(acc[i][j][2] + bb.x, acc[i][j][3] + bb.y);
            *(float2*)(row0 + j*8 + cc) = v0;
            *(float2*)(row1 + j*8 + cc) = v1;
        }
    }
}

// ---------------------------------------------------------------------------
extern "C" void kernel_launch(void* const* d_in, const int* in_sizes, int n_in,
                              void* d_out, int out_size)
{
    const float* x  = (const float*)d_in[0];
    const float* Wq = (const float*)d_in[2];
    const float* Wk = (const float*)d_in[3];
    const float* Wv = (const float*)d_in[4];
    const float* bq = (const float*)d_in[5];
    const float* bk = (const float*)d_in[6];
    const float* bv = (const float*)d_in[7];
    const float* Wo = (const float*)d_in[8];
    const float* bo = (const float*)d_in[9];
    float* out = (float*)d_out;

    qkv_kernel<<<dim3(SS/64, BB*HH), 256>>>(x, Wq, Wk, Wv, bq, bk, bv);

    split_kernel<<<dim3(DD), 256>>>(Wo);

    cudaFuncSetAttribute(attn_kernel, cudaFuncAttributeMaxDynamicSharedMemorySize, AT_SMEM);
    attn_kernel<<<dim3(SS/QT, BB*HH), 512, AT_SMEM>>>();

    cudaFuncSetAttribute(proj_mma_kernel, cudaFuncAttributeMaxDynamicSharedMemorySize, PJ_SMEM);
    proj_mma_kernel<<<dim3(16, 16, BB), 256, PJ_SMEM>>>(bo, out);
}

// round 9
// speedup vs baseline: 2.8262x; 1.1605x over previous
#include <cuda_runtime.h>
#include <cuda_bf16.h>
#include <cstdint>
#include <math.h>

#define BB 2
#define HH 16
#define SS 2048
#define HD 128
#define DD 2048
#define KKEEP 819
#define NEGV -1e9f
#define FULLW 0xffffffffu

// ---------------- scratch (device globals; no allocation allowed) ----------
__device__ __nv_bfloat16 g_qhi [BB*HH*SS*HD];  // [bh][s][d]
__device__ __nv_bfloat16 g_qlo [BB*HH*SS*HD];
__device__ __nv_bfloat16 g_khi [BB*HH*SS*HD];  // [bh][t][d]
__device__ __nv_bfloat16 g_klo [BB*HH*SS*HD];
__device__ __nv_bfloat16 g_vthi[BB*HH*HD*SS];  // [bh][d][t]
__device__ __nv_bfloat16 g_vtlo[BB*HH*HD*SS];

__device__ float         g_sc [(size_t)BB*HH*SS*SS];   // scores [bh][s][t] (512MB)
__device__ __nv_bfloat16 g_wh [(size_t)BB*HH*SS*SS];   // normalized weights hi
__device__ __nv_bfloat16 g_wl [(size_t)BB*HH*SS*SS];   // normalized weights lo

// proj operands (A written directly by av_gemm epilogue)
__device__ __nv_bfloat16 g_Ahi[(size_t)BB*DD*SS];      // [b][i][s]
__device__ __nv_bfloat16 g_Alo[(size_t)BB*DD*SS];
__device__ __nv_bfloat16 g_Whi[(size_t)DD*SS];
__device__ __nv_bfloat16 g_Wlo[(size_t)DD*SS];

// ---------------- common helpers -------------------------------------------
__device__ __forceinline__ uint32_t smem_u32(const void* p) {
    uint32_t a;
    asm("{ .reg .u64 t; cvta.to.shared.u64 t, %1; cvt.u32.u64 %0, t; }" : "=r"(a) : "l"(p));
    return a;
}
__device__ __forceinline__ void cpa16(uint32_t s, const void* g) {
    asm volatile("cp.async.cg.shared.global [%0], [%1], 16;" :: "r"(s), "l"(g));
}
__device__ __forceinline__ void ldsm4(uint32_t* r, uint32_t a) {
    asm volatile("ldmatrix.sync.aligned.m8n8.x4.shared.b16 {%0,%1,%2,%3}, [%4];"
                 : "=r"(r[0]), "=r"(r[1]), "=r"(r[2]), "=r"(r[3]) : "r"(a));
}
__device__ __forceinline__ void mma16816(float* c, const uint32_t* a, uint32_t b0, uint32_t b1) {
    asm volatile("mma.sync.aligned.m16n8k16.row.col.f32.bf16.bf16.f32 "
                 "{%0,%1,%2,%3}, {%4,%5,%6,%7}, {%8,%9}, {%0,%1,%2,%3};"
                 : "+f"(c[0]), "+f"(c[1]), "+f"(c[2]), "+f"(c[3])
                 : "r"(a[0]), "r"(a[1]), "r"(a[2]), "r"(a[3]), "r"(b0), "r"(b1));
}
__device__ __forceinline__ void splitbf(float a, __nv_bfloat16& h, __nv_bfloat16& l) {
    h = __float2bfloat16(a);
    l = __float2bfloat16(a - __bfloat162float(h));
}

// ---------------------------------------------------------------------------
// Kernel 1: per-head QKV projections -> bf16 hi/lo operands
// ---------------------------------------------------------------------------
__global__ __launch_bounds__(256) void qkv_kernel(
    const float* __restrict__ x,
    const float* __restrict__ Wq, const float* __restrict__ Wk, const float* __restrict__ Wv,
    const float* __restrict__ bq, const float* __restrict__ bk, const float* __restrict__ bv)
{
    __shared__ float xs[64][HD];
    __shared__ float Ws[16][HD + 1];

    int bh = blockIdx.y;
    int s0 = blockIdx.x * 64;
    int tid = threadIdx.x;
    int b  = bh >> 4, h = bh & 15;

    const float* xbase = x + ((size_t)b*SS + s0)*DD + h*HD;
    for (int i = tid; i < 64*32; i += 256) {
        int sr = i >> 5, dv = (i & 31) << 2;
        float4 val = *(const float4*)(xbase + (size_t)sr*DD + dv);
        xs[sr][dv+0] = val.x; xs[sr][dv+1] = val.y;
        xs[sr][dv+2] = val.z; xs[sr][dv+3] = val.w;
    }

    int ei = tid & 15, si = tid >> 4;

    for (int w = 0; w < 3; w++) {
        const float* Wh   = ((w==0) ? Wq : (w==1) ? Wk : Wv) + (size_t)h*HD*HD;
        const float* bias = ((w==0) ? bq : (w==1) ? bk : bv) + h*HD;
        for (int et = 0; et < 8; et++) {
            __syncthreads();
            for (int i = tid; i < 512; i += 256) {
                int er = i >> 5, dv = (i & 31) << 2;
                float4 val = *(const float4*)(Wh + (size_t)(et*16 + er)*HD + dv);
                Ws[er][dv+0] = val.x; Ws[er][dv+1] = val.y;
                Ws[er][dv+2] = val.z; Ws[er][dv+3] = val.w;
            }
            __syncthreads();
            float a0 = 0.f, a1 = 0.f, a2 = 0.f, a3 = 0.f;
            #pragma unroll 8
            for (int d = 0; d < HD; d++) {
                float wv = Ws[ei][d];
                a0 += xs[si     ][d] * wv;
                a1 += xs[si + 16][d] * wv;
                a2 += xs[si + 32][d] * wv;
                a3 += xs[si + 48][d] * wv;
            }
            int e = et*16 + ei;
            float bbv = bias[e];
            a0 += bbv; a1 += bbv; a2 += bbv; a3 += bbv;

            float vals[4] = {a0, a1, a2, a3};
            if (w == 2) {
                size_t vb = ((size_t)bh*HD + e)*SS + s0;
                #pragma unroll
                for (int k = 0; k < 4; k++) {
                    __nv_bfloat16 hh, ll;
                    splitbf(vals[k], hh, ll);
                    g_vthi[vb + si + 16*k] = hh;
                    g_vtlo[vb + si + 16*k] = ll;
                }
            } else {
                size_t ob = ((size_t)bh*SS + s0)*HD + e;
                __nv_bfloat16* ph = (w == 0 ? g_qhi : g_khi) + ob;
                __nv_bfloat16* pl = (w == 0 ? g_qlo : g_klo) + ob;
                #pragma unroll
                for (int k = 0; k < 4; k++) {
                    __nv_bfloat16 hh, ll;
                    splitbf(vals[k], hh, ll);
                    ph[(size_t)(si + 16*k)*HD] = hh;
                    pl[(size_t)(si + 16*k)*HD] = ll;
                }
            }
        }
    }
}

// ---------------------------------------------------------------------------
// gemm3 core: 128x128 tile, K in 64-chunks, 3 terms (AhBh + AlBh + AhBl).
// 4 buffers per stage (Ah, Al, Bh, Bl; 16KB each), 2 stages, cp.async pipe.
// acc[i(2)][j(8)][q(4)], warp layout wm(4) x wn(2).
// ---------------------------------------------------------------------------
#define G3_STAGE 65536
#define G3_SMEM  (2*G3_STAGE)

__device__ __forceinline__ void gemm3_core(
    float (*acc)[8][4], uint32_t sb, int tid,
    const __nv_bfloat16* Ah, const __nv_bfloat16* Al, size_t strideA,
    const __nv_bfloat16* Bh, const __nv_bfloat16* Bl, size_t strideB,
    int NC)
{
    int lane = tid & 31, wid = tid >> 5;
    int wm = wid & 3, wn = wid >> 2;
    int lrow = tid >> 3, lc16 = tid & 7;

    int rowa_l = wm*32 + (lane & 15);
    int ca_l   = (lane >> 4);
    int rowb_l = wn*64 + (lane & 7) + ((lane >> 4) << 3);
    int cb_l   = (lane >> 3) & 1;

    // prologue: chunk 0 -> stage 0
    {
        uint32_t sa = sb;
        #pragma unroll
        for (int rep = 0; rep < 4; rep++) {
            int row = lrow + rep*32;
            uint32_t off = (uint32_t)row*128 + 16u*(uint32_t)(lc16 ^ (row & 7));
            cpa16(sa +     0 + off, Ah + (size_t)row*strideA + lc16*8);
            cpa16(sa + 16384 + off, Al + (size_t)row*strideA + lc16*8);
            cpa16(sa + 32768 + off, Bh + (size_t)row*strideB + lc16*8);
            cpa16(sa + 49152 + off, Bl + (size_t)row*strideB + lc16*8);
        }
        asm volatile("cp.async.commit_group;");
    }

    for (int c = 0; c < NC; c++) {
        int st = c & 1;
        if (c + 1 < NC) {
            int kk = (c + 1) * 64;
            uint32_t sa = sb + (st^1)*G3_STAGE;
            #pragma unroll
            for (int rep = 0; rep < 4; rep++) {
                int row = lrow + rep*32;
                uint32_t off = (uint32_t)row*128 + 16u*(uint32_t)(lc16 ^ (row & 7));
                cpa16(sa +     0 + off, Ah + (size_t)row*strideA + kk + lc16*8);
                cpa16(sa + 16384 + off, Al + (size_t)row*strideA + kk + lc16*8);
                cpa16(sa + 32768 + off, Bh + (size_t)row*strideB + kk + lc16*8);
                cpa16(sa + 49152 + off, Bl + (size_t)row*strideB + kk + lc16*8);
            }
            asm volatile("cp.async.commit_group;");
            asm volatile("cp.async.wait_group 1;");
        } else {
            asm volatile("cp.async.wait_group 0;");
        }
        __syncthreads();

        uint32_t sa = sb + st*G3_STAGE;
        #pragma unroll
        for (int kstep = 0; kstep < 4; kstep++) {
            uint32_t ah[2][4], al[2][4];
            #pragma unroll
            for (int i = 0; i < 2; i++) {
                int row = rowa_l + i*16;
                int c16 = kstep*2 + ca_l;
                uint32_t off = (uint32_t)row*128 + 16u*(uint32_t)(c16 ^ (row & 7));
                ldsm4(ah[i], sa + off);
                ldsm4(al[i], sa + 16384 + off);
            }
            #pragma unroll
            for (int j4 = 0; j4 < 4; j4++) {
                int row = rowb_l + j4*16;
                int c16 = kstep*2 + cb_l;
                uint32_t off = (uint32_t)row*128 + 16u*(uint32_t)(c16 ^ (row & 7));
                uint32_t bhf[4], blf[4];
                ldsm4(bhf, sa + 32768 + off);
                ldsm4(blf, sa + 49152 + off);
                #pragma unroll
                for (int i = 0; i < 2; i++) {
                    mma16816(acc[i][2*j4+0], ah[i], bhf[0], bhf[1]);
                    mma16816(acc[i][2*j4+1], ah[i], bhf[2], bhf[3]);
                    mma16816(acc[i][2*j4+0], al[i], bhf[0], bhf[1]);
                    mma16816(acc[i][2*j4+1], al[i], bhf[2], bhf[3]);
                    mma16816(acc[i][2*j4+0], ah[i], blf[0], blf[1]);
                    mma16816(acc[i][2*j4+1], ah[i], blf[2], blf[3]);
                }
            }
        }
        __syncthreads();
    }
}

// ---------------------------------------------------------------------------
// Kernel 2: score GEMM  g_sc[bh][i][j] = scale * Q[i,:]·K[j,:] (causal mask)
// ---------------------------------------------------------------------------
__global__ __launch_bounds__(256) void score_gemm_kernel()
{
    int jt = blockIdx.x, it = blockIdx.y, bh = blockIdx.z;
    if (jt > it) return;

    extern __shared__ char sm3[];
    uint32_t sb = smem_u32(sm3);
    int tid = threadIdx.x, lane = tid & 31, wid = tid >> 5;
    int wm = wid & 3, wn = wid >> 2;

    float acc[2][8][4];
    #pragma unroll
    for (int i = 0; i < 2; i++)
        #pragma unroll
        for (int j = 0; j < 8; j++)
            #pragma unroll
            for (int q = 0; q < 4; q++) acc[i][j][q] = 0.f;

    size_t aoff = ((size_t)bh*SS + it*128)*HD;
    size_t boff = ((size_t)bh*SS + jt*128)*HD;
    gemm3_core(acc, sb, tid, g_qhi + aoff, g_qlo + aoff, HD,
               g_khi + boff, g_klo + boff, HD, 2);

    const float scale = 0.08838834764831845f;
    int r0w = lane >> 2, cc = (lane & 3) * 2;
    #pragma unroll
    for (int i = 0; i < 2; i++) {
        int m0 = it*128 + wm*32 + i*16 + r0w;
        int m1 = m0 + 8;
        float* row0 = g_sc + ((size_t)bh*SS + m0)*SS + jt*128 + wn*64;
        float* row1 = row0 + (size_t)8*SS;
        #pragma unroll
        for (int j = 0; j < 8; j++) {
            int j0 = jt*128 + wn*64 + j*8 + cc;
            float2 v0, v1;
            v0.x = (j0     <= m0) ? acc[i][j][0]*scale : NEGV;
            v0.y = (j0 + 1 <= m0) ? acc[i][j][1]*scale : NEGV;
            v1.x = (j0     <= m1) ? acc[i][j][2]*scale : NEGV;
            v1.y = (j0 + 1 <= m1) ? acc[i][j][3]*scale : NEGV;
            *(float2*)(row0 + j*8 + cc) = v0;
            *(float2*)(row1 + j*8 + cc) = v1;
        }
    }
}

// ---------------------------------------------------------------------------
// Kernel 3: exact top-k select + softmax -> normalized bf16 hi/lo weights
// ---------------------------------------------------------------------------
__device__ __forceinline__ unsigned f2key(float f) {
    unsigned u = __float_as_uint(f);
    return u ^ ((u & 0x80000000u) ? 0xFFFFFFFFu : 0x80000000u);
}
__device__ __forceinline__ float key2f(unsigned k) {
    unsigned u = (k & 0x80000000u) ? (k ^ 0x80000000u) : ~k;
    return __uint_as_float(u);
}

#define SCW 2056
#define SEL_SMEM (16*SCW*4 + 16*256*4)   // 147968

__global__ __launch_bounds__(512) void select_kernel()
{
    extern __shared__ char sm[];
    float* sc  = (float*)sm;
    int*  hist = (int*)(sm + 16*SCW*4);
    __shared__ float thr_s[16], lm_s[16], rsv_s[16];

    uint32_t sb = smem_u32(sm);
    int bh   = blockIdx.y;
    int s0   = (gridDim.x - 1 - blockIdx.x) * 16;
    int tid  = threadIdx.x;
    int lane = tid & 31, wid = tid >> 5;

    // ---- load 16 score rows ----
    {
        int t4 = tid * 4;
        float4 n4 = make_float4(NEGV, NEGV, NEGV, NEGV);
        #pragma unroll 1
        for (int r = 0; r < 16; r++) {
            int limit = s0 + r;
            if (t4 <= limit)
                cpa16(sb + (r*SCW + t4)*4, g_sc + ((size_t)bh*SS + limit)*SS + t4);
            else
                *(float4*)(sc + r*SCW + t4) = n4;
        }
        asm volatile("cp.async.commit_group;");
        asm volatile("cp.async.wait_group 0;");
    }
    __syncthreads();
    if (tid < 16) {
        int limit = s0 + tid;
        #pragma unroll
        for (int p = 1; p <= 3; p++) {
            int pos = limit + p;
            if (pos < SS) sc[tid*SCW + pos] = NEGV;
        }
    }
    __syncthreads();

    // ---- warp-per-row exact radix select ----
    {
        int r = wid;
        float* row = sc + r*SCW;
        int*   hh  = hist + r*256;
        unsigned prefix = 0; int K = KKEEP;
        float lm = -3.4e38f;

        #pragma unroll
        for (int pass = 0; pass < 4; pass++) {
            int shift = 24 - pass*8;
            #pragma unroll
            for (int i = lane; i < 256; i += 32) hh[i] = 0;
            __syncwarp();
            for (int t = lane; t < SS; t += 32) {
                float v = row[t];
                if (pass == 0) lm = fmaxf(lm, v);
                unsigned key = f2key(v);
                bool cand = (pass == 0) || (((key ^ prefix) >> (shift + 8)) == 0u);
                int bin = cand ? (int)((key >> shift) & 255u) : -1;
                unsigned peers = __match_any_sync(FULLW, bin);
                if (cand && lane == (__ffs(peers) - 1))
                    atomicAdd(&hh[bin], __popc(peers));
            }
            __syncwarp();
            int hv[8]; int ssum = 0;
            #pragma unroll
            for (int i = 0; i < 8; i++) { hv[i] = hh[lane*8 + i]; ssum += hv[i]; }
            int suf = ssum;
            #pragma unroll
            for (int off = 1; off < 32; off <<= 1) {
                int v = __shfl_down_sync(FULLW, suf, off);
                if (lane + off < 32) suf += v;
            }
            int above = suf - ssum;
            int selbin = -1, newK = 0;
            if (suf >= K && above < K) {
                int run = above;
                #pragma unroll
                for (int bb2 = 7; bb2 >= 0; bb2--) {
                    run += hv[bb2];
                    if (run >= K) { selbin = lane*8 + bb2; newK = K - (run - hv[bb2]); break; }
                }
            }
            unsigned msk = __ballot_sync(FULLW, selbin >= 0);
            int src = __ffs(msk) - 1;
            selbin = __shfl_sync(FULLW, selbin, src);
            newK   = __shfl_sync(FULLW, newK,  src);
            prefix |= ((unsigned)selbin) << shift;
            K = newK;
        }
        float thr = key2f(prefix);

        #pragma unroll
        for (int off = 16; off > 0; off >>= 1)
            lm = fmaxf(lm, __shfl_xor_sync(FULLW, lm, off));

        // sum of kept weights (only t <= limit can be kept with nonzero weight)
        int limit = s0 + r;
        float ls = 0.f;
        for (int t = lane; t <= limit; t += 32) {
            float v = row[t];
            if (v >= thr) ls += __expf(v - lm);
        }
        #pragma unroll
        for (int off = 16; off > 0; off >>= 1)
            ls += __shfl_xor_sync(FULLW, ls, off);
        if (lane == 0) { thr_s[r] = thr; lm_s[r] = lm; rsv_s[r] = 1.f / ls; }
    }
    __syncthreads();

    // ---- block-wide normalized-weight write (zero-padded to tile boundary) ----
    {
        int CEIL = (s0 & ~127) + 128;
        int t4 = tid * 4;
        if (t4 < CEIL) {
            #pragma unroll 1
            for (int r = 0; r < 16; r++) {
                float thr = thr_s[r], lm = lm_s[r], rsv = rsv_s[r];
                float4 v4 = *(const float4*)(sc + r*SCW + t4);
                float w0 = 0.f, w1 = 0.f, w2 = 0.f, w3 = 0.f;
                if (v4.x >= thr) w0 = __expf(v4.x - lm) * rsv;
                if (v4.y >= thr) w1 = __expf(v4.y - lm) * rsv;
                if (v4.z >= thr) w2 = __expf(v4.z - lm) * rsv;
                if (v4.w >= thr) w3 = __expf(v4.w - lm) * rsv;
                __nv_bfloat16 h0,l0,h1,l1,h2,l2,h3,l3;
                splitbf(w0,h0,l0); splitbf(w1,h1,l1);
                splitbf(w2,h2,l2); splitbf(w3,h3,l3);
                uint2 ph, pl;
                ph.x = (unsigned)*(unsigned short*)&h0 | ((unsigned)*(unsigned short*)&h1 << 16);
                ph.y = (unsigned)*(unsigned short*)&h2 | ((unsigned)*(unsigned short*)&h3 << 16);
                pl.x = (unsigned)*(unsigned short*)&l0 | ((unsigned)*(unsigned short*)&l1 << 16);
                pl.y = (unsigned)*(unsigned short*)&l2 | ((unsigned)*(unsigned short*)&l3 << 16);
                size_t go = ((size_t)bh*SS + s0 + r)*SS + t4;
                *(uint2*)(g_wh + go) = ph;
                *(uint2*)(g_wl + go) = pl;
            }
        }
    }
}

// ---------------------------------------------------------------------------
// Kernel 4: AV GEMM (transposed): outT[d, s] = sum_t V^T[d,t] * W[s,t]
// epilogue split-stores straight into g_Ahi/g_Alo [b][h*128+d][s]
// ---------------------------------------------------------------------------
__global__ __launch_bounds__(256) void av_gemm_kernel()
{
    int st = gridDim.x - 1 - blockIdx.x;   // longest first
    int bh = blockIdx.y;

    extern __shared__ char sm3[];
    uint32_t sb = smem_u32(sm3);
    int tid = threadIdx.x, lane = tid & 31, wid = tid >> 5;
    int wm = wid & 3, wn = wid >> 2;

    float acc[2][8][4];
    #pragma unroll
    for (int i = 0; i < 2; i++)
        #pragma unroll
        for (int j = 0; j < 8; j++)
            #pragma unroll
            for (int q = 0; q < 4; q++) acc[i][j][q] = 0.f;

    size_t aoff = (size_t)bh*HD*SS;                 // V^T rows (d)
    size_t boff = ((size_t)bh*SS + st*128)*SS;      // weight rows (s)
    gemm3_core(acc, sb, tid, g_vthi + aoff, g_vtlo + aoff, SS,
               g_wh + boff, g_wl + boff, SS, 2*(st + 1));

    int b = bh >> 4, h = bh & 15;
    int r0w = lane >> 2, cc = (lane & 3) * 2;
    #pragma unroll
    for (int i = 0; i < 2; i++) {
        int d0 = wm*32 + i*16 + r0w;
        size_t rowA = ((size_t)b*DD + h*HD + d0)*SS;
        size_t rowB = rowA + (size_t)8*SS;
        #pragma unroll
        for (int j = 0; j < 8; j++) {
            int s_col = st*128 + wn*64 + j*8 + cc;
            __nv_bfloat16 h0,l0,h1,l1;
            splitbf(acc[i][j][0], h0, l0);
            splitbf(acc[i][j][1], h1, l1);
            *(unsigned*)(g_Ahi + rowA + s_col) =
                (unsigned)*(unsigned short*)&h0 | ((unsigned)*(unsigned short*)&h1 << 16);
            *(unsigned*)(g_Alo + rowA + s_col) =
                (unsigned)*(unsigned short*)&l0 | ((unsigned)*(unsigned short*)&l1 << 16);
            splitbf(acc[i][j][2], h0, l0);
            splitbf(acc[i][j][3], h1, l1);
            *(unsigned*)(g_Ahi + rowB + s_col) =
                (unsigned)*(unsigned short*)&h0 | ((unsigned)*(unsigned short*)&h1 << 16);
            *(unsigned*)(g_Alo + rowB + s_col) =
                (unsigned)*(unsigned short*)&l0 | ((unsigned)*(unsigned short*)&l1 << 16);
        }
    }
}

// ---------------------------------------------------------------------------
// Kernel 5: fp32 -> bf16 hi/lo split for Wo
// ---------------------------------------------------------------------------
__global__ __launch_bounds__(256) void split_kernel(const float* __restrict__ Wo)
{
    int row = blockIdx.x;
    int tid = threadIdx.x;
    const float* src = Wo + (size_t)row*SS;
    __nv_bfloat16* dhi = g_Whi + (size_t)row*SS;
    __nv_bfloat16* dlo = g_Wlo + (size_t)row*SS;

    int base = tid * 8;
    float4 f0 = *(const float4*)(src + base);
    float4 f1 = *(const float4*)(src + base + 4);
    float v[8] = {f0.x, f0.y, f0.z, f0.w, f1.x, f1.y, f1.z, f1.w};
    unsigned hw[4], lw[4];
    #pragma unroll
    for (int p = 0; p < 4; p++) {
        __nv_bfloat16 ha, hb, la, lb;
        splitbf(v[2*p], ha, la);
        splitbf(v[2*p+1], hb, lb);
        __nv_bfloat162 hp = __halves2bfloat162(ha, hb);
        __nv_bfloat162 lp = __halves2bfloat162(la, lb);
        hw[p] = *(unsigned*)&hp;
        lw[p] = *(unsigned*)&lp;
    }
    *(uint4*)(dhi + base) = make_uint4(hw[0], hw[1], hw[2], hw[3]);
    *(uint4*)(dlo + base) = make_uint4(lw[0], lw[1], lw[2], lw[3]);
}

// ---------------------------------------------------------------------------
// Kernel 6: proj GEMM  out[b, m, n] = sum_s A[m,s]*W[n,s] + bo[n]  (3 segs)
// ---------------------------------------------------------------------------
#define PJ_STAGE 32768
#define PJ_SMEM  (2*PJ_STAGE)

__global__ __launch_bounds__(256) void proj_mma_kernel(
    const float* __restrict__ bo, float* __restrict__ out)
{
    extern __shared__ char psm[];
    uint32_t sb = smem_u32(psm);

    int tid = threadIdx.x, lane = tid & 31, wid = tid >> 5;
    int wm = wid & 3, wn = wid >> 2;
    int nt = blockIdx.x, mt = blockIdx.y, b = blockIdx.z;

    const __nv_bfloat16* Abase   = g_Ahi + ((size_t)b*DD + mt*128)*SS;
    const __nv_bfloat16* AbaseLo = g_Alo + ((size_t)b*DD + mt*128)*SS;
    const __nv_bfloat16* Wbase   = g_Whi + (size_t)(nt*128)*SS;
    const __nv_bfloat16* WbaseLo = g_Wlo + (size_t)(nt*128)*SS;

    int lrow = tid >> 3, lc16 = tid & 7;

    float acc[2][8][4];
    #pragma unroll
    for (int i = 0; i < 2; i++)
        #pragma unroll
        for (int j = 0; j < 8; j++)
            #pragma unroll
            for (int q = 0; q < 4; q++) acc[i][j][q] = 0.f;

    int rowa_l = wm*32 + (lane & 15);
    int ca_l   = (lane >> 4);
    int rowb_l = wn*64 + (lane & 7) + ((lane >> 4) << 3);
    int cb_l   = (lane >> 3) & 1;

    const int NC = 96;

    {
        uint32_t sa = sb, sbB = sb + 16384;
        #pragma unroll
        for (int rep = 0; rep < 4; rep++) {
            int row = lrow + rep*32;
            uint32_t off = (uint32_t)row*128 + 16u*(uint32_t)(lc16 ^ (row & 7));
            cpa16(sa  + off, Abase + (size_t)row*SS + lc16*8);
            cpa16(sbB + off, Wbase + (size_t)row*SS + lc16*8);
        }
        asm volatile("cp.async.commit_group;");
    }

    for (int c = 0; c < NC; c++) {
        int st = c & 1;
        if (c + 1 < NC) {
            int nc2 = c + 1;
            int seg = nc2 >> 5, kk = (nc2 & 31) * 64;
            const __nv_bfloat16* As = (seg == 1 ? AbaseLo : Abase);
            const __nv_bfloat16* Bs = (seg == 2 ? WbaseLo : Wbase);
            uint32_t sa = sb + (st^1)*PJ_STAGE, sbB = sa + 16384;
            #pragma unroll
            for (int rep = 0; rep < 4; rep++) {
                int row = lrow + rep*32;
                uint32_t off = (uint32_t)row*128 + 16u*(uint32_t)(lc16 ^ (row & 7));
                cpa16(sa  + off, As + (size_t)row*SS + kk + lc16*8);
                cpa16(sbB + off, Bs + (size_t)row*SS + kk + lc16*8);
            }
            asm volatile("cp.async.commit_group;");
            asm volatile("cp.async.wait_group 1;");
        } else {
            asm volatile("cp.async.wait_group 0;");
        }
        __syncthreads();

        uint32_t sa = sb + st*PJ_STAGE, sbB = sa + 16384;
        #pragma unroll
        for (int kstep = 0; kstep < 4; kstep++) {
            uint32_t afr[2][4];
            #pragma unroll
            for (int i = 0; i < 2; i++) {
                int row = rowa_l + i*16;
                int c16 = kstep*2 + ca_l;
                ldsm4(afr[i], sa + (uint32_t)row*128 + 16u*(uint32_t)(c16 ^ (row & 7)));
            }
            uint32_t bfr[4][4];
            #pragma unroll
            for (int j4 = 0; j4 < 4; j4++) {
                int row = rowb_l + j4*16;
                int c16 = kstep*2 + cb_l;
                ldsm4(bfr[j4], sbB + (uint32_t)row*128 + 16u*(uint32_t)(c16 ^ (row & 7)));
            }
            #pragma unroll
            for (int i = 0; i < 2; i++)
                #pragma unroll
                for (int j4 = 0; j4 < 4; j4++) {
                    mma16816(acc[i][2*j4+0], afr[i], bfr[j4][0], bfr[j4][1]);
                    mma16816(acc[i][2*j4+1], afr[i], bfr[j4][2], bfr[j4][3]);
                }
        }
        __syncthreads();
    }

    int r0w = lane >> 2, cc = (lane & 3) * 2;
    const float* bop = bo + nt*128 + wn*64;
    #pragma unroll
    for (int i = 0; i < 2; i++) {
        int m = mt*128 + wm*32 + i*16 + r0w;
        float* row0 = out + ((size_t)b*DD + m)*DD + nt*128 + wn*64;
        float* row1 = row0 + (size_t)8*DD;
        #pragma unroll
        for (int j = 0; j < 8; j++) {
            float2 bb = *(const float2*)(bop + j*8 + cc);
            float2 v0 = make_float2(acc[i][j][0] + bb.x, acc[i][j][1] + bb.y);
            float2 v1 = make_float2(acc[i][j][2] + bb.x, acc[i][j][3] + bb.y);
            *(float2*)(row0 + j*8 + cc) = v0;
            *(float2*)(row1 + j*8 + cc) = v1;
        }
    }
}

// ---------------------------------------------------------------------------
extern "C" void kernel_launch(void* const* d_in, const int* in_sizes, int n_in,
                              void* d_out, int out_size)
{
    const float* x  = (const float*)d_in[0];
    const float* Wq = (const float*)d_in[2];
    const float* Wk = (const float*)d_in[3];
    const float* Wv = (const float*)d_in[4];
    const float* bq = (const float*)d_in[5];
    const float* bk = (const float*)d_in[6];
    const float* bv = (const float*)d_in[7];
    const float* Wo = (const float*)d_in[8];
    const float* bo = (const float*)d_in[9];
    float* out = (float*)d_out;

    qkv_kernel<<<dim3(SS/64, BB*HH), 256>>>(x, Wq, Wk, Wv, bq, bk, bv);

    split_kernel<<<dim3(DD), 256>>>(Wo);

    cudaFuncSetAttribute(score_gemm_kernel, cudaFuncAttributeMaxDynamicSharedMemorySize, G3_SMEM);
    score_gemm_kernel<<<dim3(16, 16, BB*HH), 256, G3_SMEM>>>();

    cudaFuncSetAttribute(select_kernel, cudaFuncAttributeMaxDynamicSharedMemorySize, SEL_SMEM);
    select_kernel<<<dim3(SS/16, BB*HH), 512, SEL_SMEM>>>();

    cudaFuncSetAttribute(av_gemm_kernel, cudaFuncAttributeMaxDynamicSharedMemorySize, G3_SMEM);
    av_gemm_kernel<<<dim3(16, BB*HH), 256, G3_SMEM>>>();

    cudaFuncSetAttribute(proj_mma_kernel, cudaFuncAttributeMaxDynamicSharedMemorySize, PJ_SMEM);
    proj_mma_kernel<<<dim3(16, 16, BB), 256, PJ_SMEM>>>(bo, out);
}

// round 11
// speedup vs baseline: 3.8709x; 1.3697x over previous
#include <cuda_runtime.h>
#include <cuda_bf16.h>
#include <cstdint>
#include <math.h>

#define BB 2
#define HH 16
#define SS 2048
#define HD 128
#define DD 2048
#define KKEEP 819
#define NEGV -1e9f
#define FULLW 0xffffffffu

// ---------------- scratch (device globals; no allocation allowed) ----------
__device__ __nv_bfloat16 g_qhi [BB*HH*SS*HD];  // [bh][s][d]
__device__ __nv_bfloat16 g_qlo [BB*HH*SS*HD];
__device__ __nv_bfloat16 g_khi [BB*HH*SS*HD];  // [bh][t][d]
__device__ __nv_bfloat16 g_klo [BB*HH*SS*HD];
__device__ __nv_bfloat16 g_vthi[BB*HH*HD*SS];  // [bh][d][t]
__device__ __nv_bfloat16 g_vtlo[BB*HH*HD*SS];

__device__ float         g_sc [(size_t)BB*HH*SS*SS];   // scores [bh][s][t]
__device__ __nv_bfloat16 g_wh [(size_t)BB*HH*SS*SS];   // normalized weights hi
__device__ __nv_bfloat16 g_wl [(size_t)BB*HH*SS*SS];   // normalized weights lo

// proj operands (A written directly by av_gemm epilogue)
__device__ __nv_bfloat16 g_Ahi[(size_t)BB*DD*SS];      // [b][i][s]
__device__ __nv_bfloat16 g_Alo[(size_t)BB*DD*SS];
__device__ __nv_bfloat16 g_Whi[(size_t)DD*SS];
__device__ __nv_bfloat16 g_Wlo[(size_t)DD*SS];

// ---------------- common helpers -------------------------------------------
__device__ __forceinline__ uint32_t smem_u32(const void* p) {
    uint32_t a;
    asm("{ .reg .u64 t; cvta.to.shared.u64 t, %1; cvt.u32.u64 %0, t; }" : "=r"(a) : "l"(p));
    return a;
}
__device__ __forceinline__ void cpa16(uint32_t s, const void* g) {
    asm volatile("cp.async.cg.shared.global [%0], [%1], 16;" :: "r"(s), "l"(g));
}
__device__ __forceinline__ void ldsm4(uint32_t* r, uint32_t a) {
    asm volatile("ldmatrix.sync.aligned.m8n8.x4.shared.b16 {%0,%1,%2,%3}, [%4];"
                 : "=r"(r[0]), "=r"(r[1]), "=r"(r[2]), "=r"(r[3]) : "r"(a));
}
__device__ __forceinline__ void mma16816(float* c, const uint32_t* a, uint32_t b0, uint32_t b1) {
    asm volatile("mma.sync.aligned.m16n8k16.row.col.f32.bf16.bf16.f32 "
                 "{%0,%1,%2,%3}, {%4,%5,%6,%7}, {%8,%9}, {%0,%1,%2,%3};"
                 : "+f"(c[0]), "+f"(c[1]), "+f"(c[2]), "+f"(c[3])
                 : "r"(a[0]), "r"(a[1]), "r"(a[2]), "r"(a[3]), "r"(b0), "r"(b1));
}
__device__ __forceinline__ void splitbf(float a, __nv_bfloat16& h, __nv_bfloat16& l) {
    h = __float2bfloat16(a);
    l = __float2bfloat16(a - __bfloat162float(h));
}

// ---------------------------------------------------------------------------
// Kernel 1: per-head QKV projections -> bf16 hi/lo operands
// ---------------------------------------------------------------------------
__global__ __launch_bounds__(256) void qkv_kernel(
    const float* __restrict__ x,
    const float* __restrict__ Wq, const float* __restrict__ Wk, const float* __restrict__ Wv,
    const float* __restrict__ bq, const float* __restrict__ bk, const float* __restrict__ bv)
{
    __shared__ float xs[64][HD];
    __shared__ float Ws[16][HD + 1];

    int bh = blockIdx.y;
    int s0 = blockIdx.x * 64;
    int tid = threadIdx.x;
    int b  = bh >> 4, h = bh & 15;

    const float* xbase = x + ((size_t)b*SS + s0)*DD + h*HD;
    for (int i = tid; i < 64*32; i += 256) {
        int sr = i >> 5, dv = (i & 31) << 2;
        float4 val = *(const float4*)(xbase + (size_t)sr*DD + dv);
        xs[sr][dv+0] = val.x; xs[sr][dv+1] = val.y;
        xs[sr][dv+2] = val.z; xs[sr][dv+3] = val.w;
    }

    int ei = tid & 15, si = tid >> 4;

    for (int w = 0; w < 3; w++) {
        const float* Wh   = ((w==0) ? Wq : (w==1) ? Wk : Wv) + (size_t)h*HD*HD;
        const float* bias = ((w==0) ? bq : (w==1) ? bk : bv) + h*HD;
        for (int et = 0; et < 8; et++) {
            __syncthreads();
            for (int i = tid; i < 512; i += 256) {
                int er = i >> 5, dv = (i & 31) << 2;
                float4 val = *(const float4*)(Wh + (size_t)(et*16 + er)*HD + dv);
                Ws[er][dv+0] = val.x; Ws[er][dv+1] = val.y;
                Ws[er][dv+2] = val.z; Ws[er][dv+3] = val.w;
            }
            __syncthreads();
            float a0 = 0.f, a1 = 0.f, a2 = 0.f, a3 = 0.f;
            #pragma unroll 8
            for (int d = 0; d < HD; d++) {
                float wv = Ws[ei][d];
                a0 += xs[si     ][d] * wv;
                a1 += xs[si + 16][d] * wv;
                a2 += xs[si + 32][d] * wv;
                a3 += xs[si + 48][d] * wv;
            }
            int e = et*16 + ei;
            float bbv = bias[e];
            a0 += bbv; a1 += bbv; a2 += bbv; a3 += bbv;

            float vals[4] = {a0, a1, a2, a3};
            if (w == 2) {
                size_t vb = ((size_t)bh*HD + e)*SS + s0;
                #pragma unroll
                for (int k = 0; k < 4; k++) {
                    __nv_bfloat16 hh, ll;
                    splitbf(vals[k], hh, ll);
                    g_vthi[vb + si + 16*k] = hh;
                    g_vtlo[vb + si + 16*k] = ll;
                }
            } else {
                size_t ob = ((size_t)bh*SS + s0)*HD + e;
                __nv_bfloat16* ph = (w == 0 ? g_qhi : g_khi) + ob;
                __nv_bfloat16* pl = (w == 0 ? g_qlo : g_klo) + ob;
                #pragma unroll
                for (int k = 0; k < 4; k++) {
                    __nv_bfloat16 hh, ll;
                    splitbf(vals[k], hh, ll);
                    ph[(size_t)(si + 16*k)*HD] = hh;
                    pl[(size_t)(si + 16*k)*HD] = ll;
                }
            }
        }
    }
}

// ---------------------------------------------------------------------------
// gemm3 core: 128x128 tile, K in 64-chunks, 3 terms (AhBh + AlBh + AhBl).
// ---------------------------------------------------------------------------
#define G3_STAGE 65536
#define G3_SMEM  (2*G3_STAGE)

__device__ __forceinline__ void gemm3_core(
    float (*acc)[8][4], uint32_t sb, int tid,
    const __nv_bfloat16* Ah, const __nv_bfloat16* Al, size_t strideA,
    const __nv_bfloat16* Bh, const __nv_bfloat16* Bl, size_t strideB,
    int NC)
{
    int lane = tid & 31, wid = tid >> 5;
    int wm = wid & 3, wn = wid >> 2;
    int lrow = tid >> 3, lc16 = tid & 7;

    int rowa_l = wm*32 + (lane & 15);
    int ca_l   = (lane >> 4);
    int rowb_l = wn*64 + (lane & 7) + ((lane >> 4) << 3);
    int cb_l   = (lane >> 3) & 1;

    {
        uint32_t sa = sb;
        #pragma unroll
        for (int rep = 0; rep < 4; rep++) {
            int row = lrow + rep*32;
            uint32_t off = (uint32_t)row*128 + 16u*(uint32_t)(lc16 ^ (row & 7));
            cpa16(sa +     0 + off, Ah + (size_t)row*strideA + lc16*8);
            cpa16(sa + 16384 + off, Al + (size_t)row*strideA + lc16*8);
            cpa16(sa + 32768 + off, Bh + (size_t)row*strideB + lc16*8);
            cpa16(sa + 49152 + off, Bl + (size_t)row*strideB + lc16*8);
        }
        asm volatile("cp.async.commit_group;");
    }

    for (int c = 0; c < NC; c++) {
        int st = c & 1;
        if (c + 1 < NC) {
            int kk = (c + 1) * 64;
            uint32_t sa = sb + (st^1)*G3_STAGE;
            #pragma unroll
            for (int rep = 0; rep < 4; rep++) {
                int row = lrow + rep*32;
                uint32_t off = (uint32_t)row*128 + 16u*(uint32_t)(lc16 ^ (row & 7));
                cpa16(sa +     0 + off, Ah + (size_t)row*strideA + kk + lc16*8);
                cpa16(sa + 16384 + off, Al + (size_t)row*strideA + kk + lc16*8);
                cpa16(sa + 32768 + off, Bh + (size_t)row*strideB + kk + lc16*8);
                cpa16(sa + 49152 + off, Bl + (size_t)row*strideB + kk + lc16*8);
            }
            asm volatile("cp.async.commit_group;");
            asm volatile("cp.async.wait_group 1;");
        } else {
            asm volatile("cp.async.wait_group 0;");
        }
        __syncthreads();

        uint32_t sa = sb + st*G3_STAGE;
        #pragma unroll
        for (int kstep = 0; kstep < 4; kstep++) {
            uint32_t ah[2][4], al[2][4];
            #pragma unroll
            for (int i = 0; i < 2; i++) {
                int row = rowa_l + i*16;
                int c16 = kstep*2 + ca_l;
                uint32_t off = (uint32_t)row*128 + 16u*(uint32_t)(c16 ^ (row & 7));
                ldsm4(ah[i], sa + off);
                ldsm4(al[i], sa + 16384 + off);
            }
            #pragma unroll
            for (int j4 = 0; j4 < 4; j4++) {
                int row = rowb_l + j4*16;
                int c16 = kstep*2 + cb_l;
                uint32_t off = (uint32_t)row*128 + 16u*(uint32_t)(c16 ^ (row & 7));
                uint32_t bhf[4], blf[4];
                ldsm4(bhf, sa + 32768 + off);
                ldsm4(blf, sa + 49152 + off);
                #pragma unroll
                for (int i = 0; i < 2; i++) {
                    mma16816(acc[i][2*j4+0], ah[i], bhf[0], bhf[1]);
                    mma16816(acc[i][2*j4+1], ah[i], bhf[2], bhf[3]);
                    mma16816(acc[i][2*j4+0], al[i], bhf[0], bhf[1]);
                    mma16816(acc[i][2*j4+1], al[i], bhf[2], bhf[3]);
                    mma16816(acc[i][2*j4+0], ah[i], blf[0], blf[1]);
                    mma16816(acc[i][2*j4+1], ah[i], blf[2], blf[3]);
                }
            }
        }
        __syncthreads();
    }
}

// ---------------------------------------------------------------------------
// Kernel 2: score GEMM  g_sc[bh][i][j] = scale * Q[i,:]·K[j,:] (causal mask)
// ---------------------------------------------------------------------------
__global__ __launch_bounds__(256) void score_gemm_kernel()
{
    int jt = blockIdx.x, it = blockIdx.y, bh = blockIdx.z;
    if (jt > it) return;

    extern __shared__ char sm3[];
    uint32_t sb = smem_u32(sm3);
    int tid = threadIdx.x, lane = tid & 31, wid = tid >> 5;
    int wm = wid & 3, wn = wid >> 2;

    float acc[2][8][4];
    #pragma unroll
    for (int i = 0; i < 2; i++)
        #pragma unroll
        for (int j = 0; j < 8; j++)
            #pragma unroll
            for (int q = 0; q < 4; q++) acc[i][j][q] = 0.f;

    size_t aoff = ((size_t)bh*SS + it*128)*HD;
    size_t boff = ((size_t)bh*SS + jt*128)*HD;
    gemm3_core(acc, sb, tid, g_qhi + aoff, g_qlo + aoff, HD,
               g_khi + boff, g_klo + boff, HD, 2);

    const float scale = 0.08838834764831845f;
    int r0w = lane >> 2, cc = (lane & 3) * 2;
    #pragma unroll
    for (int i = 0; i < 2; i++) {
        int m0 = it*128 + wm*32 + i*16 + r0w;
        int m1 = m0 + 8;
        float* row0 = g_sc + ((size_t)bh*SS + m0)*SS + jt*128 + wn*64;
        float* row1 = row0 + (size_t)8*SS;
        #pragma unroll
        for (int j = 0; j < 8; j++) {
            int j0 = jt*128 + wn*64 + j*8 + cc;
            float2 v0, v1;
            v0.x = (j0     <= m0) ? acc[i][j][0]*scale : NEGV;
            v0.y = (j0 + 1 <= m0) ? acc[i][j][1]*scale : NEGV;
            v1.x = (j0     <= m1) ? acc[i][j][2]*scale : NEGV;
            v1.y = (j0 + 1 <= m1) ? acc[i][j][3]*scale : NEGV;
            *(float2*)(row0 + j*8 + cc) = v0;
            *(float2*)(row1 + j*8 + cc) = v1;
        }
    }
}

// ---------------------------------------------------------------------------
// Kernel 3: exact top-k select + softmax -> normalized bf16 hi/lo weights.
// Warp-per-row, gmem-direct, only t <= s swept (rounded to warp multiples so
// all 32 lanes stay converged for __match_any_sync), cheap-row skip.
// ---------------------------------------------------------------------------
__device__ __forceinline__ unsigned f2key(float f) {
    unsigned u = __float_as_uint(f);
    return u ^ ((u & 0x80000000u) ? 0xFFFFFFFFu : 0x80000000u);
}
__device__ __forceinline__ float key2f(unsigned k) {
    unsigned u = (k & 0x80000000u) ? (k ^ 0x80000000u) : ~k;
    return __uint_as_float(u);
}

__global__ __launch_bounds__(512) void select_kernel()
{
    __shared__ int hist[16*256];   // per-warp histograms, 16KB

    int bh   = blockIdx.y;
    int s0   = (gridDim.x - 1 - blockIdx.x) * 16;   // longest rows first
    int tid  = threadIdx.x;
    int lane = tid & 31, wid = tid >> 5;
    int s    = s0 + wid;
    int nvalid = s + 1;
    int nround = (nvalid + 31) & ~31;               // <= SS; keeps warp converged

    const float* row = g_sc + ((size_t)bh*SS + s)*SS;
    int* hh = hist + wid*256;

    float lm  = -3.4e38f;
    float thr = -3.4e38f;

    if (s >= KKEEP - 1) {
        // exact radix select over the nvalid (>= KKEEP) valid entries.
        // Tail lanes (t >= nvalid) stay in the loop with bin=-1 so every
        // __match_any_sync sees the full converged warp.
        unsigned prefix = 0; int K = KKEEP;
        #pragma unroll
        for (int pass = 0; pass < 4; pass++) {
            int shift = 24 - pass*8;
            #pragma unroll
            for (int i = lane; i < 256; i += 32) hh[i] = 0;
            __syncwarp();
            for (int t = lane; t < nround; t += 32) {
                bool valid = (t < nvalid);
                float v = valid ? row[t] : NEGV;
                if (pass == 0 && valid) lm = fmaxf(lm, v);
                unsigned key = f2key(v);
                bool cand = valid &&
                    ((pass == 0) || (((key ^ prefix) >> (shift + 8)) == 0u));
                int bin = cand ? (int)((key >> shift) & 255u) : -1;
                unsigned peers = __match_any_sync(FULLW, bin);
                if (cand && lane == (__ffs(peers) - 1))
                    atomicAdd(&hh[bin], __popc(peers));
            }
            __syncwarp();
            int hv[8]; int ssum = 0;
            #pragma unroll
            for (int i = 0; i < 8; i++) { hv[i] = hh[lane*8 + i]; ssum += hv[i]; }
            int suf = ssum;
            #pragma unroll
            for (int off = 1; off < 32; off <<= 1) {
                int v = __shfl_down_sync(FULLW, suf, off);
                if (lane + off < 32) suf += v;
            }
            int above = suf - ssum;
            int selbin = -1, newK = 0;
            if (suf >= K && above < K) {
                int run = above;
                #pragma unroll
                for (int bb2 = 7; bb2 >= 0; bb2--) {
                    run += hv[bb2];
                    if (run >= K) { selbin = lane*8 + bb2; newK = K - (run - hv[bb2]); break; }
                }
            }
            unsigned msk = __ballot_sync(FULLW, selbin >= 0);
            int src = __ffs(msk) - 1;
            selbin = __shfl_sync(FULLW, selbin, src);
            newK   = __shfl_sync(FULLW, newK,  src);
            prefix |= ((unsigned)selbin) << shift;
            K = newK;
        }
        thr = key2f(prefix);
    } else {
        // kth of full row is NEGV -> keep all valid entries
        for (int t = lane; t < nvalid; t += 32) lm = fmaxf(lm, row[t]);
    }

    #pragma unroll
    for (int off = 16; off > 0; off >>= 1)
        lm = fmaxf(lm, __shfl_xor_sync(FULLW, lm, off));

    // sum of kept weights (L1-resident re-read)
    float ls = 0.f;
    for (int t = lane; t < nvalid; t += 32) {
        float v = row[t];
        if (v >= thr) ls += __expf(v - lm);
    }
    #pragma unroll
    for (int off = 16; off > 0; off >>= 1)
        ls += __shfl_xor_sync(FULLW, ls, off);
    float rsv = 1.f / ls;

    // write normalized weights, zero-padded to the block's 128-tile ceiling
    int CEIL = (s0 & ~127) + 128;
    size_t go = ((size_t)bh*SS + s)*SS;
    for (int t4 = lane*4; t4 < CEIL; t4 += 128) {
        float w0 = 0.f, w1 = 0.f, w2 = 0.f, w3 = 0.f;
        if (t4 + 3 < nvalid) {
            float4 v4 = *(const float4*)(row + t4);
            if (v4.x >= thr) w0 = __expf(v4.x - lm) * rsv;
            if (v4.y >= thr) w1 = __expf(v4.y - lm) * rsv;
            if (v4.z >= thr) w2 = __expf(v4.z - lm) * rsv;
            if (v4.w >= thr) w3 = __expf(v4.w - lm) * rsv;
        } else if (t4 < nvalid) {
            float vv;
            vv = row[t4];
            if (vv >= thr) w0 = __expf(vv - lm) * rsv;
            if (t4 + 1 < nvalid) { vv = row[t4+1]; if (vv >= thr) w1 = __expf(vv - lm) * rsv; }
            if (t4 + 2 < nvalid) { vv = row[t4+2]; if (vv >= thr) w2 = __expf(vv - lm) * rsv; }
        }
        __nv_bfloat16 h0,l0,h1,l1,h2,l2,h3,l3;
        splitbf(w0,h0,l0); splitbf(w1,h1,l1);
        splitbf(w2,h2,l2); splitbf(w3,h3,l3);
        uint2 ph, pl;
        ph.x = (unsigned)*(unsigned short*)&h0 | ((unsigned)*(unsigned short*)&h1 << 16);
        ph.y = (unsigned)*(unsigned short*)&h2 | ((unsigned)*(unsigned short*)&h3 << 16);
        pl.x = (unsigned)*(unsigned short*)&l0 | ((unsigned)*(unsigned short*)&l1 << 16);
        pl.y = (unsigned)*(unsigned short*)&l2 | ((unsigned)*(unsigned short*)&l3 << 16);
        *(uint2*)(g_wh + go + t4) = ph;
        *(uint2*)(g_wl + go + t4) = pl;
    }
}

// ---------------------------------------------------------------------------
// Kernel 4: AV GEMM (transposed): outT[d, s] = sum_t V^T[d,t] * W[s,t]
// ---------------------------------------------------------------------------
__global__ __launch_bounds__(256) void av_gemm_kernel()
{
    int st = gridDim.x - 1 - blockIdx.x;   // longest first
    int bh = blockIdx.y;

    extern __shared__ char sm3[];
    uint32_t sb = smem_u32(sm3);
    int tid = threadIdx.x, lane = tid & 31, wid = tid >> 5;
    int wm = wid & 3, wn = wid >> 2;

    float acc[2][8][4];
    #pragma unroll
    for (int i = 0; i < 2; i++)
        #pragma unroll
        for (int j = 0; j < 8; j++)
            #pragma unroll
            for (int q = 0; q < 4; q++) acc[i][j][q] = 0.f;

    size_t aoff = (size_t)bh*HD*SS;
    size_t boff = ((size_t)bh*SS + st*128)*SS;
    gemm3_core(acc, sb, tid, g_vthi + aoff, g_vtlo + aoff, SS,
               g_wh + boff, g_wl + boff, SS, 2*(st + 1));

    int b = bh >> 4, h = bh & 15;
    int r0w = lane >> 2, cc = (lane & 3) * 2;
    #pragma unroll
    for (int i = 0; i < 2; i++) {
        int d0 = wm*32 + i*16 + r0w;
        size_t rowA = ((size_t)b*DD + h*HD + d0)*SS;
        size_t rowB = rowA + (size_t)8*SS;
        #pragma unroll
        for (int j = 0; j < 8; j++) {
            int s_col = st*128 + wn*64 + j*8 + cc;
            __nv_bfloat16 h0,l0,h1,l1;
            splitbf(acc[i][j][0], h0, l0);
            splitbf(acc[i][j][1], h1, l1);
            *(unsigned*)(g_Ahi + rowA + s_col) =
                (unsigned)*(unsigned short*)&h0 | ((unsigned)*(unsigned short*)&h1 << 16);
            *(unsigned*)(g_Alo + rowA + s_col) =
                (unsigned)*(unsigned short*)&l0 | ((unsigned)*(unsigned short*)&l1 << 16);
            splitbf(acc[i][j][2], h0, l0);
            splitbf(acc[i][j][3], h1, l1);
            *(unsigned*)(g_Ahi + rowB + s_col) =
                (unsigned)*(unsigned short*)&h0 | ((unsigned)*(unsigned short*)&h1 << 16);
            *(unsigned*)(g_Alo + rowB + s_col) =
                (unsigned)*(unsigned short*)&l0 | ((unsigned)*(unsigned short*)&l1 << 16);
        }
    }
}

// ---------------------------------------------------------------------------
// Kernel 5: fp32 -> bf16 hi/lo split for Wo
// ---------------------------------------------------------------------------
__global__ __launch_bounds__(256) void split_kernel(const float* __restrict__ Wo)
{
    int row = blockIdx.x;
    int tid = threadIdx.x;
    const float* src = Wo + (size_t)row*SS;
    __nv_bfloat16* dhi = g_Whi + (size_t)row*SS;
    __nv_bfloat16* dlo = g_Wlo + (size_t)row*SS;

    int base = tid * 8;
    float4 f0 = *(const float4*)(src + base);
    float4 f1 = *(const float4*)(src + base + 4);
    float v[8] = {f0.x, f0.y, f0.z, f0.w, f1.x, f1.y, f1.z, f1.w};
    unsigned hw[4], lw[4];
    #pragma unroll
    for (int p = 0; p < 4; p++) {
        __nv_bfloat16 ha, hb, la, lb;
        splitbf(v[2*p], ha, la);
        splitbf(v[2*p+1], hb, lb);
        __nv_bfloat162 hp = __halves2bfloat162(ha, hb);
        __nv_bfloat162 lp = __halves2bfloat162(la, lb);
        hw[p] = *(unsigned*)&hp;
        lw[p] = *(unsigned*)&lp;
    }
    *(uint4*)(dhi + base) = make_uint4(hw[0], hw[1], hw[2], hw[3]);
    *(uint4*)(dlo + base) = make_uint4(lw[0], lw[1], lw[2], lw[3]);
}

// ---------------------------------------------------------------------------
// Kernel 6: proj GEMM  out[b, m, n] = sum_s A[m,s]*W[n,s] + bo[n]  (3 segs)
// ---------------------------------------------------------------------------
#define PJ_STAGE 32768
#define PJ_SMEM  (2*PJ_STAGE)

__global__ __launch_bounds__(256) void proj_mma_kernel(
    const float* __restrict__ bo, float* __restrict__ out)
{
    extern __shared__ char psm[];
    uint32_t sb = smem_u32(psm);

    int tid = threadIdx.x, lane = tid & 31, wid = tid >> 5;
    int wm = wid & 3, wn = wid >> 2;
    int nt = blockIdx.x, mt = blockIdx.y, b = blockIdx.z;

    const __nv_bfloat16* Abase   = g_Ahi + ((size_t)b*DD + mt*128)*SS;
    const __nv_bfloat16* AbaseLo = g_Alo + ((size_t)b*DD + mt*128)*SS;
    const __nv_bfloat16* Wbase   = g_Whi + (size_t)(nt*128)*SS;
    const __nv_bfloat16* WbaseLo = g_Wlo + (size_t)(nt*128)*SS;

    int lrow = tid >> 3, lc16 = tid & 7;

    float acc[2][8][4];
    #pragma unroll
    for (int i = 0; i < 2; i++)
        #pragma unroll
        for (int j = 0; j < 8; j++)
            #pragma unroll
            for (int q = 0; q < 4; q++) acc[i][j][q] = 0.f;

    int rowa_l = wm*32 + (lane & 15);
    int ca_l   = (lane >> 4);
    int rowb_l = wn*64 + (lane & 7) + ((lane >> 4) << 3);
    int cb_l   = (lane >> 3) & 1;

    const int NC = 96;

    {
        uint32_t sa = sb, sbB = sb + 16384;
        #pragma unroll
        for (int rep = 0; rep < 4; rep++) {
            int row = lrow + rep*32;
            uint32_t off = (uint32_t)row*128 + 16u*(uint32_t)(lc16 ^ (row & 7));
            cpa16(sa  + off, Abase + (size_t)row*SS + lc16*8);
            cpa16(sbB + off, Wbase + (size_t)row*SS + lc16*8);
        }
        asm volatile("cp.async.commit_group;");
    }

    for (int c = 0; c < NC; c++) {
        int st = c & 1;
        if (c + 1 < NC) {
            int nc2 = c + 1;
            int seg = nc2 >> 5, kk = (nc2 & 31) * 64;
            const __nv_bfloat16* As = (seg == 1 ? AbaseLo : Abase);
            const __nv_bfloat16* Bs = (seg == 2 ? WbaseLo : Wbase);
            uint32_t sa = sb + (st^1)*PJ_STAGE, sbB = sa + 16384;
            #pragma unroll
            for (int rep = 0; rep < 4; rep++) {
                int row = lrow + rep*32;
                uint32_t off = (uint32_t)row*128 + 16u*(uint32_t)(lc16 ^ (row & 7));
                cpa16(sa  + off, As + (size_t)row*SS + kk + lc16*8);
                cpa16(sbB + off, Bs + (size_t)row*SS + kk + lc16*8);
            }
            asm volatile("cp.async.commit_group;");
            asm volatile("cp.async.wait_group 1;");
        } else {
            asm volatile("cp.async.wait_group 0;");
        }
        __syncthreads();

        uint32_t sa = sb + st*PJ_STAGE, sbB = sa + 16384;
        #pragma unroll
        for (int kstep = 0; kstep < 4; kstep++) {
            uint32_t afr[2][4];
            #pragma unroll
            for (int i = 0; i < 2; i++) {
                int row = rowa_l + i*16;
                int c16 = kstep*2 + ca_l;
                ldsm4(afr[i], sa + (uint32_t)row*128 + 16u*(uint32_t)(c16 ^ (row & 7)));
            }
            uint32_t bfr[4][4];
            #pragma unroll
            for (int j4 = 0; j4 < 4; j4++) {
                int row = rowb_l + j4*16;
                int c16 = kstep*2 + cb_l;
                ldsm4(bfr[j4], sbB + (uint32_t)row*128 + 16u*(uint32_t)(c16 ^ (row & 7)));
            }
            #pragma unroll
            for (int i = 0; i < 2; i++)
                #pragma unroll
                for (int j4 = 0; j4 < 4; j4++) {
                    mma16816(acc[i][2*j4+0], afr[i], bfr[j4][0], bfr[j4][1]);
                    mma16816(acc[i][2*j4+1], afr[i], bfr[j4][2], bfr[j4][3]);
                }
        }
        __syncthreads();
    }

    int r0w = lane >> 2, cc = (lane & 3) * 2;
    const float* bop = bo + nt*128 + wn*64;
    #pragma unroll
    for (int i = 0; i < 2; i++) {
        int m = mt*128 + wm*32 + i*16 + r0w;
        float* row0 = out + ((size_t)b*DD + m)*DD + nt*128 + wn*64;
        float* row1 = row0 + (size_t)8*DD;
        #pragma unroll
        for (int j = 0; j < 8; j++) {
            float2 bb = *(const float2*)(bop + j*8 + cc);
            float2 v0 = make_float2(acc[i][j][0] + bb.x, acc[i][j][1] + bb.y);
            float2 v1 = make_float2(acc[i][j][2] + bb.x, acc[i][j][3] + bb.y);
            *(float2*)(row0 + j*8 + cc) = v0;
            *(float2*)(row1 + j*8 + cc) = v1;
        }
    }
}

// ---------------------------------------------------------------------------
extern "C" void kernel_launch(void* const* d_in, const int* in_sizes, int n_in,
                              void* d_out, int out_size)
{
    const float* x  = (const float*)d_in[0];
    const float* Wq = (const float*)d_in[2];
    const float* Wk = (const float*)d_in[3];
    const float* Wv = (const float*)d_in[4];
    const float* bq = (const float*)d_in[5];
    const float* bk = (const float*)d_in[6];
    const float* bv = (const float*)d_in[7];
    const float* Wo = (const float*)d_in[8];
    const float* bo = (const float*)d_in[9];
    float* out = (float*)d_out;

    qkv_kernel<<<dim3(SS/64, BB*HH), 256>>>(x, Wq, Wk, Wv, bq, bk, bv);

    split_kernel<<<dim3(DD), 256>>>(Wo);

    cudaFuncSetAttribute(score_gemm_kernel, cudaFuncAttributeMaxDynamicSharedMemorySize, G3_SMEM);
    score_gemm_kernel<<<dim3(16, 16, BB*HH), 256, G3_SMEM>>>();

    select_kernel<<<dim3(SS/16, BB*HH), 512>>>();

    cudaFuncSetAttribute(av_gemm_kernel, cudaFuncAttributeMaxDynamicSharedMemorySize, G3_SMEM);
    av_gemm_kernel<<<dim3(16, BB*HH), 256, G3_SMEM>>>();

    cudaFuncSetAttribute(proj_mma_kernel, cudaFuncAttributeMaxDynamicSharedMemorySize, PJ_SMEM);
    proj_mma_kernel<<<dim3(16, 16, BB), 256, PJ_SMEM>>>(bo, out);
}

// round 12
// speedup vs baseline: 4.7096x; 1.2166x over previous
#include <cuda_runtime.h>
#include <cuda_bf16.h>
#include <cstdint>
#include <math.h>

#define BB 2
#define HH 16
#define SS 2048
#define HD 128
#define DD 2048
#define KKEEP 819
#define NEGV -1e9f
#define FULLW 0xffffffffu

// ---------------- scratch (device globals; no allocation allowed) ----------
__device__ __nv_bfloat16 g_qhi [BB*HH*SS*HD];  // [bh][s][d]
__device__ __nv_bfloat16 g_qlo [BB*HH*SS*HD];
__device__ __nv_bfloat16 g_khi [BB*HH*SS*HD];  // [bh][t][d]
__device__ __nv_bfloat16 g_klo [BB*HH*SS*HD];
__device__ __nv_bfloat16 g_vthi[BB*HH*HD*SS];  // [bh][d][t]
__device__ __nv_bfloat16 g_vtlo[BB*HH*HD*SS];

__device__ __nv_bfloat16 g_xhi[(size_t)BB*SS*DD];   // x split [b][s][D]
__device__ __nv_bfloat16 g_xlo[(size_t)BB*SS*DD];
__device__ __nv_bfloat16 g_wwhi[3*HH*HD*HD];        // Wq/Wk/Wv split [w][h][e][k]
__device__ __nv_bfloat16 g_wwlo[3*HH*HD*HD];

__device__ float         g_sc [(size_t)BB*HH*SS*SS];   // scores [bh][s][t]
__device__ __nv_bfloat16 g_wh [(size_t)BB*HH*SS*SS];   // UNNORMALIZED weights hi
__device__ __nv_bfloat16 g_wl [(size_t)BB*HH*SS*SS];   // UNNORMALIZED weights lo
__device__ float         g_rsv[(size_t)BB*HH*SS];      // per-row 1/sum

// proj operands (A written directly by av_gemm epilogue)
__device__ __nv_bfloat16 g_Ahi[(size_t)BB*DD*SS];      // [b][i][s]
__device__ __nv_bfloat16 g_Alo[(size_t)BB*DD*SS];
__device__ __nv_bfloat16 g_Whi[(size_t)DD*SS];
__device__ __nv_bfloat16 g_Wlo[(size_t)DD*SS];

// ---------------- common helpers -------------------------------------------
__device__ __forceinline__ uint32_t smem_u32(const void* p) {
    uint32_t a;
    asm("{ .reg .u64 t; cvta.to.shared.u64 t, %1; cvt.u32.u64 %0, t; }" : "=r"(a) : "l"(p));
    return a;
}
__device__ __forceinline__ void cpa16(uint32_t s, const void* g) {
    asm volatile("cp.async.cg.shared.global [%0], [%1], 16;" :: "r"(s), "l"(g));
}
__device__ __forceinline__ void ldsm4(uint32_t* r, uint32_t a) {
    asm volatile("ldmatrix.sync.aligned.m8n8.x4.shared.b16 {%0,%1,%2,%3}, [%4];"
                 : "=r"(r[0]), "=r"(r[1]), "=r"(r[2]), "=r"(r[3]) : "r"(a));
}
__device__ __forceinline__ void mma16816(float* c, const uint32_t* a, uint32_t b0, uint32_t b1) {
    asm volatile("mma.sync.aligned.m16n8k16.row.col.f32.bf16.bf16.f32 "
                 "{%0,%1,%2,%3}, {%4,%5,%6,%7}, {%8,%9}, {%0,%1,%2,%3};"
                 : "+f"(c[0]), "+f"(c[1]), "+f"(c[2]), "+f"(c[3])
                 : "r"(a[0]), "r"(a[1]), "r"(a[2]), "r"(a[3]), "r"(b0), "r"(b1));
}
__device__ __forceinline__ void splitbf(float a, __nv_bfloat16& h, __nv_bfloat16& l) {
    h = __float2bfloat16(a);
    l = __float2bfloat16(a - __bfloat162float(h));
}
__device__ __forceinline__ unsigned pack2(__nv_bfloat16 a, __nv_bfloat16 b) {
    return (unsigned)*(unsigned short*)&a | ((unsigned)*(unsigned short*)&b << 16);
}

// ---------------------------------------------------------------------------
// gemm3 core: 128x128 tile, K in 64-chunks, 3 terms (AhBh + AlBh + AhBl).
// ---------------------------------------------------------------------------
#define G3_STAGE 65536
#define G3_SMEM  (2*G3_STAGE)

__device__ __forceinline__ void gemm3_core(
    float (*acc)[8][4], uint32_t sb, int tid,
    const __nv_bfloat16* Ah, const __nv_bfloat16* Al, size_t strideA,
    const __nv_bfloat16* Bh, const __nv_bfloat16* Bl, size_t strideB,
    int NC)
{
    int lane = tid & 31, wid = tid >> 5;
    int wm = wid & 3, wn = wid >> 2;
    int lrow = tid >> 3, lc16 = tid & 7;

    int rowa_l = wm*32 + (lane & 15);
    int ca_l   = (lane >> 4);
    int rowb_l = wn*64 + (lane & 7) + ((lane >> 4) << 3);
    int cb_l   = (lane >> 3) & 1;

    {
        uint32_t sa = sb;
        #pragma unroll
        for (int rep = 0; rep < 4; rep++) {
            int row = lrow + rep*32;
            uint32_t off = (uint32_t)row*128 + 16u*(uint32_t)(lc16 ^ (row & 7));
            cpa16(sa +     0 + off, Ah + (size_t)row*strideA + lc16*8);
            cpa16(sa + 16384 + off, Al + (size_t)row*strideA + lc16*8);
            cpa16(sa + 32768 + off, Bh + (size_t)row*strideB + lc16*8);
            cpa16(sa + 49152 + off, Bl + (size_t)row*strideB + lc16*8);
        }
        asm volatile("cp.async.commit_group;");
    }

    for (int c = 0; c < NC; c++) {
        int st = c & 1;
        if (c + 1 < NC) {
            int kk = (c + 1) * 64;
            uint32_t sa = sb + (st^1)*G3_STAGE;
            #pragma unroll
            for (int rep = 0; rep < 4; rep++) {
                int row = lrow + rep*32;
                uint32_t off = (uint32_t)row*128 + 16u*(uint32_t)(lc16 ^ (row & 7));
                cpa16(sa +     0 + off, Ah + (size_t)row*strideA + kk + lc16*8);
                cpa16(sa + 16384 + off, Al + (size_t)row*strideA + kk + lc16*8);
                cpa16(sa + 32768 + off, Bh + (size_t)row*strideB + kk + lc16*8);
                cpa16(sa + 49152 + off, Bl + (size_t)row*strideB + kk + lc16*8);
            }
            asm volatile("cp.async.commit_group;");
            asm volatile("cp.async.wait_group 1;");
        } else {
            asm volatile("cp.async.wait_group 0;");
        }
        __syncthreads();

        uint32_t sa = sb + st*G3_STAGE;
        #pragma unroll
        for (int kstep = 0; kstep < 4; kstep++) {
            uint32_t ah[2][4], al[2][4];
            #pragma unroll
            for (int i = 0; i < 2; i++) {
                int row = rowa_l + i*16;
                int c16 = kstep*2 + ca_l;
                uint32_t off = (uint32_t)row*128 + 16u*(uint32_t)(c16 ^ (row & 7));
                ldsm4(ah[i], sa + off);
                ldsm4(al[i], sa + 16384 + off);
            }
            #pragma unroll
            for (int j4 = 0; j4 < 4; j4++) {
                int row = rowb_l + j4*16;
                int c16 = kstep*2 + cb_l;
                uint32_t off = (uint32_t)row*128 + 16u*(uint32_t)(c16 ^ (row & 7));
                uint32_t bhf[4], blf[4];
                ldsm4(bhf, sa + 32768 + off);
                ldsm4(blf, sa + 49152 + off);
                #pragma unroll
                for (int i = 0; i < 2; i++) {
                    mma16816(acc[i][2*j4+0], ah[i], bhf[0], bhf[1]);
                    mma16816(acc[i][2*j4+1], ah[i], bhf[2], bhf[3]);
                    mma16816(acc[i][2*j4+0], al[i], bhf[0], bhf[1]);
                    mma16816(acc[i][2*j4+1], al[i], bhf[2], bhf[3]);
                    mma16816(acc[i][2*j4+0], ah[i], blf[0], blf[1]);
                    mma16816(acc[i][2*j4+1], ah[i], blf[2], blf[3]);
                }
            }
        }
        __syncthreads();
    }
}

// ---------------------------------------------------------------------------
// Kernel 1a: fp32 -> bf16 hi/lo split for Wo + x (rows of 2048)
// ---------------------------------------------------------------------------
__global__ __launch_bounds__(256) void split_kernel(
    const float* __restrict__ Wo, const float* __restrict__ x)
{
    int row = blockIdx.x;
    int tid = threadIdx.x;
    const float* src;
    __nv_bfloat16 *dhi, *dlo;
    if (row < DD) {
        src = Wo + (size_t)row*SS;
        dhi = g_Whi + (size_t)row*SS; dlo = g_Wlo + (size_t)row*SS;
    } else {
        int r = row - DD;
        src = x + (size_t)r*DD;
        dhi = g_xhi + (size_t)r*DD; dlo = g_xlo + (size_t)r*DD;
    }

    int base = tid * 8;
    float4 f0 = *(const float4*)(src + base);
    float4 f1 = *(const float4*)(src + base + 4);
    float v[8] = {f0.x, f0.y, f0.z, f0.w, f1.x, f1.y, f1.z, f1.w};
    unsigned hw[4], lw[4];
    #pragma unroll
    for (int p = 0; p < 4; p++) {
        __nv_bfloat16 ha, hb, la, lb;
        splitbf(v[2*p], ha, la);
        splitbf(v[2*p+1], hb, lb);
        hw[p] = pack2(ha, hb);
        lw[p] = pack2(la, lb);
    }
    *(uint4*)(dhi + base) = make_uint4(hw[0], hw[1], hw[2], hw[3]);
    *(uint4*)(dlo + base) = make_uint4(lw[0], lw[1], lw[2], lw[3]);
}

// ---------------------------------------------------------------------------
// Kernel 1b: fp32 -> bf16 hi/lo split for Wq/Wk/Wv (flat, 4 elems/thread)
// ---------------------------------------------------------------------------
__global__ __launch_bounds__(256) void splitw_kernel(
    const float* __restrict__ Wq, const float* __restrict__ Wk,
    const float* __restrict__ Wv)
{
    int base = (blockIdx.x*256 + threadIdx.x) * 4;   // total 3*16*128*128
    int wsel = base >> 18;                            // / 262144
    int off  = base & 262143;
    const float* src = (wsel == 0 ? Wq : wsel == 1 ? Wk : Wv) + off;
    float4 f = *(const float4*)src;
    __nv_bfloat16 h0,l0,h1,l1,h2,l2,h3,l3;
    splitbf(f.x,h0,l0); splitbf(f.y,h1,l1); splitbf(f.z,h2,l2); splitbf(f.w,h3,l3);
    *(uint2*)(g_wwhi + base) = make_uint2(pack2(h0,h1), pack2(h2,h3));
    *(uint2*)(g_wwlo + base) = make_uint2(pack2(l0,l1), pack2(l2,l3));
}

// ---------------------------------------------------------------------------
// Kernel 2: QKV projections via HMMA. grid (mt 32, h 16, w 3)
// ---------------------------------------------------------------------------
__global__ __launch_bounds__(256) void qkv_mma_kernel(
    const float* __restrict__ bq, const float* __restrict__ bk,
    const float* __restrict__ bv)
{
    int mt = blockIdx.x, h = blockIdx.y, w = blockIdx.z;
    extern __shared__ char sm3[];
    uint32_t sb = smem_u32(sm3);
    int tid = threadIdx.x, lane = tid & 31, wid = tid >> 5;
    int wm = wid & 3, wn = wid >> 2;

    float acc[2][8][4];
    #pragma unroll
    for (int i = 0; i < 2; i++)
        #pragma unroll
        for (int j = 0; j < 8; j++)
            #pragma unroll
            for (int q = 0; q < 4; q++) acc[i][j][q] = 0.f;

    size_t aoff = (size_t)(mt*128)*DD + h*HD;
    size_t boff = (size_t)((w*HH + h)*HD)*HD;
    gemm3_core(acc, sb, tid, g_xhi + aoff, g_xlo + aoff, DD,
               g_wwhi + boff, g_wwlo + boff, HD, 2);

    const float* bias = (w == 0 ? bq : w == 1 ? bk : bv) + h*HD;
    int b = mt >> 4;
    int bh = b*HH + h;
    int sbase = (mt*128) & (SS - 1);
    int r0w = lane >> 2, cc = (lane & 3)*2;

    if (w < 2) {
        __nv_bfloat16* dh = (w == 0 ? g_qhi : g_khi);
        __nv_bfloat16* dl = (w == 0 ? g_qlo : g_klo);
        #pragma unroll
        for (int i = 0; i < 2; i++) {
            int m0 = wm*32 + i*16 + r0w;
            size_t row0 = ((size_t)bh*SS + sbase + m0)*HD;
            size_t row1 = row0 + (size_t)8*HD;
            #pragma unroll
            for (int j = 0; j < 8; j++) {
                int d0 = wn*64 + j*8 + cc;
                float b0 = bias[d0], b1 = bias[d0+1];
                __nv_bfloat16 ha,la,hb,lb;
                splitbf(acc[i][j][0] + b0, ha, la);
                splitbf(acc[i][j][1] + b1, hb, lb);
                *(unsigned*)(dh + row0 + d0) = pack2(ha, hb);
                *(unsigned*)(dl + row0 + d0) = pack2(la, lb);
                splitbf(acc[i][j][2] + b0, ha, la);
                splitbf(acc[i][j][3] + b1, hb, lb);
                *(unsigned*)(dh + row1 + d0) = pack2(ha, hb);
                *(unsigned*)(dl + row1 + d0) = pack2(la, lb);
            }
        }
    } else {
        // V: transpose via smem staging (smem free after gemm3_core)
        __nv_bfloat16* th = (__nv_bfloat16*)sm3;          // [d][m] 128x128
        __nv_bfloat16* tl = th + 128*128;
        #pragma unroll
        for (int i = 0; i < 2; i++) {
            int m0 = wm*32 + i*16 + r0w;
            #pragma unroll
            for (int j = 0; j < 8; j++) {
                int d0 = wn*64 + j*8 + cc;
                float b0 = bias[d0], b1 = bias[d0+1];
                __nv_bfloat16 hh, ll;
                splitbf(acc[i][j][0] + b0, hh, ll);
                th[d0*128 + m0] = hh;         tl[d0*128 + m0] = ll;
                splitbf(acc[i][j][1] + b1, hh, ll);
                th[(d0+1)*128 + m0] = hh;     tl[(d0+1)*128 + m0] = ll;
                splitbf(acc[i][j][2] + b0, hh, ll);
                th[d0*128 + m0 + 8] = hh;     tl[d0*128 + m0 + 8] = ll;
                splitbf(acc[i][j][3] + b1, hh, ll);
                th[(d0+1)*128 + m0 + 8] = hh; tl[(d0+1)*128 + m0 + 8] = ll;
            }
        }
        __syncthreads();
        int d = tid >> 1, half = tid & 1;
        size_t go = ((size_t)bh*HD + d)*SS + sbase + half*64;
        const uint4* s4h = (const uint4*)(th + d*128 + half*64);
        const uint4* s4l = (const uint4*)(tl + d*128 + half*64);
        #pragma unroll
        for (int p = 0; p < 8; p++) {
            *(uint4*)(g_vthi + go + p*8) = s4h[p];
            *(uint4*)(g_vtlo + go + p*8) = s4l[p];
        }
    }
}

// ---------------------------------------------------------------------------
// Kernel 3: score GEMM  g_sc[bh][i][j] = scale * Q[i,:]·K[j,:] (causal mask)
// ---------------------------------------------------------------------------
__global__ __launch_bounds__(256) void score_gemm_kernel()
{
    int jt = blockIdx.x, it = blockIdx.y, bh = blockIdx.z;
    if (jt > it) return;

    extern __shared__ char sm3[];
    uint32_t sb = smem_u32(sm3);
    int tid = threadIdx.x, lane = tid & 31, wid = tid >> 5;
    int wm = wid & 3, wn = wid >> 2;

    float acc[2][8][4];
    #pragma unroll
    for (int i = 0; i < 2; i++)
        #pragma unroll
        for (int j = 0; j < 8; j++)
            #pragma unroll
            for (int q = 0; q < 4; q++) acc[i][j][q] = 0.f;

    size_t aoff = ((size_t)bh*SS + it*128)*HD;
    size_t boff = ((size_t)bh*SS + jt*128)*HD;
    gemm3_core(acc, sb, tid, g_qhi + aoff, g_qlo + aoff, HD,
               g_khi + boff, g_klo + boff, HD, 2);

    const float scale = 0.08838834764831845f;
    int r0w = lane >> 2, cc = (lane & 3) * 2;
    #pragma unroll
    for (int i = 0; i < 2; i++) {
        int m0 = it*128 + wm*32 + i*16 + r0w;
        int m1 = m0 + 8;
        float* row0 = g_sc + ((size_t)bh*SS + m0)*SS + jt*128 + wn*64;
        float* row1 = row0 + (size_t)8*SS;
        #pragma unroll
        for (int j = 0; j < 8; j++) {
            int j0 = jt*128 + wn*64 + j*8 + cc;
            float2 v0, v1;
            v0.x = (j0     <= m0) ? acc[i][j][0]*scale : NEGV;
            v0.y = (j0 + 1 <= m0) ? acc[i][j][1]*scale : NEGV;
            v1.x = (j0     <= m1) ? acc[i][j][2]*scale : NEGV;
            v1.y = (j0 + 1 <= m1) ? acc[i][j][3]*scale : NEGV;
            *(float2*)(row0 + j*8 + cc) = v0;
            *(float2*)(row1 + j*8 + cc) = v1;
        }
    }
}

// ---------------------------------------------------------------------------
// Kernel 4: exact top-k select + fused exp/sum -> UNNORMALIZED bf16 weights.
// Warp-per-row, gmem-direct, converged sweeps, cheap-row skip, rsv deferred.
// ---------------------------------------------------------------------------
__device__ __forceinline__ unsigned f2key(float f) {
    unsigned u = __float_as_uint(f);
    return u ^ ((u & 0x80000000u) ? 0xFFFFFFFFu : 0x80000000u);
}
__device__ __forceinline__ float key2f(unsigned k) {
    unsigned u = (k & 0x80000000u) ? (k ^ 0x80000000u) : ~k;
    return __uint_as_float(u);
}

__global__ __launch_bounds__(512) void select_kernel()
{
    __shared__ int hist[16*256];   // per-warp histograms, 16KB

    int bh   = blockIdx.y;
    int s0   = (gridDim.x - 1 - blockIdx.x) * 16;   // longest rows first
    int tid  = threadIdx.x;
    int lane = tid & 31, wid = tid >> 5;
    int s    = s0 + wid;
    int nvalid = s + 1;
    int nround = (nvalid + 31) & ~31;               // keeps warp converged

    const float* row = g_sc + ((size_t)bh*SS + s)*SS;
    int* hh = hist + wid*256;

    float lm  = -3.4e38f;
    float thr = -3.4e38f;

    if (s >= KKEEP - 1) {
        unsigned prefix = 0; int K = KKEEP;
        #pragma unroll
        for (int pass = 0; pass < 4; pass++) {
            int shift = 24 - pass*8;
            #pragma unroll
            for (int i = lane; i < 256; i += 32) hh[i] = 0;
            __syncwarp();
            for (int t = lane; t < nround; t += 32) {
                bool valid = (t < nvalid);
                float v = valid ? row[t] : NEGV;
                if (pass == 0 && valid) lm = fmaxf(lm, v);
                unsigned key = f2key(v);
                bool cand = valid &&
                    ((pass == 0) || (((key ^ prefix) >> (shift + 8)) == 0u));
                int bin = cand ? (int)((key >> shift) & 255u) : -1;
                unsigned peers = __match_any_sync(FULLW, bin);
                if (cand && lane == (__ffs(peers) - 1))
                    atomicAdd(&hh[bin], __popc(peers));
            }
            __syncwarp();
            int hv[8]; int ssum = 0;
            #pragma unroll
            for (int i = 0; i < 8; i++) { hv[i] = hh[lane*8 + i]; ssum += hv[i]; }
            int suf = ssum;
            #pragma unroll
            for (int off = 1; off < 32; off <<= 1) {
                int v = __shfl_down_sync(FULLW, suf, off);
                if (lane + off < 32) suf += v;
            }
            int above = suf - ssum;
            int selbin = -1, newK = 0;
            if (suf >= K && above < K) {
                int run = above;
                #pragma unroll
                for (int bb2 = 7; bb2 >= 0; bb2--) {
                    run += hv[bb2];
                    if (run >= K) { selbin = lane*8 + bb2; newK = K - (run - hv[bb2]); break; }
                }
            }
            unsigned msk = __ballot_sync(FULLW, selbin >= 0);
            int src = __ffs(msk) - 1;
            selbin = __shfl_sync(FULLW, selbin, src);
            newK   = __shfl_sync(FULLW, newK,  src);
            prefix |= ((unsigned)selbin) << shift;
            K = newK;
        }
        thr = key2f(prefix);
    } else {
        for (int t = lane; t < nvalid; t += 32) lm = fmaxf(lm, row[t]);
    }

    #pragma unroll
    for (int off = 16; off > 0; off >>= 1)
        lm = fmaxf(lm, __shfl_xor_sync(FULLW, lm, off));

    // fused: write UNNORMALIZED weights + accumulate sum (zero-pad to 128 tile)
    int CEIL = (s0 & ~127) + 128;
    size_t go = ((size_t)bh*SS + s)*SS;
    float ls = 0.f;
    for (int t4 = lane*4; t4 < CEIL; t4 += 128) {
        float w0 = 0.f, w1 = 0.f, w2 = 0.f, w3 = 0.f;
        if (t4 + 3 < nvalid) {
            float4 v4 = *(const float4*)(row + t4);
            if (v4.x >= thr) w0 = __expf(v4.x - lm);
            if (v4.y >= thr) w1 = __expf(v4.y - lm);
            if (v4.z >= thr) w2 = __expf(v4.z - lm);
            if (v4.w >= thr) w3 = __expf(v4.w - lm);
        } else if (t4 < nvalid) {
            float vv;
            vv = row[t4];
            if (vv >= thr) w0 = __expf(vv - lm);
            if (t4 + 1 < nvalid) { vv = row[t4+1]; if (vv >= thr) w1 = __expf(vv - lm); }
            if (t4 + 2 < nvalid) { vv = row[t4+2]; if (vv >= thr) w2 = __expf(vv - lm); }
        }
        ls += (w0 + w1) + (w2 + w3);
        __nv_bfloat16 h0,l0,h1,l1,h2,l2,h3,l3;
        splitbf(w0,h0,l0); splitbf(w1,h1,l1);
        splitbf(w2,h2,l2); splitbf(w3,h3,l3);
        *(uint2*)(g_wh + go + t4) = make_uint2(pack2(h0,h1), pack2(h2,h3));
        *(uint2*)(g_wl + go + t4) = make_uint2(pack2(l0,l1), pack2(l2,l3));
    }
    #pragma unroll
    for (int off = 16; off > 0; off >>= 1)
        ls += __shfl_xor_sync(FULLW, ls, off);
    if (lane == 0) g_rsv[(size_t)bh*SS + s] = 1.f / ls;
}

// ---------------------------------------------------------------------------
// Kernel 5: AV GEMM (transposed): outT[d, s] = rsv[s] * sum_t V^T[d,t]*W[s,t]
// ---------------------------------------------------------------------------
__global__ __launch_bounds__(256) void av_gemm_kernel()
{
    int st = gridDim.x - 1 - blockIdx.x;   // longest first
    int bh = blockIdx.y;

    extern __shared__ char sm3[];
    uint32_t sb = smem_u32(sm3);
    int tid = threadIdx.x, lane = tid & 31, wid = tid >> 5;
    int wm = wid & 3, wn = wid >> 2;

    float acc[2][8][4];
    #pragma unroll
    for (int i = 0; i < 2; i++)
        #pragma unroll
        for (int j = 0; j < 8; j++)
            #pragma unroll
            for (int q = 0; q < 4; q++) acc[i][j][q] = 0.f;

    size_t aoff = (size_t)bh*HD*SS;
    size_t boff = ((size_t)bh*SS + st*128)*SS;
    gemm3_core(acc, sb, tid, g_vthi + aoff, g_vtlo + aoff, SS,
               g_wh + boff, g_wl + boff, SS, 2*(st + 1));

    int b = bh >> 4, h = bh & 15;
    int r0w = lane >> 2, cc = (lane & 3) * 2;
    const float* rsvp = g_rsv + (size_t)bh*SS;
    #pragma unroll
    for (int i = 0; i < 2; i++) {
        int d0 = wm*32 + i*16 + r0w;
        size_t rowA = ((size_t)b*DD + h*HD + d0)*SS;
        size_t rowB = rowA + (size_t)8*SS;
        #pragma unroll
        for (int j = 0; j < 8; j++) {
            int s_col = st*128 + wn*64 + j*8 + cc;
            float r0 = rsvp[s_col], r1 = rsvp[s_col + 1];
            __nv_bfloat16 h0,l0,h1,l1;
            splitbf(acc[i][j][0]*r0, h0, l0);
            splitbf(acc[i][j][1]*r1, h1, l1);
            *(unsigned*)(g_Ahi + rowA + s_col) = pack2(h0, h1);
            *(unsigned*)(g_Alo + rowA + s_col) = pack2(l0, l1);
            splitbf(acc[i][j][2]*r0, h0, l0);
            splitbf(acc[i][j][3]*r1, h1, l1);
            *(unsigned*)(g_Ahi + rowB + s_col) = pack2(h0, h1);
            *(unsigned*)(g_Alo + rowB + s_col) = pack2(l0, l1);
        }
    }
}

// ---------------------------------------------------------------------------
// Kernel 6: proj GEMM  out[b, m, n] = sum_s A[m,s]*W[n,s] + bo[n]  (3 segs)
// ---------------------------------------------------------------------------
#define PJ_STAGE 32768
#define PJ_SMEM  (2*PJ_STAGE)

__global__ __launch_bounds__(256) void proj_mma_kernel(
    const float* __restrict__ bo, float* __restrict__ out)
{
    extern __shared__ char psm[];
    uint32_t sb = smem_u32(psm);

    int tid = threadIdx.x, lane = tid & 31, wid = tid >> 5;
    int wm = wid & 3, wn = wid >> 2;
    int nt = blockIdx.x, mt = blockIdx.y, b = blockIdx.z;

    const __nv_bfloat16* Abase   = g_Ahi + ((size_t)b*DD + mt*128)*SS;
    const __nv_bfloat16* AbaseLo = g_Alo + ((size_t)b*DD + mt*128)*SS;
    const __nv_bfloat16* Wbase   = g_Whi + (size_t)(nt*128)*SS;
    const __nv_bfloat16* WbaseLo = g_Wlo + (size_t)(nt*128)*SS;

    int lrow = tid >> 3, lc16 = tid & 7;

    float acc[2][8][4];
    #pragma unroll
    for (int i = 0; i < 2; i++)
        #pragma unroll
        for (int j = 0; j < 8; j++)
            #pragma unroll
            for (int q = 0; q < 4; q++) acc[i][j][q] = 0.f;

    int rowa_l = wm*32 + (lane & 15);
    int ca_l   = (lane >> 4);
    int rowb_l = wn*64 + (lane & 7) + ((lane >> 4) << 3);
    int cb_l   = (lane >> 3) & 1;

    const int NC = 96;

    {
        uint32_t sa = sb, sbB = sb + 16384;
        #pragma unroll
        for (int rep = 0; rep < 4; rep++) {
            int row = lrow + rep*32;
            uint32_t off = (uint32_t)row*128 + 16u*(uint32_t)(lc16 ^ (row & 7));
            cpa16(sa  + off, Abase + (size_t)row*SS + lc16*8);
            cpa16(sbB + off, Wbase + (size_t)row*SS + lc16*8);
        }
        asm volatile("cp.async.commit_group;");
    }

    for (int c = 0; c < NC; c++) {
        int st = c & 1;
        if (c + 1 < NC) {
            int nc2 = c + 1;
            int seg = nc2 >> 5, kk = (nc2 & 31) * 64;
            const __nv_bfloat16* As = (seg == 1 ? AbaseLo : Abase);
            const __nv_bfloat16* Bs = (seg == 2 ? WbaseLo : Wbase);
            uint32_t sa = sb + (st^1)*PJ_STAGE, sbB = sa + 16384;
            #pragma unroll
            for (int rep = 0; rep < 4; rep++) {
                int row = lrow + rep*32;
                uint32_t off = (uint32_t)row*128 + 16u*(uint32_t)(lc16 ^ (row & 7));
                cpa16(sa  + off, As + (size_t)row*SS + kk + lc16*8);
                cpa16(sbB + off, Bs + (size_t)row*SS + kk + lc16*8);
            }
            asm volatile("cp.async.commit_group;");
            asm volatile("cp.async.wait_group 1;");
        } else {
            asm volatile("cp.async.wait_group 0;");
        }
        __syncthreads();

        uint32_t sa = sb + st*PJ_STAGE, sbB = sa + 16384;
        #pragma unroll
        for (int kstep = 0; kstep < 4; kstep++) {
            uint32_t afr[2][4];
            #pragma unroll
            for (int i = 0; i < 2; i++) {
                int row = rowa_l + i*16;
                int c16 = kstep*2 + ca_l;
                ldsm4(afr[i], sa + (uint32_t)row*128 + 16u*(uint32_t)(c16 ^ (row & 7)));
            }
            uint32_t bfr[4][4];
            #pragma unroll
            for (int j4 = 0; j4 < 4; j4++) {
                int row = rowb_l + j4*16;
                int c16 = kstep*2 + cb_l;
                ldsm4(bfr[j4], sbB + (uint32_t)row*128 + 16u*(uint32_t)(c16 ^ (row & 7)));
            }
            #pragma unroll
            for (int i = 0; i < 2; i++)
                #pragma unroll
                for (int j4 = 0; j4 < 4; j4++) {
                    mma16816(acc[i][2*j4+0], afr[i], bfr[j4][0], bfr[j4][1]);
                    mma16816(acc[i][2*j4+1], afr[i], bfr[j4][2], bfr[j4][3]);
                }
        }
        __syncthreads();
    }

    int r0w = lane >> 2, cc = (lane & 3) * 2;
    const float* bop = bo + nt*128 + wn*64;
    #pragma unroll
    for (int i = 0; i < 2; i++) {
        int m = mt*128 + wm*32 + i*16 + r0w;
        float* row0 = out + ((size_t)b*DD + m)*DD + nt*128 + wn*64;
        float* row1 = row0 + (size_t)8*DD;
        #pragma unroll
        for (int j = 0; j < 8; j++) {
            float2 bb = *(const float2*)(bop + j*8 + cc);
            float2 v0 = make_float2(acc[i][j][0] + bb.x, acc[i][j][1] + bb.y);
            float2 v1 = make_float2(acc[i][j][2] + bb.x, acc[i][j][3] + bb.y);
            *(float2*)(row0 + j*8 + cc) = v0;
            *(float2*)(row1 + j*8 + cc) = v1;
        }
    }
}

// ---------------------------------------------------------------------------
extern "C" void kernel_launch(void* const* d_in, const int* in_sizes, int n_in,
                              void* d_out, int out_size)
{
    const float* x  = (const float*)d_in[0];
    const float* Wq = (const float*)d_in[2];
    const float* Wk = (const float*)d_in[3];
    const float* Wv = (const float*)d_in[4];
    const float* bq = (const float*)d_in[5];
    const float* bk = (const float*)d_in[6];
    const float* bv = (const float*)d_in[7];
    const float* Wo = (const float*)d_in[8];
    const float* bo = (const float*)d_in[9];
    float* out = (float*)d_out;

    split_kernel<<<dim3(DD + BB*SS), 256>>>(Wo, x);
    splitw_kernel<<<dim3(768), 256>>>(Wq, Wk, Wv);

    cudaFuncSetAttribute(qkv_mma_kernel, cudaFuncAttributeMaxDynamicSharedMemorySize, G3_SMEM);
    qkv_mma_kernel<<<dim3(32, HH, 3), 256, G3_SMEM>>>(bq, bk, bv);

    cudaFuncSetAttribute(score_gemm_kernel, cudaFuncAttributeMaxDynamicSharedMemorySize, G3_SMEM);
    score_gemm_kernel<<<dim3(16, 16, BB*HH), 256, G3_SMEM>>>();

    select_kernel<<<dim3(SS/16, BB*HH), 512>>>();

    cudaFuncSetAttribute(av_gemm_kernel, cudaFuncAttributeMaxDynamicSharedMemorySize, G3_SMEM);
    av_gemm_kernel<<<dim3(16, BB*HH), 256, G3_SMEM>>>();

    cudaFuncSetAttribute(proj_mma_kernel, cudaFuncAttributeMaxDynamicSharedMemorySize, PJ_SMEM);
    proj_mma_kernel<<<dim3(16, 16, BB), 256, PJ_SMEM>>>(bo, out);
}

// round 13
// speedup vs baseline: 5.0356x; 1.0692x over previous
#include <cuda_runtime.h>
#include <cuda_bf16.h>
#include <cstdint>
#include <math.h>

#define BB 2
#define HH 16
#define SS 2048
#define HD 128
#define DD 2048
#define KKEEP 819
#define NEGV -1e9f
#define FULLW 0xffffffffu

// ---------------- scratch (device globals; no allocation allowed) ----------
__device__ __nv_bfloat16 g_qhi [BB*HH*SS*HD];  // [bh][s][d]
__device__ __nv_bfloat16 g_qlo [BB*HH*SS*HD];
__device__ __nv_bfloat16 g_khi [BB*HH*SS*HD];  // [bh][t][d]
__device__ __nv_bfloat16 g_klo [BB*HH*SS*HD];
__device__ __nv_bfloat16 g_vthi[BB*HH*HD*SS];  // [bh][d][t]
__device__ __nv_bfloat16 g_vtlo[BB*HH*HD*SS];

__device__ __nv_bfloat16 g_xhi[(size_t)BB*SS*DD];   // x split [b][s][D]
__device__ __nv_bfloat16 g_xlo[(size_t)BB*SS*DD];
__device__ __nv_bfloat16 g_wwhi[3*HH*HD*HD];        // Wq/Wk/Wv split [w][h][e][k]
__device__ __nv_bfloat16 g_wwlo[3*HH*HD*HD];

__device__ float         g_sc [(size_t)BB*HH*SS*SS];   // scores [bh][s][t]
__device__ __nv_bfloat16 g_wh [(size_t)BB*HH*SS*SS];   // UNNORMALIZED weights hi
__device__ __nv_bfloat16 g_wl [(size_t)BB*HH*SS*SS];   // UNNORMALIZED weights lo
__device__ float         g_rsv[(size_t)BB*HH*SS];      // per-row 1/sum

// proj operands (A written directly by av_gemm epilogue)
__device__ __nv_bfloat16 g_Ahi[(size_t)BB*DD*SS];      // [b][i][s]
__device__ __nv_bfloat16 g_Alo[(size_t)BB*DD*SS];
__device__ __nv_bfloat16 g_Whi[(size_t)DD*SS];
__device__ __nv_bfloat16 g_Wlo[(size_t)DD*SS];

// ---------------- common helpers -------------------------------------------
__device__ __forceinline__ uint32_t smem_u32(const void* p) {
    uint32_t a;
    asm("{ .reg .u64 t; cvta.to.shared.u64 t, %1; cvt.u32.u64 %0, t; }" : "=r"(a) : "l"(p));
    return a;
}
__device__ __forceinline__ void cpa16(uint32_t s, const void* g) {
    asm volatile("cp.async.cg.shared.global [%0], [%1], 16;" :: "r"(s), "l"(g));
}
__device__ __forceinline__ void ldsm4(uint32_t* r, uint32_t a) {
    asm volatile("ldmatrix.sync.aligned.m8n8.x4.shared.b16 {%0,%1,%2,%3}, [%4];"
                 : "=r"(r[0]), "=r"(r[1]), "=r"(r[2]), "=r"(r[3]) : "r"(a));
}
__device__ __forceinline__ void mma16816(float* c, const uint32_t* a, uint32_t b0, uint32_t b1) {
    asm volatile("mma.sync.aligned.m16n8k16.row.col.f32.bf16.bf16.f32 "
                 "{%0,%1,%2,%3}, {%4,%5,%6,%7}, {%8,%9}, {%0,%1,%2,%3};"
                 : "+f"(c[0]), "+f"(c[1]), "+f"(c[2]), "+f"(c[3])
                 : "r"(a[0]), "r"(a[1]), "r"(a[2]), "r"(a[3]), "r"(b0), "r"(b1));
}
__device__ __forceinline__ void splitbf(float a, __nv_bfloat16& h, __nv_bfloat16& l) {
    h = __float2bfloat16(a);
    l = __float2bfloat16(a - __bfloat162float(h));
}
__device__ __forceinline__ unsigned pack2(__nv_bfloat16 a, __nv_bfloat16 b) {
    return (unsigned)*(unsigned short*)&a | ((unsigned)*(unsigned short*)&b << 16);
}

// ---------------------------------------------------------------------------
// gemm3 core: 128x128 tile, K in 64-chunks, 3 terms (AhBh + AlBh + AhBl).
// ---------------------------------------------------------------------------
#define G3_STAGE 65536
#define G3_SMEM  (2*G3_STAGE)

__device__ __forceinline__ void gemm3_core(
    float (*acc)[8][4], uint32_t sb, int tid,
    const __nv_bfloat16* Ah, const __nv_bfloat16* Al, size_t strideA,
    const __nv_bfloat16* Bh, const __nv_bfloat16* Bl, size_t strideB,
    int NC)
{
    int lane = tid & 31, wid = tid >> 5;
    int wm = wid & 3, wn = wid >> 2;
    int lrow = tid >> 3, lc16 = tid & 7;

    int rowa_l = wm*32 + (lane & 15);
    int ca_l   = (lane >> 4);
    int rowb_l = wn*64 + (lane & 7) + ((lane >> 4) << 3);
    int cb_l   = (lane >> 3) & 1;

    {
        uint32_t sa = sb;
        #pragma unroll
        for (int rep = 0; rep < 4; rep++) {
            int row = lrow + rep*32;
            uint32_t off = (uint32_t)row*128 + 16u*(uint32_t)(lc16 ^ (row & 7));
            cpa16(sa +     0 + off, Ah + (size_t)row*strideA + lc16*8);
            cpa16(sa + 16384 + off, Al + (size_t)row*strideA + lc16*8);
            cpa16(sa + 32768 + off, Bh + (size_t)row*strideB + lc16*8);
            cpa16(sa + 49152 + off, Bl + (size_t)row*strideB + lc16*8);
        }
        asm volatile("cp.async.commit_group;");
    }

    for (int c = 0; c < NC; c++) {
        int st = c & 1;
        if (c + 1 < NC) {
            int kk = (c + 1) * 64;
            uint32_t sa = sb + (st^1)*G3_STAGE;
            #pragma unroll
            for (int rep = 0; rep < 4; rep++) {
                int row = lrow + rep*32;
                uint32_t off = (uint32_t)row*128 + 16u*(uint32_t)(lc16 ^ (row & 7));
                cpa16(sa +     0 + off, Ah + (size_t)row*strideA + kk + lc16*8);
                cpa16(sa + 16384 + off, Al + (size_t)row*strideA + kk + lc16*8);
                cpa16(sa + 32768 + off, Bh + (size_t)row*strideB + kk + lc16*8);
                cpa16(sa + 49152 + off, Bl + (size_t)row*strideB + kk + lc16*8);
            }
            asm volatile("cp.async.commit_group;");
            asm volatile("cp.async.wait_group 1;");
        } else {
            asm volatile("cp.async.wait_group 0;");
        }
        __syncthreads();

        uint32_t sa = sb + st*G3_STAGE;
        #pragma unroll
        for (int kstep = 0; kstep < 4; kstep++) {
            uint32_t ah[2][4], al[2][4];
            #pragma unroll
            for (int i = 0; i < 2; i++) {
                int row = rowa_l + i*16;
                int c16 = kstep*2 + ca_l;
                uint32_t off = (uint32_t)row*128 + 16u*(uint32_t)(c16 ^ (row & 7));
                ldsm4(ah[i], sa + off);
                ldsm4(al[i], sa + 16384 + off);
            }
            #pragma unroll
            for (int j4 = 0; j4 < 4; j4++) {
                int row = rowb_l + j4*16;
                int c16 = kstep*2 + cb_l;
                uint32_t off = (uint32_t)row*128 + 16u*(uint32_t)(c16 ^ (row & 7));
                uint32_t bhf[4], blf[4];
                ldsm4(bhf, sa + 32768 + off);
                ldsm4(blf, sa + 49152 + off);
                #pragma unroll
                for (int i = 0; i < 2; i++) {
                    mma16816(acc[i][2*j4+0], ah[i], bhf[0], bhf[1]);
                    mma16816(acc[i][2*j4+1], ah[i], bhf[2], bhf[3]);
                    mma16816(acc[i][2*j4+0], al[i], bhf[0], bhf[1]);
                    mma16816(acc[i][2*j4+1], al[i], bhf[2], bhf[3]);
                    mma16816(acc[i][2*j4+0], ah[i], blf[0], blf[1]);
                    mma16816(acc[i][2*j4+1], ah[i], blf[2], blf[3]);
                }
            }
        }
        __syncthreads();
    }
}

// ---------------------------------------------------------------------------
// Kernel 1a: fp32 -> bf16 hi/lo split for Wo + x (rows of 2048)
// ---------------------------------------------------------------------------
__global__ __launch_bounds__(256) void split_kernel(
    const float* __restrict__ Wo, const float* __restrict__ x)
{
    int row = blockIdx.x;
    int tid = threadIdx.x;
    const float* src;
    __nv_bfloat16 *dhi, *dlo;
    if (row < DD) {
        src = Wo + (size_t)row*SS;
        dhi = g_Whi + (size_t)row*SS; dlo = g_Wlo + (size_t)row*SS;
    } else {
        int r = row - DD;
        src = x + (size_t)r*DD;
        dhi = g_xhi + (size_t)r*DD; dlo = g_xlo + (size_t)r*DD;
    }

    int base = tid * 8;
    float4 f0 = *(const float4*)(src + base);
    float4 f1 = *(const float4*)(src + base + 4);
    float v[8] = {f0.x, f0.y, f0.z, f0.w, f1.x, f1.y, f1.z, f1.w};
    unsigned hw[4], lw[4];
    #pragma unroll
    for (int p = 0; p < 4; p++) {
        __nv_bfloat16 ha, hb, la, lb;
        splitbf(v[2*p], ha, la);
        splitbf(v[2*p+1], hb, lb);
        hw[p] = pack2(ha, hb);
        lw[p] = pack2(la, lb);
    }
    *(uint4*)(dhi + base) = make_uint4(hw[0], hw[1], hw[2], hw[3]);
    *(uint4*)(dlo + base) = make_uint4(lw[0], lw[1], lw[2], lw[3]);
}

// ---------------------------------------------------------------------------
// Kernel 1b: fp32 -> bf16 hi/lo split for Wq/Wk/Wv (flat, 4 elems/thread)
// ---------------------------------------------------------------------------
__global__ __launch_bounds__(256) void splitw_kernel(
    const float* __restrict__ Wq, const float* __restrict__ Wk,
    const float* __restrict__ Wv)
{
    int base = (blockIdx.x*256 + threadIdx.x) * 4;
    int wsel = base >> 18;
    int off  = base & 262143;
    const float* src = (wsel == 0 ? Wq : wsel == 1 ? Wk : Wv) + off;
    float4 f = *(const float4*)src;
    __nv_bfloat16 h0,l0,h1,l1,h2,l2,h3,l3;
    splitbf(f.x,h0,l0); splitbf(f.y,h1,l1); splitbf(f.z,h2,l2); splitbf(f.w,h3,l3);
    *(uint2*)(g_wwhi + base) = make_uint2(pack2(h0,h1), pack2(h2,h3));
    *(uint2*)(g_wwlo + base) = make_uint2(pack2(l0,l1), pack2(l2,l3));
}

// ---------------------------------------------------------------------------
// Kernel 2: QKV projections via HMMA. grid (16, HH, 3) + mt_base
// ---------------------------------------------------------------------------
__global__ __launch_bounds__(256) void qkv_mma_kernel(
    const float* __restrict__ bq, const float* __restrict__ bk,
    const float* __restrict__ bv, int mt_base)
{
    int mt = mt_base + blockIdx.x, h = blockIdx.y, w = blockIdx.z;
    extern __shared__ char sm3[];
    uint32_t sb = smem_u32(sm3);
    int tid = threadIdx.x, lane = tid & 31, wid = tid >> 5;
    int wm = wid & 3, wn = wid >> 2;

    float acc[2][8][4];
    #pragma unroll
    for (int i = 0; i < 2; i++)
        #pragma unroll
        for (int j = 0; j < 8; j++)
            #pragma unroll
            for (int q = 0; q < 4; q++) acc[i][j][q] = 0.f;

    size_t aoff = (size_t)(mt*128)*DD + h*HD;
    size_t boff = (size_t)((w*HH + h)*HD)*HD;
    gemm3_core(acc, sb, tid, g_xhi + aoff, g_xlo + aoff, DD,
               g_wwhi + boff, g_wwlo + boff, HD, 2);

    const float* bias = (w == 0 ? bq : w == 1 ? bk : bv) + h*HD;
    int b = mt >> 4;
    int bh = b*HH + h;
    int sbase = (mt*128) & (SS - 1);
    int r0w = lane >> 2, cc = (lane & 3)*2;

    if (w < 2) {
        __nv_bfloat16* dh = (w == 0 ? g_qhi : g_khi);
        __nv_bfloat16* dl = (w == 0 ? g_qlo : g_klo);
        #pragma unroll
        for (int i = 0; i < 2; i++) {
            int m0 = wm*32 + i*16 + r0w;
            size_t row0 = ((size_t)bh*SS + sbase + m0)*HD;
            size_t row1 = row0 + (size_t)8*HD;
            #pragma unroll
            for (int j = 0; j < 8; j++) {
                int d0 = wn*64 + j*8 + cc;
                float b0 = bias[d0], b1 = bias[d0+1];
                __nv_bfloat16 ha,la,hb,lb;
                splitbf(acc[i][j][0] + b0, ha, la);
                splitbf(acc[i][j][1] + b1, hb, lb);
                *(unsigned*)(dh + row0 + d0) = pack2(ha, hb);
                *(unsigned*)(dl + row0 + d0) = pack2(la, lb);
                splitbf(acc[i][j][2] + b0, ha, la);
                splitbf(acc[i][j][3] + b1, hb, lb);
                *(unsigned*)(dh + row1 + d0) = pack2(ha, hb);
                *(unsigned*)(dl + row1 + d0) = pack2(la, lb);
            }
        }
    } else {
        __nv_bfloat16* th = (__nv_bfloat16*)sm3;          // [d][m] 128x128
        __nv_bfloat16* tl = th + 128*128;
        #pragma unroll
        for (int i = 0; i < 2; i++) {
            int m0 = wm*32 + i*16 + r0w;
            #pragma unroll
            for (int j = 0; j < 8; j++) {
                int d0 = wn*64 + j*8 + cc;
                float b0 = bias[d0], b1 = bias[d0+1];
                __nv_bfloat16 hh, ll;
                splitbf(acc[i][j][0] + b0, hh, ll);
                th[d0*128 + m0] = hh;         tl[d0*128 + m0] = ll;
                splitbf(acc[i][j][1] + b1, hh, ll);
                th[(d0+1)*128 + m0] = hh;     tl[(d0+1)*128 + m0] = ll;
                splitbf(acc[i][j][2] + b0, hh, ll);
                th[d0*128 + m0 + 8] = hh;     tl[d0*128 + m0 + 8] = ll;
                splitbf(acc[i][j][3] + b1, hh, ll);
                th[(d0+1)*128 + m0 + 8] = hh; tl[(d0+1)*128 + m0 + 8] = ll;
            }
        }
        __syncthreads();
        int d = tid >> 1, half = tid & 1;
        size_t go = ((size_t)bh*HD + d)*SS + sbase + half*64;
        const uint4* s4h = (const uint4*)(th + d*128 + half*64);
        const uint4* s4l = (const uint4*)(tl + d*128 + half*64);
        #pragma unroll
        for (int p = 0; p < 8; p++) {
            *(uint4*)(g_vthi + go + p*8) = s4h[p];
            *(uint4*)(g_vtlo + go + p*8) = s4l[p];
        }
    }
}

// ---------------------------------------------------------------------------
// Kernel 3: score GEMM. Triangular grid (136, HH) + bh_base
// ---------------------------------------------------------------------------
__global__ __launch_bounds__(256) void score_gemm_kernel(int bh_base)
{
    int l = blockIdx.x;
    int it = 0, tbase = 0;
    while (l >= tbase + it + 1) { tbase += it + 1; it++; }
    int jt = l - tbase;
    int bh = bh_base + blockIdx.y;

    extern __shared__ char sm3[];
    uint32_t sb = smem_u32(sm3);
    int tid = threadIdx.x, lane = tid & 31, wid = tid >> 5;
    int wm = wid & 3, wn = wid >> 2;

    float acc[2][8][4];
    #pragma unroll
    for (int i = 0; i < 2; i++)
        #pragma unroll
        for (int j = 0; j < 8; j++)
            #pragma unroll
            for (int q = 0; q < 4; q++) acc[i][j][q] = 0.f;

    size_t aoff = ((size_t)bh*SS + it*128)*HD;
    size_t boff = ((size_t)bh*SS + jt*128)*HD;
    gemm3_core(acc, sb, tid, g_qhi + aoff, g_qlo + aoff, HD,
               g_khi + boff, g_klo + boff, HD, 2);

    const float scale = 0.08838834764831845f;
    int r0w = lane >> 2, cc = (lane & 3) * 2;
    #pragma unroll
    for (int i = 0; i < 2; i++) {
        int m0 = it*128 + wm*32 + i*16 + r0w;
        int m1 = m0 + 8;
        float* row0 = g_sc + ((size_t)bh*SS + m0)*SS + jt*128 + wn*64;
        float* row1 = row0 + (size_t)8*SS;
        #pragma unroll
        for (int j = 0; j < 8; j++) {
            int j0 = jt*128 + wn*64 + j*8 + cc;
            float2 v0, v1;
            v0.x = (j0     <= m0) ? acc[i][j][0]*scale : NEGV;
            v0.y = (j0 + 1 <= m0) ? acc[i][j][1]*scale : NEGV;
            v1.x = (j0     <= m1) ? acc[i][j][2]*scale : NEGV;
            v1.y = (j0 + 1 <= m1) ? acc[i][j][3]*scale : NEGV;
            *(float2*)(row0 + j*8 + cc) = v0;
            *(float2*)(row1 + j*8 + cc) = v1;
        }
    }
}

// ---------------------------------------------------------------------------
// Kernel 4: exact top-k select + fused exp/sum -> UNNORMALIZED bf16 weights
// ---------------------------------------------------------------------------
__device__ __forceinline__ unsigned f2key(float f) {
    unsigned u = __float_as_uint(f);
    return u ^ ((u & 0x80000000u) ? 0xFFFFFFFFu : 0x80000000u);
}
__device__ __forceinline__ float key2f(unsigned k) {
    unsigned u = (k & 0x80000000u) ? (k ^ 0x80000000u) : ~k;
    return __uint_as_float(u);
}

__global__ __launch_bounds__(512) void select_kernel(int bh_base)
{
    __shared__ int hist[16*256];

    int bh   = bh_base + blockIdx.y;
    int s0   = (gridDim.x - 1 - blockIdx.x) * 16;
    int tid  = threadIdx.x;
    int lane = tid & 31, wid = tid >> 5;
    int s    = s0 + wid;
    int nvalid = s + 1;
    int nround = (nvalid + 31) & ~31;

    const float* row = g_sc + ((size_t)bh*SS + s)*SS;
    int* hh = hist + wid*256;

    float lm  = -3.4e38f;
    float thr = -3.4e38f;

    if (s >= KKEEP - 1) {
        unsigned prefix = 0; int K = KKEEP;
        #pragma unroll
        for (int pass = 0; pass < 4; pass++) {
            int shift = 24 - pass*8;
            #pragma unroll
            for (int i = lane; i < 256; i += 32) hh[i] = 0;
            __syncwarp();
            for (int t = lane; t < nround; t += 32) {
                bool valid = (t < nvalid);
                float v = valid ? row[t] : NEGV;
                if (pass == 0 && valid) lm = fmaxf(lm, v);
                unsigned key = f2key(v);
                bool cand = valid &&
                    ((pass == 0) || (((key ^ prefix) >> (shift + 8)) == 0u));
                int bin = cand ? (int)((key >> shift) & 255u) : -1;
                unsigned peers = __match_any_sync(FULLW, bin);
                if (cand && lane == (__ffs(peers) - 1))
                    atomicAdd(&hh[bin], __popc(peers));
            }
            __syncwarp();
            int hv[8]; int ssum = 0;
            #pragma unroll
            for (int i = 0; i < 8; i++) { hv[i] = hh[lane*8 + i]; ssum += hv[i]; }
            int suf = ssum;
            #pragma unroll
            for (int off = 1; off < 32; off <<= 1) {
                int v = __shfl_down_sync(FULLW, suf, off);
                if (lane + off < 32) suf += v;
            }
            int above = suf - ssum;
            int selbin = -1, newK = 0;
            if (suf >= K && above < K) {
                int run = above;
                #pragma unroll
                for (int bb2 = 7; bb2 >= 0; bb2--) {
                    run += hv[bb2];
                    if (run >= K) { selbin = lane*8 + bb2; newK = K - (run - hv[bb2]); break; }
                }
            }
            unsigned msk = __ballot_sync(FULLW, selbin >= 0);
            int src = __ffs(msk) - 1;
            selbin = __shfl_sync(FULLW, selbin, src);
            newK   = __shfl_sync(FULLW, newK,  src);
            prefix |= ((unsigned)selbin) << shift;
            K = newK;
        }
        thr = key2f(prefix);
    } else {
        for (int t = lane; t < nvalid; t += 32) lm = fmaxf(lm, row[t]);
    }

    #pragma unroll
    for (int off = 16; off > 0; off >>= 1)
        lm = fmaxf(lm, __shfl_xor_sync(FULLW, lm, off));

    int CEIL = (s0 & ~127) + 128;
    size_t go = ((size_t)bh*SS + s)*SS;
    float ls = 0.f;
    for (int t4 = lane*4; t4 < CEIL; t4 += 128) {
        float w0 = 0.f, w1 = 0.f, w2 = 0.f, w3 = 0.f;
        if (t4 + 3 < nvalid) {
            float4 v4 = *(const float4*)(row + t4);
            if (v4.x >= thr) w0 = __expf(v4.x - lm);
            if (v4.y >= thr) w1 = __expf(v4.y - lm);
            if (v4.z >= thr) w2 = __expf(v4.z - lm);
            if (v4.w >= thr) w3 = __expf(v4.w - lm);
        } else if (t4 < nvalid) {
            float vv;
            vv = row[t4];
            if (vv >= thr) w0 = __expf(vv - lm);
            if (t4 + 1 < nvalid) { vv = row[t4+1]; if (vv >= thr) w1 = __expf(vv - lm); }
            if (t4 + 2 < nvalid) { vv = row[t4+2]; if (vv >= thr) w2 = __expf(vv - lm); }
        }
        ls += (w0 + w1) + (w2 + w3);
        __nv_bfloat16 h0,l0,h1,l1,h2,l2,h3,l3;
        splitbf(w0,h0,l0); splitbf(w1,h1,l1);
        splitbf(w2,h2,l2); splitbf(w3,h3,l3);
        *(uint2*)(g_wh + go + t4) = make_uint2(pack2(h0,h1), pack2(h2,h3));
        *(uint2*)(g_wl + go + t4) = make_uint2(pack2(l0,l1), pack2(l2,l3));
    }
    #pragma unroll
    for (int off = 16; off > 0; off >>= 1)
        ls += __shfl_xor_sync(FULLW, ls, off);
    if (lane == 0) g_rsv[(size_t)bh*SS + s] = 1.f / ls;
}

// ---------------------------------------------------------------------------
// Kernel 5: AV GEMM (transposed): outT[d, s] = rsv[s] * sum_t V^T[d,t]*W[s,t]
// ---------------------------------------------------------------------------
__global__ __launch_bounds__(256) void av_gemm_kernel(int bh_base)
{
    int st = gridDim.x - 1 - blockIdx.x;
    int bh = bh_base + blockIdx.y;

    extern __shared__ char sm3[];
    uint32_t sb = smem_u32(sm3);
    int tid = threadIdx.x, lane = tid & 31, wid = tid >> 5;
    int wm = wid & 3, wn = wid >> 2;

    float acc[2][8][4];
    #pragma unroll
    for (int i = 0; i < 2; i++)
        #pragma unroll
        for (int j = 0; j < 8; j++)
            #pragma unroll
            for (int q = 0; q < 4; q++) acc[i][j][q] = 0.f;

    size_t aoff = (size_t)bh*HD*SS;
    size_t boff = ((size_t)bh*SS + st*128)*SS;
    gemm3_core(acc, sb, tid, g_vthi + aoff, g_vtlo + aoff, SS,
               g_wh + boff, g_wl + boff, SS, 2*(st + 1));

    int b = bh >> 4, h = bh & 15;
    int r0w = lane >> 2, cc = (lane & 3) * 2;
    const float* rsvp = g_rsv + (size_t)bh*SS;
    #pragma unroll
    for (int i = 0; i < 2; i++) {
        int d0 = wm*32 + i*16 + r0w;
        size_t rowA = ((size_t)b*DD + h*HD + d0)*SS;
        size_t rowB = rowA + (size_t)8*SS;
        #pragma unroll
        for (int j = 0; j < 8; j++) {
            int s_col = st*128 + wn*64 + j*8 + cc;
            float r0 = rsvp[s_col], r1 = rsvp[s_col + 1];
            __nv_bfloat16 h0,l0,h1,l1;
            splitbf(acc[i][j][0]*r0, h0, l0);
            splitbf(acc[i][j][1]*r1, h1, l1);
            *(unsigned*)(g_Ahi + rowA + s_col) = pack2(h0, h1);
            *(unsigned*)(g_Alo + rowA + s_col) = pack2(l0, l1);
            splitbf(acc[i][j][2]*r0, h0, l0);
            splitbf(acc[i][j][3]*r1, h1, l1);
            *(unsigned*)(g_Ahi + rowB + s_col) = pack2(h0, h1);
            *(unsigned*)(g_Alo + rowB + s_col) = pack2(l0, l1);
        }
    }
}

// ---------------------------------------------------------------------------
// Kernel 6: proj GEMM (3-stage pipeline), per-batch. grid (16, 16)
// ---------------------------------------------------------------------------
#define PJ_STAGE 32768
#define PJ_SMEM  (3*PJ_STAGE)

__global__ __launch_bounds__(256) void proj_mma_kernel(
    const float* __restrict__ bo, float* __restrict__ out, int b)
{
    extern __shared__ char psm[];
    uint32_t sb = smem_u32(psm);

    int tid = threadIdx.x, lane = tid & 31, wid = tid >> 5;
    int wm = wid & 3, wn = wid >> 2;
    int nt = blockIdx.x, mt = blockIdx.y;

    const __nv_bfloat16* Abase   = g_Ahi + ((size_t)b*DD + mt*128)*SS;
    const __nv_bfloat16* AbaseLo = g_Alo + ((size_t)b*DD + mt*128)*SS;
    const __nv_bfloat16* Wbase   = g_Whi + (size_t)(nt*128)*SS;
    const __nv_bfloat16* WbaseLo = g_Wlo + (size_t)(nt*128)*SS;

    int lrow = tid >> 3, lc16 = tid & 7;

    float acc[2][8][4];
    #pragma unroll
    for (int i = 0; i < 2; i++)
        #pragma unroll
        for (int j = 0; j < 8; j++)
            #pragma unroll
            for (int q = 0; q < 4; q++) acc[i][j][q] = 0.f;

    int rowa_l = wm*32 + (lane & 15);
    int ca_l   = (lane >> 4);
    int rowb_l = wn*64 + (lane & 7) + ((lane >> 4) << 3);
    int cb_l   = (lane >> 3) & 1;

    const int NC = 96;

    auto load_chunk = [&](int c, int stg) {
        int seg = c >> 5, kk = (c & 31) * 64;
        const __nv_bfloat16* As = (seg == 1 ? AbaseLo : Abase);
        const __nv_bfloat16* Bs = (seg == 2 ? WbaseLo : Wbase);
        uint32_t sa = sb + stg*PJ_STAGE, sbB = sa + 16384;
        #pragma unroll
        for (int rep = 0; rep < 4; rep++) {
            int row = lrow + rep*32;
            uint32_t off = (uint32_t)row*128 + 16u*(uint32_t)(lc16 ^ (row & 7));
            cpa16(sa  + off, As + (size_t)row*SS + kk + lc16*8);
            cpa16(sbB + off, Bs + (size_t)row*SS + kk + lc16*8);
        }
        asm volatile("cp.async.commit_group;");
    };

    load_chunk(0, 0);
    load_chunk(1, 1);

    for (int c = 0; c < NC; c++) {
        int st = c % 3;
        if (c + 2 < NC) {
            load_chunk(c + 2, (c + 2) % 3);
            asm volatile("cp.async.wait_group 2;");
        } else if (c + 1 < NC) {
            asm volatile("cp.async.wait_group 1;");
        } else {
            asm volatile("cp.async.wait_group 0;");
        }
        __syncthreads();

        uint32_t sa = sb + st*PJ_STAGE, sbB = sa + 16384;
        #pragma unroll
        for (int kstep = 0; kstep < 4; kstep++) {
            uint32_t afr[2][4];
            #pragma unroll
            for (int i = 0; i < 2; i++) {
                int row = rowa_l + i*16;
                int c16 = kstep*2 + ca_l;
                ldsm4(afr[i], sa + (uint32_t)row*128 + 16u*(uint32_t)(c16 ^ (row & 7)));
            }
            uint32_t bfr[4][4];
            #pragma unroll
            for (int j4 = 0; j4 < 4; j4++) {
                int row = rowb_l + j4*16;
                int c16 = kstep*2 + cb_l;
                ldsm4(bfr[j4], sbB + (uint32_t)row*128 + 16u*(uint32_t)(c16 ^ (row & 7)));
            }
            #pragma unroll
            for (int i = 0; i < 2; i++)
                #pragma unroll
                for (int j4 = 0; j4 < 4; j4++) {
                    mma16816(acc[i][2*j4+0], afr[i], bfr[j4][0], bfr[j4][1]);
                    mma16816(acc[i][2*j4+1], afr[i], bfr[j4][2], bfr[j4][3]);
                }
        }
        __syncthreads();
    }

    int r0w = lane >> 2, cc = (lane & 3) * 2;
    const float* bop = bo + nt*128 + wn*64;
    #pragma unroll
    for (int i = 0; i < 2; i++) {
        int m = mt*128 + wm*32 + i*16 + r0w;
        float* row0 = out + ((size_t)b*DD + m)*DD + nt*128 + wn*64;
        float* row1 = row0 + (size_t)8*DD;
        #pragma unroll
        for (int j = 0; j < 8; j++) {
            float2 bb = *(const float2*)(bop + j*8 + cc);
            float2 v0 = make_float2(acc[i][j][0] + bb.x, acc[i][j][1] + bb.y);
            float2 v1 = make_float2(acc[i][j][2] + bb.x, acc[i][j][3] + bb.y);
            *(float2*)(row0 + j*8 + cc) = v0;
            *(float2*)(row1 + j*8 + cc) = v1;
        }
    }
}

// ---------------------------------------------------------------------------
// Host: 2-stream pipeline over batch b (static resources created pre-capture)
// ---------------------------------------------------------------------------
static cudaStream_t g_s1 = nullptr;
static cudaEvent_t  g_evF = nullptr, g_evJ = nullptr;
namespace {
struct StreamInit {
    StreamInit() {
        cudaStreamCreateWithFlags(&g_s1, cudaStreamNonBlocking);
        cudaEventCreateWithFlags(&g_evF, cudaEventDisableTiming);
        cudaEventCreateWithFlags(&g_evJ, cudaEventDisableTiming);
    }
};
static StreamInit g_stream_init;
}

extern "C" void kernel_launch(void* const* d_in, const int* in_sizes, int n_in,
                              void* d_out, int out_size)
{
    const float* x  = (const float*)d_in[0];
    const float* Wq = (const float*)d_in[2];
    const float* Wk = (const float*)d_in[3];
    const float* Wv = (const float*)d_in[4];
    const float* bq = (const float*)d_in[5];
    const float* bk = (const float*)d_in[6];
    const float* bv = (const float*)d_in[7];
    const float* Wo = (const float*)d_in[8];
    const float* bo = (const float*)d_in[9];
    float* out = (float*)d_out;

    if (!g_s1) {   // fallback (first call is uncaptured)
        cudaStreamCreateWithFlags(&g_s1, cudaStreamNonBlocking);
        cudaEventCreateWithFlags(&g_evF, cudaEventDisableTiming);
        cudaEventCreateWithFlags(&g_evJ, cudaEventDisableTiming);
    }

    cudaFuncSetAttribute(qkv_mma_kernel,  cudaFuncAttributeMaxDynamicSharedMemorySize, G3_SMEM);
    cudaFuncSetAttribute(score_gemm_kernel, cudaFuncAttributeMaxDynamicSharedMemorySize, G3_SMEM);
    cudaFuncSetAttribute(av_gemm_kernel,  cudaFuncAttributeMaxDynamicSharedMemorySize, G3_SMEM);
    cudaFuncSetAttribute(proj_mma_kernel, cudaFuncAttributeMaxDynamicSharedMemorySize, PJ_SMEM);

    // shared prologue on capture stream
    split_kernel<<<dim3(DD + BB*SS), 256>>>(Wo, x);
    splitw_kernel<<<dim3(768), 256>>>(Wq, Wk, Wv);
    cudaEventRecord(g_evF, 0);
    cudaStreamWaitEvent(g_s1, g_evF, 0);

    // per-batch chains: b=0 on capture stream, b=1 on g_s1
    for (int b = 0; b < BB; b++) {
        cudaStream_t strm = (b == 0) ? (cudaStream_t)0 : g_s1;
        qkv_mma_kernel<<<dim3(16, HH, 3), 256, G3_SMEM, strm>>>(bq, bk, bv, b*16);
        score_gemm_kernel<<<dim3(136, HH), 256, G3_SMEM, strm>>>(b*HH);
        select_kernel<<<dim3(SS/16, HH), 512, 0, strm>>>(b*HH);
        av_gemm_kernel<<<dim3(16, HH), 256, G3_SMEM, strm>>>(b*HH);
        proj_mma_kernel<<<dim3(16, 16), 256, PJ_SMEM, strm>>>(bo, out, b);
    }

    cudaEventRecord(g_evJ, g_s1);
    cudaStreamWaitEvent(0, g_evJ, 0);
}